// round 7
// baseline (speedup 1.0000x reference)
#include <cuda_runtime.h>
#include <math.h>

// ---------------- problem constants ----------------
#define NTOK   8282          // tokens incl. cls (1 + 8281)
#define PAD    166           // front zero-pad inside nystrom
#define NP     8448          // padded length = 33*256
#define D      512
#define H3D    1536          // 3*D
#define NH     8             // heads
#define DH     64
#define MLM    256           // landmarks
#define LWIN   33            // tokens per landmark
#define SCALE  0.125f        // DH^-0.5
#define HS     91            // ppeg grid 91x91 = 8281
#define NPIX   8281
#define KSPL   33            // split-K chunks for a3v (8448/33 = 256)

// ---------------- static device scratch ----------------
__device__ float g_h   [NP * D];
__device__ float g_t   [NP * D];
__device__ float g_xp  [NP * D];
__device__ float g_qkv [NP * H3D];
__device__ float g_kT  [NH * DH * NP];
__device__ float g_s   [NH * NP * MLM];      // reused: a3 scores then a1 scores
__device__ float g_ql  [NH * MLM * DH];
__device__ float g_klT [NH * DH * MLM];
__device__ float g_a2  [NH * MLM * MLM];
__device__ float g_z0  [NH * MLM * MLM];
__device__ float g_z1  [NH * MLM * MLM];
__device__ float g_xz  [NH * MLM * MLM];
__device__ float g_u   [NH * MLM * MLM];
__device__ float g_tt  [NH * MLM * MLM];
__device__ float g_part[NH * KSPL * MLM * DH];  // split-K partials for a3v
__device__ float g_a3v [NH * MLM * DH];
__device__ float g_z2  [NH * MLM * DH];
__device__ float g_ab  [NP * D];
__device__ float g_red [NH * 2];

// ---------------- block reductions ----------------
__device__ __forceinline__ float blkSum(float v, float* sh, int nt) {
    int tid = threadIdx.x;
    #pragma unroll
    for (int o = 16; o; o >>= 1) v += __shfl_down_sync(0xffffffffu, v, o);
    __syncthreads();
    if ((tid & 31) == 0) sh[tid >> 5] = v;
    __syncthreads();
    int nw = nt >> 5;
    float r = (tid < nw) ? sh[tid] : 0.0f;
    if (tid < 32) {
        for (int o = nw >> 1; o; o >>= 1) r += __shfl_down_sync(0xffffffffu, r, o);
    }
    if (tid == 0) sh[0] = r;
    __syncthreads();
    float res = sh[0];
    __syncthreads();
    return res;
}

__device__ __forceinline__ float blkMax(float v, float* sh, int nt) {
    int tid = threadIdx.x;
    #pragma unroll
    for (int o = 16; o; o >>= 1) v = fmaxf(v, __shfl_down_sync(0xffffffffu, v, o));
    __syncthreads();
    if ((tid & 31) == 0) sh[tid >> 5] = v;
    __syncthreads();
    int nw = nt >> 5;
    float r = (tid < nw) ? sh[tid] : -INFINITY;
    if (tid < 32) {
        for (int o = nw >> 1; o; o >>= 1) r = fmaxf(r, __shfl_down_sync(0xffffffffu, r, o));
    }
    if (tid == 0) sh[0] = r;
    __syncthreads();
    float res = sh[0];
    __syncthreads();
    return res;
}

// ---------------- 64x64 batched SGEMM (double-buffered, emode, split-K) ----
// C = alpha * A @ B' (+bias)(+relu); B' = B, or (cval*I - B) when emode=1.
// ksplit>1: z = batch*ksplit + chunk; A,B advance chunk*K along k; C indexed
// by z (per-z stride sC). K is the PER-CHUNK depth. M,N mult 64; K mult 16.
__global__ void __launch_bounds__(256) sgemm(
    const float* __restrict__ A, int lda, long long sA,
    const float* __restrict__ B, int ldb, long long sB,
    float* __restrict__ C, int ldc, long long sC,
    int M, int N, int K, float alpha,
    const float* __restrict__ bias, int relu,
    int emode, float cval, int ksplit)
{
    __shared__ float As[2][16][64];
    __shared__ float Bs[2][16][64];
    int bz = blockIdx.z / ksplit, ch = blockIdx.z % ksplit;
    A += (long long)bz * sA + (long long)ch * K;
    B += (long long)bz * sB + (long long)ch * K * ldb;
    C += (long long)blockIdx.z * sC;
    int tid = threadIdx.x;
    int tx = tid & 15, ty = tid >> 4;
    int row0 = blockIdx.y * 64, col0 = blockIdx.x * 64;
    int ar = tid >> 2, ak = (tid & 3) << 2;
    int bk = tid >> 4, bc = (tid & 15) << 2;
    float acc[4][4] = {};
    const float* Ap = A + (long long)(row0 + ar) * lda + ak;
    const float* Bp = B + (long long)bk * ldb + col0 + bc;
    int nt = K >> 4;

    float4 a4 = *reinterpret_cast<const float4*>(Ap);
    float4 b4 = *reinterpret_cast<const float4*>(Bp);
    if (emode) {
        int kr = bk;
        b4.x = ((kr == col0 + bc + 0) ? cval : 0.0f) - b4.x;
        b4.y = ((kr == col0 + bc + 1) ? cval : 0.0f) - b4.y;
        b4.z = ((kr == col0 + bc + 2) ? cval : 0.0f) - b4.z;
        b4.w = ((kr == col0 + bc + 3) ? cval : 0.0f) - b4.w;
    }
    As[0][ak + 0][ar] = a4.x; As[0][ak + 1][ar] = a4.y;
    As[0][ak + 2][ar] = a4.z; As[0][ak + 3][ar] = a4.w;
    *reinterpret_cast<float4*>(&Bs[0][bk][bc]) = b4;
    __syncthreads();

    int buf = 0;
    for (int t = 0; t < nt; t++) {
        float4 na, nb;
        if (t + 1 < nt) {
            na = *reinterpret_cast<const float4*>(Ap + (t + 1) * 16);
            nb = *reinterpret_cast<const float4*>(Bp + (long long)(t + 1) * 16 * ldb);
            if (emode) {
                int kr = (t + 1) * 16 + bk;
                nb.x = ((kr == col0 + bc + 0) ? cval : 0.0f) - nb.x;
                nb.y = ((kr == col0 + bc + 1) ? cval : 0.0f) - nb.y;
                nb.z = ((kr == col0 + bc + 2) ? cval : 0.0f) - nb.z;
                nb.w = ((kr == col0 + bc + 3) ? cval : 0.0f) - nb.w;
            }
        }
        #pragma unroll
        for (int kk = 0; kk < 16; kk++) {
            float4 av = *reinterpret_cast<const float4*>(&As[buf][kk][ty << 2]);
            float4 bv = *reinterpret_cast<const float4*>(&Bs[buf][kk][tx << 2]);
            acc[0][0] += av.x * bv.x; acc[0][1] += av.x * bv.y; acc[0][2] += av.x * bv.z; acc[0][3] += av.x * bv.w;
            acc[1][0] += av.y * bv.x; acc[1][1] += av.y * bv.y; acc[1][2] += av.y * bv.z; acc[1][3] += av.y * bv.w;
            acc[2][0] += av.z * bv.x; acc[2][1] += av.z * bv.y; acc[2][2] += av.z * bv.z; acc[2][3] += av.z * bv.w;
            acc[3][0] += av.w * bv.x; acc[3][1] += av.w * bv.y; acc[3][2] += av.w * bv.z; acc[3][3] += av.w * bv.w;
        }
        if (t + 1 < nt) {
            buf ^= 1;
            As[buf][ak + 0][ar] = na.x; As[buf][ak + 1][ar] = na.y;
            As[buf][ak + 2][ar] = na.z; As[buf][ak + 3][ar] = na.w;
            *reinterpret_cast<float4*>(&Bs[buf][bk][bc]) = nb;
            __syncthreads();
        }
    }
    #pragma unroll
    for (int i = 0; i < 4; i++) {
        int r = row0 + (ty << 2) + i;
        if (r >= M) continue;
        #pragma unroll
        for (int j = 0; j < 4; j++) {
            int c = col0 + (tx << 2) + j;
            if (c >= N) continue;
            float v = alpha * acc[i][j];
            if (bias) v += bias[c];
            if (relu) v = fmaxf(v, 0.0f);
            C[(long long)r * ldc + c] = v;
        }
    }
}

// ---------------- 128x128 batched SGEMM (double-buffered) ----------------
// For big GEMMs. M,N mult of 128; K mult of 8. 256 threads, 8x8 micro split
// into 4+4 rows/cols offset by 64 (conflict-free LDS.128 phases).
__global__ void __launch_bounds__(256) sgemm128(
    const float* __restrict__ A, int lda, long long sA,
    const float* __restrict__ B, int ldb, long long sB,
    float* __restrict__ C, int ldc, long long sC,
    int M, int N, int K, float alpha,
    const float* __restrict__ bias, int relu)
{
    __shared__ float As[2][8][128];
    __shared__ float Bs[2][8][128];
    A += (long long)blockIdx.z * sA;
    B += (long long)blockIdx.z * sB;
    C += (long long)blockIdx.z * sC;
    int tid = threadIdx.x;
    int row0 = blockIdx.y * 128, col0 = blockIdx.x * 128;
    int ar = tid >> 1, ak = (tid & 1) << 2;    // A: 128 rows x 8 k
    int bk = tid >> 5, bc = (tid & 31) << 2;   // B: 8 k x 128 cols
    int tx = tid & 15, ty = tid >> 4;
    float acc[8][8] = {};
    const float* Ap = A + (long long)(row0 + ar) * lda + ak;
    const float* Bp = B + (long long)bk * ldb + col0 + bc;
    int nt = K >> 3;

    float4 a4 = *reinterpret_cast<const float4*>(Ap);
    float4 b4 = *reinterpret_cast<const float4*>(Bp);
    As[0][ak + 0][ar] = a4.x; As[0][ak + 1][ar] = a4.y;
    As[0][ak + 2][ar] = a4.z; As[0][ak + 3][ar] = a4.w;
    *reinterpret_cast<float4*>(&Bs[0][bk][bc]) = b4;
    __syncthreads();

    int buf = 0;
    for (int t = 0; t < nt; t++) {
        float4 na, nb;
        if (t + 1 < nt) {
            na = *reinterpret_cast<const float4*>(Ap + (t + 1) * 8);
            nb = *reinterpret_cast<const float4*>(Bp + (long long)(t + 1) * 8 * ldb);
        }
        #pragma unroll
        for (int kk = 0; kk < 8; kk++) {
            float4 a0 = *reinterpret_cast<const float4*>(&As[buf][kk][ty << 2]);
            float4 a1 = *reinterpret_cast<const float4*>(&As[buf][kk][64 + (ty << 2)]);
            float4 b0 = *reinterpret_cast<const float4*>(&Bs[buf][kk][tx << 2]);
            float4 b1 = *reinterpret_cast<const float4*>(&Bs[buf][kk][64 + (tx << 2)]);
            float ra[8] = {a0.x, a0.y, a0.z, a0.w, a1.x, a1.y, a1.z, a1.w};
            float rb[8] = {b0.x, b0.y, b0.z, b0.w, b1.x, b1.y, b1.z, b1.w};
            #pragma unroll
            for (int i = 0; i < 8; i++)
                #pragma unroll
                for (int j = 0; j < 8; j++)
                    acc[i][j] += ra[i] * rb[j];
        }
        if (t + 1 < nt) {
            buf ^= 1;
            As[buf][ak + 0][ar] = na.x; As[buf][ak + 1][ar] = na.y;
            As[buf][ak + 2][ar] = na.z; As[buf][ak + 3][ar] = na.w;
            *reinterpret_cast<float4*>(&Bs[buf][bk][bc]) = nb;
            __syncthreads();
        }
    }
    // rows: ty*4+i (i<4) then 64+ty*4+(i-4); cols: tx*4 and 64+tx*4 (float4 each)
    #pragma unroll
    for (int i = 0; i < 8; i++) {
        int r = row0 + ((i < 4) ? ((ty << 2) + i) : (64 + (ty << 2) + i - 4));
        #pragma unroll
        for (int jg = 0; jg < 2; jg++) {
            int c = col0 + jg * 64 + (tx << 2);
            float4 v;
            v.x = alpha * acc[i][jg * 4 + 0];
            v.y = alpha * acc[i][jg * 4 + 1];
            v.z = alpha * acc[i][jg * 4 + 2];
            v.w = alpha * acc[i][jg * 4 + 3];
            if (bias) {
                v.x += bias[c + 0]; v.y += bias[c + 1];
                v.z += bias[c + 2]; v.w += bias[c + 3];
            }
            if (relu) {
                v.x = fmaxf(v.x, 0.0f); v.y = fmaxf(v.y, 0.0f);
                v.z = fmaxf(v.z, 0.0f); v.w = fmaxf(v.w, 0.0f);
            }
            *reinterpret_cast<float4*>(&C[(long long)r * ldc + c]) = v;
        }
    }
}

// ---------------- misc kernels ----------------
__global__ void k_zero(float* p, int n) {
    int i = blockIdx.x * 256 + threadIdx.x;
    if (i < n) p[i] = 0.0f;
}

// deterministic reduction of KSPL split-K partials
__global__ void k_redsplit(const float* __restrict__ part, float* __restrict__ out) {
    int i = blockIdx.x * 256 + threadIdx.x;
    if (i >= NH * MLM * DH) return;
    int b = i / (MLM * DH), r = i - b * (MLM * DH);
    const float* p = part + ((long long)b * KSPL) * (MLM * DH) + r;
    float s = 0.0f;
    #pragma unroll 1
    for (int ch = 0; ch < KSPL; ch++) s += p[(long long)ch * (MLM * DH)];
    out[i] = s;
}

// h rows 1..8192 already hold relu(fc1). Set row0=cls, wrap rows 8193..8281 <- rows 1..89.
__global__ void k_build(float* h, const float* cls) {
    int idx = blockIdx.x * 256 + threadIdx.x;
    if (idx < D) h[idx] = cls[idx];
    int j = idx - D;
    if (j >= 0 && j < 89 * D) {
        int r = j / D, c = j - r * D;
        h[(long long)(8193 + r) * D + c] = h[(long long)(1 + r) * D + c];
    }
}

__global__ void k_ln(const float* __restrict__ in, float* __restrict__ out,
                     const float* __restrict__ gg, const float* __restrict__ bb, int rows) {
    __shared__ float sh[32];
    int r = blockIdx.x;
    if (r >= rows) return;
    const float* x = in + (long long)r * D;
    int tid = threadIdx.x;
    float v0 = x[tid], v1 = x[tid + 256];
    float s  = blkSum(v0 + v1, sh, 256);
    float s2 = blkSum(v0 * v0 + v1 * v1, sh, 256);
    float mu = s * (1.0f / 512.0f);
    float var = s2 * (1.0f / 512.0f) - mu * mu;
    float inv = rsqrtf(var + 1e-5f);
    float* o = out + (long long)r * D;
    o[tid]       = (v0 - mu) * inv * gg[tid] + bb[tid];
    o[tid + 256] = (v1 - mu) * inv * gg[tid + 256] + bb[tid + 256];
}

// generic softmax (rows of arbitrary len); exp cached on pass 2
__global__ void k_softmax(float* __restrict__ S, int len) {
    __shared__ float sh[32];
    float* row = S + (long long)blockIdx.x * len;
    int tid = threadIdx.x;
    float m = -INFINITY;
    for (int i = tid; i < len; i += 256) m = fmaxf(m, row[i]);
    m = blkMax(m, sh, 256);
    float s = 0.0f;
    for (int i = tid; i < len; i += 256) {
        float e = __expf(row[i] - m);
        row[i] = e;
        s += e;
    }
    s = blkSum(s, sh, 256);
    float inv = 1.0f / s;
    for (int i = tid; i < len; i += 256) row[i] *= inv;
}

// one-pass softmax for rows of exactly 256 (one element per thread)
__global__ void k_softmax256(float* __restrict__ S) {
    __shared__ float sh[32];
    int tid = threadIdx.x;
    float* row = S + (long long)blockIdx.x * 256;
    float v = row[tid];
    float m = blkMax(v, sh, 256);
    float e = __expf(v - m);
    float s = blkSum(e, sh, 256);
    row[tid] = e / s;
}

// landmark means: ql[h][m][d] = mean_t q[m*33+t][h*64+d]; klT[h][d][m] = mean_t k[...]
__global__ void k_landmark(const float* __restrict__ qkv, float* __restrict__ ql,
                           float* __restrict__ klT) {
    int m = blockIdx.x, h = blockIdx.y, d = threadIdx.x;
    const float* base = qkv + (long long)(m * LWIN) * H3D + h * DH + d;
    float qs = 0.0f, ks = 0.0f;
    for (int t = 0; t < LWIN; t++) {
        qs += base[(long long)t * H3D];
        ks += base[(long long)t * H3D + D];
    }
    ql[((h * MLM) + m) * DH + d]  = qs * (1.0f / 33.0f);
    klT[((h * DH) + d) * MLM + m] = ks * (1.0f / 33.0f);
}

// kT[c][n] = qkv[n][D + c]  (c = h*64+d), tiled transpose
__global__ void k_transpose(const float* __restrict__ src, float* __restrict__ dst) {
    __shared__ float tile[32][33];
    int c0 = blockIdx.x * 32, n0 = blockIdx.y * 32;
    for (int i = threadIdx.y; i < 32; i += 8)
        tile[i][threadIdx.x] = src[(long long)(n0 + i) * H3D + D + c0 + threadIdx.x];
    __syncthreads();
    for (int i = threadIdx.y; i < 32; i += 8)
        dst[(long long)(c0 + i) * NP + n0 + threadIdx.x] = tile[threadIdx.x][i];
}

// per-head reductions: red[h*2]=max row-sum |a2_h|, red[h*2+1]=max col-sum |a2_h|
__global__ void k_pinv_red(const float* __restrict__ a2, float* __restrict__ red) {
    __shared__ float sh[32];
    int h = blockIdx.x;
    const float* A = a2 + (long long)h * MLM * MLM;
    int i = threadIdx.x;
    float rs = 0.0f, cs = 0.0f;
    for (int j = 0; j < MLM; j++) {
        rs += fabsf(A[i * MLM + j]);
        cs += fabsf(A[j * MLM + i]);
    }
    float colv = blkMax(rs, sh, 256);
    float rowv = blkMax(cs, sh, 256);
    if (i == 0) { red[h * 2] = colv; red[h * 2 + 1] = rowv; }
}

// z0 = a2^T / (col*row), col/row are GLOBAL maxima across all heads (matches
// jnp .max() with no axis argument in the reference).
__global__ void k_pinv_zinit(const float* __restrict__ a2, const float* __restrict__ red,
                             float* __restrict__ z) {
    int idx = blockIdx.x * 256 + threadIdx.x;
    if (idx >= NH * MLM * MLM) return;
    float colm = 0.0f, rowm = 0.0f;
    #pragma unroll
    for (int hh = 0; hh < NH; hh++) {
        colm = fmaxf(colm, red[hh * 2]);
        rowm = fmaxf(rowm, red[hh * 2 + 1]);
    }
    int h = idx >> 16;
    int r = (idx >> 8) & 255;
    int c = idx & 255;
    z[idx] = a2[((long long)h << 16) + c * MLM + r] / (colm * rowm);
}

// depthwise 33-tap conv over sequence of v, added to ab (float4: 4 ch/thread)
__global__ void k_conv(const float* __restrict__ qkv, const float* __restrict__ w,
                       float* __restrict__ ab) {
    __shared__ float ws[NH * LWIN];
    int tid = threadIdx.x;   // 128 threads, each handles 4 channels
    for (int i = tid; i < NH * LWIN; i += 128) ws[i] = w[i];
    __syncthreads();
    int n = blockIdx.x;
    int c4 = tid << 2;            // 0,4,...,508 — all 4 within one head
    int h = c4 >> 6;
    const float* wrow = ws + h * LWIN;
    float4 s = make_float4(0.0f, 0.0f, 0.0f, 0.0f);
    #pragma unroll
    for (int t = 0; t < LWIN; t++) {
        int nn = n - 16 + t;
        if (nn >= 0 && nn < NP) {
            float wv = wrow[t];
            float4 v = *reinterpret_cast<const float4*>(
                qkv + (long long)nn * H3D + 2 * D + c4);
            s.x += wv * v.x; s.y += wv * v.y; s.z += wv * v.z; s.w += wv * v.w;
        }
    }
    float4* dst = reinterpret_cast<float4*>(ab + (long long)n * D + c4);
    float4 o = *dst;
    o.x += s.x; o.y += s.y; o.z += s.z; o.w += s.w;
    *dst = o;
}

__global__ void k_resid(float* __restrict__ h, const float* __restrict__ t) {
    int idx = blockIdx.x * 256 + threadIdx.x;   // float4 index
    if (idx < (NTOK * D) / 4) {
        float4 a = reinterpret_cast<float4*>(h)[idx];
        float4 b = reinterpret_cast<const float4*>(t + PAD * D)[idx];
        a.x += b.x; a.y += b.y; a.z += b.z; a.w += b.w;
        reinterpret_cast<float4*>(h)[idx] = a;
    }
}

// PPEG: out row 1+p = center + dw7 + dw5 + dw3 (+biases). 512 threads = channels.
// Block 0 also carries the cls row (row 0) into out.
__global__ void k_ppeg(const float* __restrict__ h, float* __restrict__ out,
                       const float* __restrict__ w7, const float* __restrict__ b7,
                       const float* __restrict__ w5, const float* __restrict__ b5,
                       const float* __restrict__ w3, const float* __restrict__ b3) {
    int p = blockIdx.x;
    int y = p / HS, x = p - y * HS;
    int c = threadIdx.x;
    if (p == 0) out[c] = h[c];
    float acc = h[(long long)(1 + p) * D + c] + b7[c] + b5[c] + b3[c];
    const float* W7 = w7 + c * 49;
    const float* W5 = w5 + c * 25;
    const float* W3 = w3 + c * 9;
    #pragma unroll
    for (int ky = 0; ky < 7; ky++) {
        int yy = y + ky - 3;
        if (yy < 0 || yy >= HS) continue;
        #pragma unroll
        for (int kx = 0; kx < 7; kx++) {
            int xx = x + kx - 3;
            if (xx < 0 || xx >= HS) continue;
            float v = h[(long long)(1 + yy * HS + xx) * D + c];
            float wsum = W7[ky * 7 + kx];
            if (ky >= 1 && ky <= 5 && kx >= 1 && kx <= 5) wsum += W5[(ky - 1) * 5 + (kx - 1)];
            if (ky >= 2 && ky <= 4 && kx >= 2 && kx <= 4) wsum += W3[(ky - 2) * 3 + (kx - 2)];
            acc += v * wsum;
        }
    }
    out[(long long)(1 + p) * D + c] = acc;
}

// final: emb = ln(h[0]); logits = emb@fc2 + b; softmax; argmax
__global__ void k_final(const float* __restrict__ h, const float* __restrict__ gg,
                        const float* __restrict__ bb, const float* __restrict__ fw,
                        const float* __restrict__ fb, float* __restrict__ out, int out_size) {
    __shared__ float sh[32];
    __shared__ float emb[512];
    int tid = threadIdx.x;
    float v = h[tid];
    float s  = blkSum(v, sh, 512);
    float s2 = blkSum(v * v, sh, 512);
    float mu = s * (1.0f / 512.0f);
    float var = s2 * (1.0f / 512.0f) - mu * mu;
    float inv = rsqrtf(var + 1e-5f);
    float e = (v - mu) * inv * gg[tid] + bb[tid];
    emb[tid] = e;
    if (5 + tid < out_size) out[5 + tid] = e;
    __syncthreads();
    if (tid == 0) {
        float l0 = fb[0], l1 = fb[1];
        for (int c = 0; c < 512; c++) { l0 += emb[c] * fw[2 * c]; l1 += emb[c] * fw[2 * c + 1]; }
        if (out_size > 0) out[0] = l0;
        if (out_size > 1) out[1] = l1;
        float m = fmaxf(l0, l1);
        float e0 = __expf(l0 - m), e1 = __expf(l1 - m);
        float ss = e0 + e1;
        if (out_size > 2) out[2] = e0 / ss;
        if (out_size > 3) out[3] = e1 / ss;
        if (out_size > 4) out[4] = (l1 > l0) ? 1.0f : 0.0f;
    }
}

// ---------------- host orchestration ----------------
static inline void gemm(const float* A, int lda, long long sA,
                        const float* B, int ldb, long long sB,
                        float* C, int ldc, long long sC,
                        int M, int N, int K, float alpha,
                        const float* bias, int relu, int batch,
                        int emode = 0, float cval = 0.0f, int ksplit = 1) {
    dim3 g(N / 64, M / 64, batch * ksplit);
    sgemm<<<g, 256>>>(A, lda, sA, B, ldb, sB, C, ldc, sC, M, N, K, alpha, bias, relu,
                      emode, cval, ksplit);
}

static inline void gemmL(const float* A, int lda, long long sA,
                         const float* B, int ldb, long long sB,
                         float* C, int ldc, long long sC,
                         int M, int N, int K, float alpha,
                         const float* bias, int relu, int batch) {
    dim3 g(N / 128, M / 128, batch);
    sgemm128<<<g, 256>>>(A, lda, sA, B, ldb, sB, C, ldc, sC, M, N, K, alpha, bias, relu);
}

struct Bufs {
    float *h, *t, *xp, *qkv, *kT, *s, *ql, *klT, *a2, *z0, *z1, *xz, *u, *tt,
          *part, *a3v, *z2, *ab, *red;
};

static void run_attn(Bufs& b, const float* lng, const float* lnb,
                     const float* qkvw, const float* outw, const float* outb,
                     const float* convw) {
    k_zero<<<(PAD * D + 255) / 256, 256>>>(b.xp, PAD * D);
    k_ln<<<NTOK, 256>>>(b.h, b.xp + (long long)PAD * D, lng, lnb, NTOK);
    gemmL(b.xp, D, 0, qkvw, H3D, 0, b.qkv, H3D, 0, NP, H3D, D, 1.0f, nullptr, 0, 1);
    k_landmark<<<dim3(MLM, NH), DH>>>(b.qkv, b.ql, b.klT);
    k_transpose<<<dim3(D / 32, NP / 32), dim3(32, 8)>>>(b.qkv, b.kT);
    // a2 = softmax(SCALE * ql @ kl^T)
    gemm(b.ql, DH, MLM * DH, b.klT, MLM, DH * MLM, b.a2, MLM, MLM * MLM,
         MLM, MLM, DH, SCALE, nullptr, 0, NH);
    k_softmax256<<<NH * MLM, 256>>>(b.a2);
    // pinv: z = 0.25 * z @ (13I - xz @ (15I - xz @ (7I - xz))), xz = a2@z
    k_pinv_red<<<NH, 256>>>(b.a2, b.red);
    k_pinv_zinit<<<(NH * MLM * MLM + 255) / 256, 256>>>(b.a2, b.red, b.z0);
    float* zc = b.z0; float* zn = b.z1;
    const long long SB = (long long)MLM * MLM;
    for (int it = 0; it < 6; it++) {
        gemm(b.a2, MLM, SB, zc, MLM, SB, b.xz, MLM, SB, MLM, MLM, MLM, 1.0f, nullptr, 0, NH);
        gemm(b.xz, MLM, SB, b.xz, MLM, SB, b.u,  MLM, SB, MLM, MLM, MLM, 1.0f, nullptr, 0, NH, 1, 7.0f);
        gemm(b.xz, MLM, SB, b.u,  MLM, SB, b.tt, MLM, SB, MLM, MLM, MLM, 1.0f, nullptr, 0, NH, 1, 15.0f);
        gemm(zc,   MLM, SB, b.tt, MLM, SB, zn,   MLM, SB, MLM, MLM, MLM, 0.25f, nullptr, 0, NH, 1, 13.0f);
        float* sw = zc; zc = zn; zn = sw;
    }
    // a3 = softmax_n(SCALE * ql @ k^T)
    gemmL(b.ql, DH, MLM * DH, b.kT, NP, (long long)DH * NP, b.s, NP, (long long)MLM * NP,
          MLM, NP, DH, SCALE, nullptr, 0, NH);
    k_softmax<<<NH * MLM, 256>>>(b.s, NP);
    // a3v = a3 @ v  (split-K: 33 chunks of 256, deterministic reduce)
    gemm(b.s, NP, (long long)MLM * NP, b.qkv + 2 * D, H3D, DH,
         b.part, DH, (long long)MLM * DH,
         MLM, DH, NP / KSPL, 1.0f, nullptr, 0, NH, 0, 0.0f, KSPL);
    k_redsplit<<<(NH * MLM * DH + 255) / 256, 256>>>(b.part, b.a3v);
    // z2 = pinv @ a3v
    gemm(zc, MLM, SB, b.a3v, DH, MLM * DH, b.z2, DH, MLM * DH, MLM, DH, MLM, 1.0f, nullptr, 0, NH);
    // a1 = softmax(SCALE * q @ kl^T); ab = a1 @ z2 (per head into column slices)
    gemmL(b.qkv, H3D, DH, b.klT, MLM, DH * MLM, b.s, MLM, (long long)NP * MLM,
          NP, MLM, DH, SCALE, nullptr, 0, NH);
    k_softmax256<<<NH * NP, 256>>>(b.s);
    gemm(b.s, MLM, (long long)NP * MLM, b.z2, DH, MLM * DH, b.ab, D, DH,
         NP, DH, MLM, 1.0f, nullptr, 0, NH);
    // + depthwise conv(v)
    k_conv<<<NP, 128>>>(b.qkv, convw, b.ab);
    // proj + residual (last NTOK rows)
    gemmL(b.ab, D, 0, outw, D, 0, b.t, D, 0, NP, D, D, 1.0f, outb, 0, 1);
    k_resid<<<((NTOK * D / 4) + 255) / 256, 256>>>(b.h, b.t);
}

extern "C" void kernel_launch(void* const* d_in, const int* in_sizes, int n_in,
                              void* d_out, int out_size) {
    const float* x      = (const float*)d_in[0];
    const float* fc1_w  = (const float*)d_in[1];
    const float* fc1_b  = (const float*)d_in[2];
    const float* cls    = (const float*)d_in[3];
    const float* ln1_g  = (const float*)d_in[4];
    const float* ln1_b  = (const float*)d_in[5];
    const float* qkv1_w = (const float*)d_in[6];
    const float* out1_w = (const float*)d_in[7];
    const float* out1_b = (const float*)d_in[8];
    const float* conv1_w= (const float*)d_in[9];
    const float* ln2_g  = (const float*)d_in[10];
    const float* ln2_b  = (const float*)d_in[11];
    const float* qkv2_w = (const float*)d_in[12];
    const float* out2_w = (const float*)d_in[13];
    const float* out2_b = (const float*)d_in[14];
    const float* conv2_w= (const float*)d_in[15];
    const float* pg7_w  = (const float*)d_in[16];
    const float* pg7_b  = (const float*)d_in[17];
    const float* pg5_w  = (const float*)d_in[18];
    const float* pg5_b  = (const float*)d_in[19];
    const float* pg3_w  = (const float*)d_in[20];
    const float* pg3_b  = (const float*)d_in[21];
    const float* norm_g = (const float*)d_in[22];
    const float* norm_b = (const float*)d_in[23];
    const float* fc2_w  = (const float*)d_in[24];
    const float* fc2_b  = (const float*)d_in[25];

    Bufs b;
    cudaGetSymbolAddress((void**)&b.h,    g_h);
    cudaGetSymbolAddress((void**)&b.t,    g_t);
    cudaGetSymbolAddress((void**)&b.xp,   g_xp);
    cudaGetSymbolAddress((void**)&b.qkv,  g_qkv);
    cudaGetSymbolAddress((void**)&b.kT,   g_kT);
    cudaGetSymbolAddress((void**)&b.s,    g_s);
    cudaGetSymbolAddress((void**)&b.ql,   g_ql);
    cudaGetSymbolAddress((void**)&b.klT,  g_klT);
    cudaGetSymbolAddress((void**)&b.a2,   g_a2);
    cudaGetSymbolAddress((void**)&b.z0,   g_z0);
    cudaGetSymbolAddress((void**)&b.z1,   g_z1);
    cudaGetSymbolAddress((void**)&b.xz,   g_xz);
    cudaGetSymbolAddress((void**)&b.u,    g_u);
    cudaGetSymbolAddress((void**)&b.tt,   g_tt);
    cudaGetSymbolAddress((void**)&b.part, g_part);
    cudaGetSymbolAddress((void**)&b.a3v,  g_a3v);
    cudaGetSymbolAddress((void**)&b.z2,   g_z2);
    cudaGetSymbolAddress((void**)&b.ab,   g_ab);
    cudaGetSymbolAddress((void**)&b.red,  g_red);

    // fc1: h rows 1..8192 = relu(x @ fc1_w + b)
    gemmL(x, 1024, 0, fc1_w, D, 0, b.h + D, D, 0, 8192, D, 1024, 1.0f, fc1_b, 1, 1);
    k_build<<<(90 * D + 255) / 256, 256>>>(b.h, cls);

    // layer 1 attention
    run_attn(b, ln1_g, ln1_b, qkv1_w, out1_w, out1_b, conv1_w);

    // PPEG: write into t (incl. cls row), then swap h <-> t
    k_ppeg<<<NPIX, 512>>>(b.h, b.t, pg7_w, pg7_b, pg5_w, pg5_b, pg3_w, pg3_b);
    { float* tmp = b.h; b.h = b.t; b.t = tmp; }

    // layer 2 attention
    run_attn(b, ln2_g, ln2_b, qkv2_w, out2_w, out2_b, conv2_w);

    // head
    k_final<<<1, 512>>>(b.h, norm_g, norm_b, fc2_w, fc2_b, (float*)d_out, out_size);
}

// round 9
// speedup vs baseline: 1.2434x; 1.2434x over previous
#include <cuda_runtime.h>
#include <math.h>

// ---------------- problem constants ----------------
#define NTOK   8282          // tokens incl. cls (1 + 8281)
#define PAD    166           // front zero-pad inside nystrom
#define NP     8448          // padded length = 33*256
#define D      512
#define H3D    1536          // 3*D
#define NH     8             // heads
#define DH     64
#define MLM    256           // landmarks
#define LWIN   33            // tokens per landmark
#define SCALE  0.125f        // DH^-0.5
#define HS     91            // ppeg grid 91x91 = 8281
#define NPIX   8281
#define KSPL   33            // split-K chunks for a3v (8448/33 = 256)

// ---------------- static device scratch ----------------
__device__ float g_h   [NP * D];
__device__ float g_t   [NP * D];
__device__ float g_xp  [NP * D];
__device__ float g_qkv [NP * H3D];
__device__ float g_kT  [NH * DH * NP];
__device__ float g_s   [NH * NP * MLM];      // reused: a3 scores then a1 scores
__device__ float g_ql  [NH * MLM * DH];
__device__ float g_klT [NH * DH * MLM];
__device__ float g_a2  [NH * MLM * MLM];
__device__ float g_z0  [NH * MLM * MLM];
__device__ float g_z1  [NH * MLM * MLM];
__device__ float g_xz  [NH * MLM * MLM];
__device__ float g_u   [NH * MLM * MLM];
__device__ float g_tt  [NH * MLM * MLM];
__device__ float g_part[NH * KSPL * MLM * DH];  // split-K partials for a3v
__device__ float g_a3v [NH * MLM * DH];
__device__ float g_z2  [NH * MLM * DH];
__device__ float g_ab  [NP * D];
__device__ float g_red [NH * 2];

// ---------------- block reductions ----------------
__device__ __forceinline__ float blkSum(float v, float* sh, int nt) {
    int tid = threadIdx.x;
    #pragma unroll
    for (int o = 16; o; o >>= 1) v += __shfl_down_sync(0xffffffffu, v, o);
    __syncthreads();
    if ((tid & 31) == 0) sh[tid >> 5] = v;
    __syncthreads();
    int nw = nt >> 5;
    float r = (tid < nw) ? sh[tid] : 0.0f;
    if (tid < 32) {
        for (int o = nw >> 1; o; o >>= 1) r += __shfl_down_sync(0xffffffffu, r, o);
    }
    if (tid == 0) sh[0] = r;
    __syncthreads();
    float res = sh[0];
    __syncthreads();
    return res;
}

__device__ __forceinline__ float blkMax(float v, float* sh, int nt) {
    int tid = threadIdx.x;
    #pragma unroll
    for (int o = 16; o; o >>= 1) v = fmaxf(v, __shfl_down_sync(0xffffffffu, v, o));
    __syncthreads();
    if ((tid & 31) == 0) sh[tid >> 5] = v;
    __syncthreads();
    int nw = nt >> 5;
    float r = (tid < nw) ? sh[tid] : -INFINITY;
    if (tid < 32) {
        for (int o = nw >> 1; o; o >>= 1) r = fmaxf(r, __shfl_down_sync(0xffffffffu, r, o));
    }
    if (tid == 0) sh[0] = r;
    __syncthreads();
    float res = sh[0];
    __syncthreads();
    return res;
}

// ---------------- tf32 helpers ----------------
__device__ __forceinline__ unsigned f2tf(float f) {
    unsigned u;
    asm("cvt.rna.tf32.f32 %0, %1;" : "=r"(u) : "f"(f));
    return u;
}

__device__ __forceinline__ void mma_tf32(float& c0, float& c1, float& c2, float& c3,
                                         unsigned a0, unsigned a1, unsigned a2, unsigned a3,
                                         unsigned b0, unsigned b1) {
    asm volatile(
        "mma.sync.aligned.m16n8k8.row.col.f32.tf32.tf32.f32 "
        "{%0,%1,%2,%3}, {%4,%5,%6,%7}, {%8,%9}, {%0,%1,%2,%3};"
        : "+f"(c0), "+f"(c1), "+f"(c2), "+f"(c3)
        : "r"(a0), "r"(a1), "r"(a2), "r"(a3), "r"(b0), "r"(b1));
}

// ---------------- 64x64 batched SGEMM (double-buffered, emode, split-K) ----
// C = alpha * A @ B' (+bias)(+relu); B' = B, or (cval*I - B) when emode=1.
// ksplit>1: z = batch*ksplit + chunk; A,B advance chunk*K along k; C indexed
// by z (per-z stride sC). K is the PER-CHUNK depth. M,N mult 64; K mult 16.
__global__ void __launch_bounds__(256) sgemm(
    const float* __restrict__ A, int lda, long long sA,
    const float* __restrict__ B, int ldb, long long sB,
    float* __restrict__ C, int ldc, long long sC,
    int M, int N, int K, float alpha,
    const float* __restrict__ bias, int relu,
    int emode, float cval, int ksplit)
{
    __shared__ float As[2][16][64];
    __shared__ float Bs[2][16][64];
    int bz = blockIdx.z / ksplit, ch = blockIdx.z % ksplit;
    A += (long long)bz * sA + (long long)ch * K;
    B += (long long)bz * sB + (long long)ch * K * ldb;
    C += (long long)blockIdx.z * sC;
    int tid = threadIdx.x;
    int tx = tid & 15, ty = tid >> 4;
    int row0 = blockIdx.y * 64, col0 = blockIdx.x * 64;
    int ar = tid >> 2, ak = (tid & 3) << 2;
    int bk = tid >> 4, bc = (tid & 15) << 2;
    float acc[4][4] = {};
    const float* Ap = A + (long long)(row0 + ar) * lda + ak;
    const float* Bp = B + (long long)bk * ldb + col0 + bc;
    int nt = K >> 4;

    float4 a4 = *reinterpret_cast<const float4*>(Ap);
    float4 b4 = *reinterpret_cast<const float4*>(Bp);
    if (emode) {
        int kr = bk;
        b4.x = ((kr == col0 + bc + 0) ? cval : 0.0f) - b4.x;
        b4.y = ((kr == col0 + bc + 1) ? cval : 0.0f) - b4.y;
        b4.z = ((kr == col0 + bc + 2) ? cval : 0.0f) - b4.z;
        b4.w = ((kr == col0 + bc + 3) ? cval : 0.0f) - b4.w;
    }
    As[0][ak + 0][ar] = a4.x; As[0][ak + 1][ar] = a4.y;
    As[0][ak + 2][ar] = a4.z; As[0][ak + 3][ar] = a4.w;
    *reinterpret_cast<float4*>(&Bs[0][bk][bc]) = b4;
    __syncthreads();

    int buf = 0;
    for (int t = 0; t < nt; t++) {
        float4 na, nb;
        if (t + 1 < nt) {
            na = *reinterpret_cast<const float4*>(Ap + (t + 1) * 16);
            nb = *reinterpret_cast<const float4*>(Bp + (long long)(t + 1) * 16 * ldb);
            if (emode) {
                int kr = (t + 1) * 16 + bk;
                nb.x = ((kr == col0 + bc + 0) ? cval : 0.0f) - nb.x;
                nb.y = ((kr == col0 + bc + 1) ? cval : 0.0f) - nb.y;
                nb.z = ((kr == col0 + bc + 2) ? cval : 0.0f) - nb.z;
                nb.w = ((kr == col0 + bc + 3) ? cval : 0.0f) - nb.w;
            }
        }
        #pragma unroll
        for (int kk = 0; kk < 16; kk++) {
            float4 av = *reinterpret_cast<const float4*>(&As[buf][kk][ty << 2]);
            float4 bv = *reinterpret_cast<const float4*>(&Bs[buf][kk][tx << 2]);
            acc[0][0] += av.x * bv.x; acc[0][1] += av.x * bv.y; acc[0][2] += av.x * bv.z; acc[0][3] += av.x * bv.w;
            acc[1][0] += av.y * bv.x; acc[1][1] += av.y * bv.y; acc[1][2] += av.y * bv.z; acc[1][3] += av.y * bv.w;
            acc[2][0] += av.z * bv.x; acc[2][1] += av.z * bv.y; acc[2][2] += av.z * bv.z; acc[2][3] += av.z * bv.w;
            acc[3][0] += av.w * bv.x; acc[3][1] += av.w * bv.y; acc[3][2] += av.w * bv.z; acc[3][3] += av.w * bv.w;
        }
        if (t + 1 < nt) {
            buf ^= 1;
            As[buf][ak + 0][ar] = na.x; As[buf][ak + 1][ar] = na.y;
            As[buf][ak + 2][ar] = na.z; As[buf][ak + 3][ar] = na.w;
            *reinterpret_cast<float4*>(&Bs[buf][bk][bc]) = nb;
            __syncthreads();
        }
    }
    #pragma unroll
    for (int i = 0; i < 4; i++) {
        int r = row0 + (ty << 2) + i;
        if (r >= M) continue;
        #pragma unroll
        for (int j = 0; j < 4; j++) {
            int c = col0 + (tx << 2) + j;
            if (c >= N) continue;
            float v = alpha * acc[i][j];
            if (bias) v += bias[c];
            if (relu) v = fmaxf(v, 0.0f);
            C[(long long)r * ldc + c] = v;
        }
    }
}

// ---------------- 128x128 tf32 tensor-core GEMM (double-buffered) --------
// C = alpha*A@B (+bias)(+relu). M,N mult of 128; K mult of 16.
// 256 threads = 8 warps (2x4); warp tile 64x32 via mma.m16n8k8.tf32.
// Smem padded to 136 words/row: fragment loads are bank-conflict-free
// (bank = 8*tg + g + const, all 32 distinct).
__global__ void __launch_bounds__(256) tgemm(
    const float* __restrict__ A, int lda, long long sA,
    const float* __restrict__ B, int ldb, long long sB,
    float* __restrict__ C, int ldc, long long sC,
    int M, int N, int K, float alpha,
    const float* __restrict__ bias, int relu)
{
    __shared__ unsigned As[2][16][136];
    __shared__ unsigned Bs[2][16][136];
    A += (long long)blockIdx.z * sA;
    B += (long long)blockIdx.z * sB;
    C += (long long)blockIdx.z * sC;
    int tid = threadIdx.x;
    int row0 = blockIdx.y * 128, col0 = blockIdx.x * 128;
    int wid = tid >> 5, lane = tid & 31;
    int wr = wid >> 2, wc = wid & 3;          // 2 x 4 warp grid
    int g = lane >> 2, tg = lane & 3;         // groupID / threadID_in_group
    int ar = tid >> 1, ak = (tid & 1) << 3;   // A: 128 rows x 16 k (8 floats/thread)
    int bk = tid >> 4, bc = (tid & 15) << 3;  // B: 16 k x 128 cols (8 floats/thread)
    const float* Ap = A + (long long)(row0 + ar) * lda + ak;
    const float* Bp = B + (long long)bk * ldb + col0 + bc;
    float acc[4][4][4];
    #pragma unroll
    for (int i = 0; i < 4; i++)
        #pragma unroll
        for (int j = 0; j < 4; j++)
            #pragma unroll
            for (int k = 0; k < 4; k++) acc[i][j][k] = 0.0f;
    int nt = K >> 4;

    // prologue: tile 0 -> buffer 0
    {
        float4 a0 = *reinterpret_cast<const float4*>(Ap);
        float4 a1 = *reinterpret_cast<const float4*>(Ap + 4);
        float4 b0 = *reinterpret_cast<const float4*>(Bp);
        float4 b1 = *reinterpret_cast<const float4*>(Bp + 4);
        As[0][ak + 0][ar] = f2tf(a0.x); As[0][ak + 1][ar] = f2tf(a0.y);
        As[0][ak + 2][ar] = f2tf(a0.z); As[0][ak + 3][ar] = f2tf(a0.w);
        As[0][ak + 4][ar] = f2tf(a1.x); As[0][ak + 5][ar] = f2tf(a1.y);
        As[0][ak + 6][ar] = f2tf(a1.z); As[0][ak + 7][ar] = f2tf(a1.w);
        Bs[0][bk][bc + 0] = f2tf(b0.x); Bs[0][bk][bc + 1] = f2tf(b0.y);
        Bs[0][bk][bc + 2] = f2tf(b0.z); Bs[0][bk][bc + 3] = f2tf(b0.w);
        Bs[0][bk][bc + 4] = f2tf(b1.x); Bs[0][bk][bc + 5] = f2tf(b1.y);
        Bs[0][bk][bc + 6] = f2tf(b1.z); Bs[0][bk][bc + 7] = f2tf(b1.w);
    }
    __syncthreads();

    int buf = 0;
    for (int t = 0; t < nt; t++) {
        float4 na0, na1, nb0, nb1;
        if (t + 1 < nt) {
            na0 = *reinterpret_cast<const float4*>(Ap + (t + 1) * 16);
            na1 = *reinterpret_cast<const float4*>(Ap + (t + 1) * 16 + 4);
            nb0 = *reinterpret_cast<const float4*>(Bp + (long long)(t + 1) * 16 * ldb);
            nb1 = *reinterpret_cast<const float4*>(Bp + (long long)(t + 1) * 16 * ldb + 4);
        }
        #pragma unroll
        for (int kb = 0; kb < 16; kb += 8) {
            unsigned af[4][4], bf[4][2];
            #pragma unroll
            for (int mi = 0; mi < 4; mi++) {
                int r = wr * 64 + mi * 16 + g;
                af[mi][0] = As[buf][kb + tg][r];
                af[mi][1] = As[buf][kb + tg][r + 8];
                af[mi][2] = As[buf][kb + tg + 4][r];
                af[mi][3] = As[buf][kb + tg + 4][r + 8];
            }
            #pragma unroll
            for (int ni = 0; ni < 4; ni++) {
                int cc = wc * 32 + ni * 8 + g;
                bf[ni][0] = Bs[buf][kb + tg][cc];
                bf[ni][1] = Bs[buf][kb + tg + 4][cc];
            }
            #pragma unroll
            for (int mi = 0; mi < 4; mi++)
                #pragma unroll
                for (int ni = 0; ni < 4; ni++)
                    mma_tf32(acc[mi][ni][0], acc[mi][ni][1], acc[mi][ni][2], acc[mi][ni][3],
                             af[mi][0], af[mi][1], af[mi][2], af[mi][3],
                             bf[ni][0], bf[ni][1]);
        }
        if (t + 1 < nt) {
            buf ^= 1;
            As[buf][ak + 0][ar] = f2tf(na0.x); As[buf][ak + 1][ar] = f2tf(na0.y);
            As[buf][ak + 2][ar] = f2tf(na0.z); As[buf][ak + 3][ar] = f2tf(na0.w);
            As[buf][ak + 4][ar] = f2tf(na1.x); As[buf][ak + 5][ar] = f2tf(na1.y);
            As[buf][ak + 6][ar] = f2tf(na1.z); As[buf][ak + 7][ar] = f2tf(na1.w);
            Bs[buf][bk][bc + 0] = f2tf(nb0.x); Bs[buf][bk][bc + 1] = f2tf(nb0.y);
            Bs[buf][bk][bc + 2] = f2tf(nb0.z); Bs[buf][bk][bc + 3] = f2tf(nb0.w);
            Bs[buf][bk][bc + 4] = f2tf(nb1.x); Bs[buf][bk][bc + 5] = f2tf(nb1.y);
            Bs[buf][bk][bc + 6] = f2tf(nb1.z); Bs[buf][bk][bc + 7] = f2tf(nb1.w);
            __syncthreads();
        }
    }

    // epilogue: c0=(g,2tg) c1=(g,2tg+1) c2=(g+8,2tg) c3=(g+8,2tg+1)
    #pragma unroll
    for (int mi = 0; mi < 4; mi++) {
        int r = row0 + wr * 64 + mi * 16 + g;
        #pragma unroll
        for (int ni = 0; ni < 4; ni++) {
            int cc = col0 + wc * 32 + ni * 8 + 2 * tg;
            float2 v0, v1;
            v0.x = alpha * acc[mi][ni][0]; v0.y = alpha * acc[mi][ni][1];
            v1.x = alpha * acc[mi][ni][2]; v1.y = alpha * acc[mi][ni][3];
            if (bias) {
                float b0 = bias[cc], b1 = bias[cc + 1];
                v0.x += b0; v0.y += b1; v1.x += b0; v1.y += b1;
            }
            if (relu) {
                v0.x = fmaxf(v0.x, 0.0f); v0.y = fmaxf(v0.y, 0.0f);
                v1.x = fmaxf(v1.x, 0.0f); v1.y = fmaxf(v1.y, 0.0f);
            }
            *reinterpret_cast<float2*>(&C[(long long)r * ldc + cc]) = v0;
            *reinterpret_cast<float2*>(&C[(long long)(r + 8) * ldc + cc]) = v1;
        }
    }
}

// ---------------- misc kernels ----------------
__global__ void k_zero(float* p, int n) {
    int i = blockIdx.x * 256 + threadIdx.x;
    if (i < n) p[i] = 0.0f;
}

// deterministic reduction of KSPL split-K partials
__global__ void k_redsplit(const float* __restrict__ part, float* __restrict__ out) {
    int i = blockIdx.x * 256 + threadIdx.x;
    if (i >= NH * MLM * DH) return;
    int b = i / (MLM * DH), r = i - b * (MLM * DH);
    const float* p = part + ((long long)b * KSPL) * (MLM * DH) + r;
    float s = 0.0f;
    #pragma unroll 1
    for (int ch = 0; ch < KSPL; ch++) s += p[(long long)ch * (MLM * DH)];
    out[i] = s;
}

// h rows 1..8192 already hold relu(fc1). Set row0=cls, wrap rows 8193..8281 <- rows 1..89.
__global__ void k_build(float* h, const float* cls) {
    int idx = blockIdx.x * 256 + threadIdx.x;
    if (idx < D) h[idx] = cls[idx];
    int j = idx - D;
    if (j >= 0 && j < 89 * D) {
        int r = j / D, c = j - r * D;
        h[(long long)(8193 + r) * D + c] = h[(long long)(1 + r) * D + c];
    }
}

__global__ void k_ln(const float* __restrict__ in, float* __restrict__ out,
                     const float* __restrict__ gg, const float* __restrict__ bb, int rows) {
    __shared__ float sh[32];
    int r = blockIdx.x;
    if (r >= rows) return;
    const float* x = in + (long long)r * D;
    int tid = threadIdx.x;
    float v0 = x[tid], v1 = x[tid + 256];
    float s  = blkSum(v0 + v1, sh, 256);
    float s2 = blkSum(v0 * v0 + v1 * v1, sh, 256);
    float mu = s * (1.0f / 512.0f);
    float var = s2 * (1.0f / 512.0f) - mu * mu;
    float inv = rsqrtf(var + 1e-5f);
    float* o = out + (long long)r * D;
    o[tid]       = (v0 - mu) * inv * gg[tid] + bb[tid];
    o[tid + 256] = (v1 - mu) * inv * gg[tid + 256] + bb[tid + 256];
}

// generic softmax (rows of arbitrary len); exp cached on pass 2
__global__ void k_softmax(float* __restrict__ S, int len) {
    __shared__ float sh[32];
    float* row = S + (long long)blockIdx.x * len;
    int tid = threadIdx.x;
    float m = -INFINITY;
    for (int i = tid; i < len; i += 256) m = fmaxf(m, row[i]);
    m = blkMax(m, sh, 256);
    float s = 0.0f;
    for (int i = tid; i < len; i += 256) {
        float e = __expf(row[i] - m);
        row[i] = e;
        s += e;
    }
    s = blkSum(s, sh, 256);
    float inv = 1.0f / s;
    for (int i = tid; i < len; i += 256) row[i] *= inv;
}

// one-pass softmax for rows of exactly 256 (one element per thread)
__global__ void k_softmax256(float* __restrict__ S) {
    __shared__ float sh[32];
    int tid = threadIdx.x;
    float* row = S + (long long)blockIdx.x * 256;
    float v = row[tid];
    float m = blkMax(v, sh, 256);
    float e = __expf(v - m);
    float s = blkSum(e, sh, 256);
    row[tid] = e / s;
}

// landmark means: ql[h][m][d] = mean_t q[m*33+t][h*64+d]; klT[h][d][m] = mean_t k[...]
__global__ void k_landmark(const float* __restrict__ qkv, float* __restrict__ ql,
                           float* __restrict__ klT) {
    int m = blockIdx.x, h = blockIdx.y, d = threadIdx.x;
    const float* base = qkv + (long long)(m * LWIN) * H3D + h * DH + d;
    float qs = 0.0f, ks = 0.0f;
    for (int t = 0; t < LWIN; t++) {
        qs += base[(long long)t * H3D];
        ks += base[(long long)t * H3D + D];
    }
    ql[((h * MLM) + m) * DH + d]  = qs * (1.0f / 33.0f);
    klT[((h * DH) + d) * MLM + m] = ks * (1.0f / 33.0f);
}

// kT[c][n] = qkv[n][D + c]  (c = h*64+d), tiled transpose
__global__ void k_transpose(const float* __restrict__ src, float* __restrict__ dst) {
    __shared__ float tile[32][33];
    int c0 = blockIdx.x * 32, n0 = blockIdx.y * 32;
    for (int i = threadIdx.y; i < 32; i += 8)
        tile[i][threadIdx.x] = src[(long long)(n0 + i) * H3D + D + c0 + threadIdx.x];
    __syncthreads();
    for (int i = threadIdx.y; i < 32; i += 8)
        dst[(long long)(c0 + i) * NP + n0 + threadIdx.x] = tile[threadIdx.x][i];
}

// per-head reductions: red[h*2]=max row-sum |a2_h|, red[h*2+1]=max col-sum |a2_h|
__global__ void k_pinv_red(const float* __restrict__ a2, float* __restrict__ red) {
    __shared__ float sh[32];
    int h = blockIdx.x;
    const float* A = a2 + (long long)h * MLM * MLM;
    int i = threadIdx.x;
    float rs = 0.0f, cs = 0.0f;
    for (int j = 0; j < MLM; j++) {
        rs += fabsf(A[i * MLM + j]);
        cs += fabsf(A[j * MLM + i]);
    }
    float colv = blkMax(rs, sh, 256);
    float rowv = blkMax(cs, sh, 256);
    if (i == 0) { red[h * 2] = colv; red[h * 2 + 1] = rowv; }
}

// z0 = a2^T / (col*row), col/row are GLOBAL maxima across all heads (matches
// jnp .max() with no axis argument in the reference).
__global__ void k_pinv_zinit(const float* __restrict__ a2, const float* __restrict__ red,
                             float* __restrict__ z) {
    int idx = blockIdx.x * 256 + threadIdx.x;
    if (idx >= NH * MLM * MLM) return;
    float colm = 0.0f, rowm = 0.0f;
    #pragma unroll
    for (int hh = 0; hh < NH; hh++) {
        colm = fmaxf(colm, red[hh * 2]);
        rowm = fmaxf(rowm, red[hh * 2 + 1]);
    }
    int h = idx >> 16;
    int r = (idx >> 8) & 255;
    int c = idx & 255;
    z[idx] = a2[((long long)h << 16) + c * MLM + r] / (colm * rowm);
}

// depthwise 33-tap conv over sequence of v, added to ab (float4: 4 ch/thread)
__global__ void k_conv(const float* __restrict__ qkv, const float* __restrict__ w,
                       float* __restrict__ ab) {
    __shared__ float ws[NH * LWIN];
    int tid = threadIdx.x;   // 128 threads, each handles 4 channels
    for (int i = tid; i < NH * LWIN; i += 128) ws[i] = w[i];
    __syncthreads();
    int n = blockIdx.x;
    int c4 = tid << 2;            // 0,4,...,508 — all 4 within one head
    int h = c4 >> 6;
    const float* wrow = ws + h * LWIN;
    float4 s = make_float4(0.0f, 0.0f, 0.0f, 0.0f);
    #pragma unroll
    for (int t = 0; t < LWIN; t++) {
        int nn = n - 16 + t;
        if (nn >= 0 && nn < NP) {
            float wv = wrow[t];
            float4 v = *reinterpret_cast<const float4*>(
                qkv + (long long)nn * H3D + 2 * D + c4);
            s.x += wv * v.x; s.y += wv * v.y; s.z += wv * v.z; s.w += wv * v.w;
        }
    }
    float4* dst = reinterpret_cast<float4*>(ab + (long long)n * D + c4);
    float4 o = *dst;
    o.x += s.x; o.y += s.y; o.z += s.z; o.w += s.w;
    *dst = o;
}

__global__ void k_resid(float* __restrict__ h, const float* __restrict__ t) {
    int idx = blockIdx.x * 256 + threadIdx.x;   // float4 index
    if (idx < (NTOK * D) / 4) {
        float4 a = reinterpret_cast<float4*>(h)[idx];
        float4 b = reinterpret_cast<const float4*>(t + PAD * D)[idx];
        a.x += b.x; a.y += b.y; a.z += b.z; a.w += b.w;
        reinterpret_cast<float4*>(h)[idx] = a;
    }
}

// PPEG: out row 1+p = center + dw7 + dw5 + dw3 (+biases). 512 threads = channels.
// Block 0 also carries the cls row (row 0) into out.
__global__ void k_ppeg(const float* __restrict__ h, float* __restrict__ out,
                       const float* __restrict__ w7, const float* __restrict__ b7,
                       const float* __restrict__ w5, const float* __restrict__ b5,
                       const float* __restrict__ w3, const float* __restrict__ b3) {
    int p = blockIdx.x;
    int y = p / HS, x = p - y * HS;
    int c = threadIdx.x;
    if (p == 0) out[c] = h[c];
    float acc = h[(long long)(1 + p) * D + c] + b7[c] + b5[c] + b3[c];
    const float* W7 = w7 + c * 49;
    const float* W5 = w5 + c * 25;
    const float* W3 = w3 + c * 9;
    #pragma unroll
    for (int ky = 0; ky < 7; ky++) {
        int yy = y + ky - 3;
        if (yy < 0 || yy >= HS) continue;
        #pragma unroll
        for (int kx = 0; kx < 7; kx++) {
            int xx = x + kx - 3;
            if (xx < 0 || xx >= HS) continue;
            float v = h[(long long)(1 + yy * HS + xx) * D + c];
            float wsum = W7[ky * 7 + kx];
            if (ky >= 1 && ky <= 5 && kx >= 1 && kx <= 5) wsum += W5[(ky - 1) * 5 + (kx - 1)];
            if (ky >= 2 && ky <= 4 && kx >= 2 && kx <= 4) wsum += W3[(ky - 2) * 3 + (kx - 2)];
            acc += v * wsum;
        }
    }
    out[(long long)(1 + p) * D + c] = acc;
}

// final: emb = ln(h[0]); logits = emb@fc2 + b; softmax; argmax
__global__ void k_final(const float* __restrict__ h, const float* __restrict__ gg,
                        const float* __restrict__ bb, const float* __restrict__ fw,
                        const float* __restrict__ fb, float* __restrict__ out, int out_size) {
    __shared__ float sh[32];
    __shared__ float emb[512];
    int tid = threadIdx.x;
    float v = h[tid];
    float s  = blkSum(v, sh, 512);
    float s2 = blkSum(v * v, sh, 512);
    float mu = s * (1.0f / 512.0f);
    float var = s2 * (1.0f / 512.0f) - mu * mu;
    float inv = rsqrtf(var + 1e-5f);
    float e = (v - mu) * inv * gg[tid] + bb[tid];
    emb[tid] = e;
    if (5 + tid < out_size) out[5 + tid] = e;
    __syncthreads();
    if (tid == 0) {
        float l0 = fb[0], l1 = fb[1];
        for (int c = 0; c < 512; c++) { l0 += emb[c] * fw[2 * c]; l1 += emb[c] * fw[2 * c + 1]; }
        if (out_size > 0) out[0] = l0;
        if (out_size > 1) out[1] = l1;
        float m = fmaxf(l0, l1);
        float e0 = __expf(l0 - m), e1 = __expf(l1 - m);
        float ss = e0 + e1;
        if (out_size > 2) out[2] = e0 / ss;
        if (out_size > 3) out[3] = e1 / ss;
        if (out_size > 4) out[4] = (l1 > l0) ? 1.0f : 0.0f;
    }
}

// ---------------- host orchestration ----------------
static inline void gemm(const float* A, int lda, long long sA,
                        const float* B, int ldb, long long sB,
                        float* C, int ldc, long long sC,
                        int M, int N, int K, float alpha,
                        const float* bias, int relu, int batch,
                        int emode = 0, float cval = 0.0f, int ksplit = 1) {
    dim3 g(N / 64, M / 64, batch * ksplit);
    sgemm<<<g, 256>>>(A, lda, sA, B, ldb, sB, C, ldc, sC, M, N, K, alpha, bias, relu,
                      emode, cval, ksplit);
}

static inline void gemmL(const float* A, int lda, long long sA,
                         const float* B, int ldb, long long sB,
                         float* C, int ldc, long long sC,
                         int M, int N, int K, float alpha,
                         const float* bias, int relu, int batch) {
    dim3 g(N / 128, M / 128, batch);
    tgemm<<<g, 256>>>(A, lda, sA, B, ldb, sB, C, ldc, sC, M, N, K, alpha, bias, relu);
}

struct Bufs {
    float *h, *t, *xp, *qkv, *kT, *s, *ql, *klT, *a2, *z0, *z1, *xz, *u, *tt,
          *part, *a3v, *z2, *ab, *red;
};

static void run_attn(Bufs& b, const float* lng, const float* lnb,
                     const float* qkvw, const float* outw, const float* outb,
                     const float* convw) {
    k_zero<<<(PAD * D + 255) / 256, 256>>>(b.xp, PAD * D);
    k_ln<<<NTOK, 256>>>(b.h, b.xp + (long long)PAD * D, lng, lnb, NTOK);
    gemmL(b.xp, D, 0, qkvw, H3D, 0, b.qkv, H3D, 0, NP, H3D, D, 1.0f, nullptr, 0, 1);
    k_landmark<<<dim3(MLM, NH), DH>>>(b.qkv, b.ql, b.klT);
    k_transpose<<<dim3(D / 32, NP / 32), dim3(32, 8)>>>(b.qkv, b.kT);
    // a2 = softmax(SCALE * ql @ kl^T)
    gemm(b.ql, DH, MLM * DH, b.klT, MLM, DH * MLM, b.a2, MLM, MLM * MLM,
         MLM, MLM, DH, SCALE, nullptr, 0, NH);
    k_softmax256<<<NH * MLM, 256>>>(b.a2);
    // pinv: z = 0.25 * z @ (13I - xz @ (15I - xz @ (7I - xz))), xz = a2@z
    k_pinv_red<<<NH, 256>>>(b.a2, b.red);
    k_pinv_zinit<<<(NH * MLM * MLM + 255) / 256, 256>>>(b.a2, b.red, b.z0);
    float* zc = b.z0; float* zn = b.z1;
    const long long SB = (long long)MLM * MLM;
    for (int it = 0; it < 6; it++) {
        gemm(b.a2, MLM, SB, zc, MLM, SB, b.xz, MLM, SB, MLM, MLM, MLM, 1.0f, nullptr, 0, NH);
        gemm(b.xz, MLM, SB, b.xz, MLM, SB, b.u,  MLM, SB, MLM, MLM, MLM, 1.0f, nullptr, 0, NH, 1, 7.0f);
        gemm(b.xz, MLM, SB, b.u,  MLM, SB, b.tt, MLM, SB, MLM, MLM, MLM, 1.0f, nullptr, 0, NH, 1, 15.0f);
        gemm(zc,   MLM, SB, b.tt, MLM, SB, zn,   MLM, SB, MLM, MLM, MLM, 0.25f, nullptr, 0, NH, 1, 13.0f);
        float* sw = zc; zc = zn; zn = sw;
    }
    // a3 = softmax_n(SCALE * ql @ k^T)
    gemmL(b.ql, DH, MLM * DH, b.kT, NP, (long long)DH * NP, b.s, NP, (long long)MLM * NP,
          MLM, NP, DH, SCALE, nullptr, 0, NH);
    k_softmax<<<NH * MLM, 256>>>(b.s, NP);
    // a3v = a3 @ v  (split-K: 33 chunks of 256, deterministic reduce)
    gemm(b.s, NP, (long long)MLM * NP, b.qkv + 2 * D, H3D, DH,
         b.part, DH, (long long)MLM * DH,
         MLM, DH, NP / KSPL, 1.0f, nullptr, 0, NH, 0, 0.0f, KSPL);
    k_redsplit<<<(NH * MLM * DH + 255) / 256, 256>>>(b.part, b.a3v);
    // z2 = pinv @ a3v
    gemm(zc, MLM, SB, b.a3v, DH, MLM * DH, b.z2, DH, MLM * DH, MLM, DH, MLM, 1.0f, nullptr, 0, NH);
    // a1 = softmax(SCALE * q @ kl^T); ab = a1 @ z2 (per head into column slices)
    gemmL(b.qkv, H3D, DH, b.klT, MLM, DH * MLM, b.s, MLM, (long long)NP * MLM,
          NP, MLM, DH, SCALE, nullptr, 0, NH);
    k_softmax256<<<NH * NP, 256>>>(b.s);
    gemm(b.s, MLM, (long long)NP * MLM, b.z2, DH, MLM * DH, b.ab, D, DH,
         NP, DH, MLM, 1.0f, nullptr, 0, NH);
    // + depthwise conv(v)
    k_conv<<<NP, 128>>>(b.qkv, convw, b.ab);
    // proj + residual (last NTOK rows)
    gemmL(b.ab, D, 0, outw, D, 0, b.t, D, 0, NP, D, D, 1.0f, outb, 0, 1);
    k_resid<<<((NTOK * D / 4) + 255) / 256, 256>>>(b.h, b.t);
}

extern "C" void kernel_launch(void* const* d_in, const int* in_sizes, int n_in,
                              void* d_out, int out_size) {
    const float* x      = (const float*)d_in[0];
    const float* fc1_w  = (const float*)d_in[1];
    const float* fc1_b  = (const float*)d_in[2];
    const float* cls    = (const float*)d_in[3];
    const float* ln1_g  = (const float*)d_in[4];
    const float* ln1_b  = (const float*)d_in[5];
    const float* qkv1_w = (const float*)d_in[6];
    const float* out1_w = (const float*)d_in[7];
    const float* out1_b = (const float*)d_in[8];
    const float* conv1_w= (const float*)d_in[9];
    const float* ln2_g  = (const float*)d_in[10];
    const float* ln2_b  = (const float*)d_in[11];
    const float* qkv2_w = (const float*)d_in[12];
    const float* out2_w = (const float*)d_in[13];
    const float* out2_b = (const float*)d_in[14];
    const float* conv2_w= (const float*)d_in[15];
    const float* pg7_w  = (const float*)d_in[16];
    const float* pg7_b  = (const float*)d_in[17];
    const float* pg5_w  = (const float*)d_in[18];
    const float* pg5_b  = (const float*)d_in[19];
    const float* pg3_w  = (const float*)d_in[20];
    const float* pg3_b  = (const float*)d_in[21];
    const float* norm_g = (const float*)d_in[22];
    const float* norm_b = (const float*)d_in[23];
    const float* fc2_w  = (const float*)d_in[24];
    const float* fc2_b  = (const float*)d_in[25];

    Bufs b;
    cudaGetSymbolAddress((void**)&b.h,    g_h);
    cudaGetSymbolAddress((void**)&b.t,    g_t);
    cudaGetSymbolAddress((void**)&b.xp,   g_xp);
    cudaGetSymbolAddress((void**)&b.qkv,  g_qkv);
    cudaGetSymbolAddress((void**)&b.kT,   g_kT);
    cudaGetSymbolAddress((void**)&b.s,    g_s);
    cudaGetSymbolAddress((void**)&b.ql,   g_ql);
    cudaGetSymbolAddress((void**)&b.klT,  g_klT);
    cudaGetSymbolAddress((void**)&b.a2,   g_a2);
    cudaGetSymbolAddress((void**)&b.z0,   g_z0);
    cudaGetSymbolAddress((void**)&b.z1,   g_z1);
    cudaGetSymbolAddress((void**)&b.xz,   g_xz);
    cudaGetSymbolAddress((void**)&b.u,    g_u);
    cudaGetSymbolAddress((void**)&b.tt,   g_tt);
    cudaGetSymbolAddress((void**)&b.part, g_part);
    cudaGetSymbolAddress((void**)&b.a3v,  g_a3v);
    cudaGetSymbolAddress((void**)&b.z2,   g_z2);
    cudaGetSymbolAddress((void**)&b.ab,   g_ab);
    cudaGetSymbolAddress((void**)&b.red,  g_red);

    // fc1: h rows 1..8192 = relu(x @ fc1_w + b)
    gemmL(x, 1024, 0, fc1_w, D, 0, b.h + D, D, 0, 8192, D, 1024, 1.0f, fc1_b, 1, 1);
    k_build<<<(90 * D + 255) / 256, 256>>>(b.h, cls);

    // layer 1 attention
    run_attn(b, ln1_g, ln1_b, qkv1_w, out1_w, out1_b, conv1_w);

    // PPEG: write into t (incl. cls row), then swap h <-> t
    k_ppeg<<<NPIX, 512>>>(b.h, b.t, pg7_w, pg7_b, pg5_w, pg5_b, pg3_w, pg3_b);
    { float* tmp = b.h; b.h = b.t; b.t = tmp; }

    // layer 2 attention
    run_attn(b, ln2_g, ln2_b, qkv2_w, out2_w, out2_b, conv2_w);

    // head
    k_final<<<1, 512>>>(b.h, norm_g, norm_b, fc2_w, fc2_b, (float*)d_out, out_size);
}

// round 12
// speedup vs baseline: 1.5292x; 1.2298x over previous
#include <cuda_runtime.h>
#include <math.h>

// ---------------- problem constants ----------------
#define NTOK   8282          // tokens incl. cls (1 + 8281)
#define PAD    166           // front zero-pad inside nystrom
#define NP     8448          // padded length = 33*256
#define D      512
#define H3D    1536          // 3*D
#define NH     8             // heads
#define DH     64
#define MLM    256           // landmarks
#define LWIN   33            // tokens per landmark
#define SCALE  0.125f        // DH^-0.5
#define HS     91            // ppeg grid 91x91 = 8281
#define NPIX   8281
#define KSPL   33            // split-K chunks for a3v (8448/33 = 256)

// ---------------- static device scratch ----------------
__device__ float g_h   [NP * D];
__device__ float g_t   [NP * D];
__device__ float g_xp  [NP * D];
__device__ float g_qkv [NP * H3D];
__device__ float g_kT  [NH * DH * NP];
__device__ float g_s   [NH * NP * MLM];      // reused: a3 scores then a1 scores
__device__ float g_ql  [NH * MLM * DH];
__device__ float g_klT [NH * DH * MLM];
__device__ float g_a2  [NH * MLM * MLM];
__device__ float g_z0  [NH * MLM * MLM];
__device__ float g_z1  [NH * MLM * MLM];
__device__ float g_xz  [NH * MLM * MLM];
__device__ float g_u   [NH * MLM * MLM];
__device__ float g_tt  [NH * MLM * MLM];
__device__ float g_part[NH * KSPL * MLM * DH];  // split-K partials for a3v
__device__ float g_a3v [NH * MLM * DH];
__device__ float g_z2  [NH * MLM * DH];
__device__ float g_ab  [NP * D];
__device__ float g_red [NH * 2];

// ---------------- block reductions ----------------
__device__ __forceinline__ float blkSum(float v, float* sh, int nt) {
    int tid = threadIdx.x;
    #pragma unroll
    for (int o = 16; o; o >>= 1) v += __shfl_down_sync(0xffffffffu, v, o);
    __syncthreads();
    if ((tid & 31) == 0) sh[tid >> 5] = v;
    __syncthreads();
    int nw = nt >> 5;
    float r = (tid < nw) ? sh[tid] : 0.0f;
    if (tid < 32) {
        for (int o = nw >> 1; o; o >>= 1) r += __shfl_down_sync(0xffffffffu, r, o);
    }
    if (tid == 0) sh[0] = r;
    __syncthreads();
    float res = sh[0];
    __syncthreads();
    return res;
}

__device__ __forceinline__ float blkMax(float v, float* sh, int nt) {
    int tid = threadIdx.x;
    #pragma unroll
    for (int o = 16; o; o >>= 1) v = fmaxf(v, __shfl_down_sync(0xffffffffu, v, o));
    __syncthreads();
    if ((tid & 31) == 0) sh[tid >> 5] = v;
    __syncthreads();
    int nw = nt >> 5;
    float r = (tid < nw) ? sh[tid] : -INFINITY;
    if (tid < 32) {
        for (int o = nw >> 1; o; o >>= 1) r = fmaxf(r, __shfl_down_sync(0xffffffffu, r, o));
    }
    if (tid == 0) sh[0] = r;
    __syncthreads();
    float res = sh[0];
    __syncthreads();
    return res;
}

// ---------------- tf32 helpers ----------------
__device__ __forceinline__ unsigned f2tf(float f) {
    unsigned u;
    asm("cvt.rna.tf32.f32 %0, %1;" : "=r"(u) : "f"(f));
    return u;
}

__device__ __forceinline__ void mma_tf32(float& c0, float& c1, float& c2, float& c3,
                                         unsigned a0, unsigned a1, unsigned a2, unsigned a3,
                                         unsigned b0, unsigned b1) {
    asm volatile(
        "mma.sync.aligned.m16n8k8.row.col.f32.tf32.tf32.f32 "
        "{%0,%1,%2,%3}, {%4,%5,%6,%7}, {%8,%9}, {%0,%1,%2,%3};"
        : "+f"(c0), "+f"(c1), "+f"(c2), "+f"(c3)
        : "r"(a0), "r"(a1), "r"(a2), "r"(a3), "r"(b0), "r"(b1));
}

// ---------------- 64x64 tf32 tensor GEMM (double-buffered, emode, split-K) --
// C = alpha * A @ B' (+bias)(+relu); B' = B, or (cval*I - B) when emode=1.
// ksplit>1: z = batch*ksplit + chunk; A,B advance chunk*K along k; C indexed
// by z (per-z stride sC). K is PER-CHUNK depth. M,N mult 64; K mult 16.
// 128 threads = 4 warps (2x2); warp tile 32x32 via mma.m16n8k8.tf32.
__global__ void __launch_bounds__(128) tgemm64(
    const float* __restrict__ A, int lda, long long sA,
    const float* __restrict__ B, int ldb, long long sB,
    float* __restrict__ C, int ldc, long long sC,
    int M, int N, int K, float alpha,
    const float* __restrict__ bias, int relu,
    int emode, float cval, int ksplit)
{
    __shared__ unsigned As[2][16][72];
    __shared__ unsigned Bs[2][16][72];
    int bz = blockIdx.z / ksplit, ch = blockIdx.z % ksplit;
    A += (long long)bz * sA + (long long)ch * K;
    B += (long long)bz * sB + (long long)ch * K * ldb;
    C += (long long)blockIdx.z * sC;
    int tid = threadIdx.x;
    int row0 = blockIdx.y * 64, col0 = blockIdx.x * 64;
    int wid = tid >> 5, lane = tid & 31;
    int wr = wid >> 1, wc = wid & 1;         // 2x2 warp grid
    int g = lane >> 2, tg = lane & 3;
    int ar = tid >> 1, ak = (tid & 1) << 3;  // A: 64 rows x 16 k (8 floats/thread)
    int bk = tid >> 3, bc = (tid & 7) << 3;  // B: 16 k x 64 cols (8 floats/thread)
    const float* Ap = A + (long long)(row0 + ar) * lda + ak;
    const float* Bp = B + (long long)bk * ldb + col0 + bc;
    float acc[2][4][4];
    #pragma unroll
    for (int i = 0; i < 2; i++)
        #pragma unroll
        for (int j = 0; j < 4; j++)
            #pragma unroll
            for (int k = 0; k < 4; k++) acc[i][j][k] = 0.0f;
    int nt = K >> 4;

    // prologue
    {
        float4 a0 = *reinterpret_cast<const float4*>(Ap);
        float4 a1 = *reinterpret_cast<const float4*>(Ap + 4);
        float4 b0 = *reinterpret_cast<const float4*>(Bp);
        float4 b1 = *reinterpret_cast<const float4*>(Bp + 4);
        if (emode) {
            int kr = bk, cb = col0 + bc;
            b0.x = ((kr == cb + 0) ? cval : 0.0f) - b0.x;
            b0.y = ((kr == cb + 1) ? cval : 0.0f) - b0.y;
            b0.z = ((kr == cb + 2) ? cval : 0.0f) - b0.z;
            b0.w = ((kr == cb + 3) ? cval : 0.0f) - b0.w;
            b1.x = ((kr == cb + 4) ? cval : 0.0f) - b1.x;
            b1.y = ((kr == cb + 5) ? cval : 0.0f) - b1.y;
            b1.z = ((kr == cb + 6) ? cval : 0.0f) - b1.z;
            b1.w = ((kr == cb + 7) ? cval : 0.0f) - b1.w;
        }
        As[0][ak + 0][ar] = f2tf(a0.x); As[0][ak + 1][ar] = f2tf(a0.y);
        As[0][ak + 2][ar] = f2tf(a0.z); As[0][ak + 3][ar] = f2tf(a0.w);
        As[0][ak + 4][ar] = f2tf(a1.x); As[0][ak + 5][ar] = f2tf(a1.y);
        As[0][ak + 6][ar] = f2tf(a1.z); As[0][ak + 7][ar] = f2tf(a1.w);
        Bs[0][bk][bc + 0] = f2tf(b0.x); Bs[0][bk][bc + 1] = f2tf(b0.y);
        Bs[0][bk][bc + 2] = f2tf(b0.z); Bs[0][bk][bc + 3] = f2tf(b0.w);
        Bs[0][bk][bc + 4] = f2tf(b1.x); Bs[0][bk][bc + 5] = f2tf(b1.y);
        Bs[0][bk][bc + 6] = f2tf(b1.z); Bs[0][bk][bc + 7] = f2tf(b1.w);
    }
    __syncthreads();

    int buf = 0;
    for (int t = 0; t < nt; t++) {
        float4 na0, na1, nb0, nb1;
        if (t + 1 < nt) {
            na0 = *reinterpret_cast<const float4*>(Ap + (t + 1) * 16);
            na1 = *reinterpret_cast<const float4*>(Ap + (t + 1) * 16 + 4);
            nb0 = *reinterpret_cast<const float4*>(Bp + (long long)(t + 1) * 16 * ldb);
            nb1 = *reinterpret_cast<const float4*>(Bp + (long long)(t + 1) * 16 * ldb + 4);
            if (emode) {
                int kr = (t + 1) * 16 + bk, cb = col0 + bc;
                nb0.x = ((kr == cb + 0) ? cval : 0.0f) - nb0.x;
                nb0.y = ((kr == cb + 1) ? cval : 0.0f) - nb0.y;
                nb0.z = ((kr == cb + 2) ? cval : 0.0f) - nb0.z;
                nb0.w = ((kr == cb + 3) ? cval : 0.0f) - nb0.w;
                nb1.x = ((kr == cb + 4) ? cval : 0.0f) - nb1.x;
                nb1.y = ((kr == cb + 5) ? cval : 0.0f) - nb1.y;
                nb1.z = ((kr == cb + 6) ? cval : 0.0f) - nb1.z;
                nb1.w = ((kr == cb + 7) ? cval : 0.0f) - nb1.w;
            }
        }
        #pragma unroll
        for (int kb = 0; kb < 16; kb += 8) {
            unsigned af[2][4], bf[4][2];
            #pragma unroll
            for (int mi = 0; mi < 2; mi++) {
                int r = wr * 32 + mi * 16 + g;
                af[mi][0] = As[buf][kb + tg][r];
                af[mi][1] = As[buf][kb + tg][r + 8];
                af[mi][2] = As[buf][kb + tg + 4][r];
                af[mi][3] = As[buf][kb + tg + 4][r + 8];
            }
            #pragma unroll
            for (int ni = 0; ni < 4; ni++) {
                int cc = wc * 32 + ni * 8 + g;
                bf[ni][0] = Bs[buf][kb + tg][cc];
                bf[ni][1] = Bs[buf][kb + tg + 4][cc];
            }
            #pragma unroll
            for (int mi = 0; mi < 2; mi++)
                #pragma unroll
                for (int ni = 0; ni < 4; ni++)
                    mma_tf32(acc[mi][ni][0], acc[mi][ni][1], acc[mi][ni][2], acc[mi][ni][3],
                             af[mi][0], af[mi][1], af[mi][2], af[mi][3],
                             bf[ni][0], bf[ni][1]);
        }
        if (t + 1 < nt) {
            buf ^= 1;
            As[buf][ak + 0][ar] = f2tf(na0.x); As[buf][ak + 1][ar] = f2tf(na0.y);
            As[buf][ak + 2][ar] = f2tf(na0.z); As[buf][ak + 3][ar] = f2tf(na0.w);
            As[buf][ak + 4][ar] = f2tf(na1.x); As[buf][ak + 5][ar] = f2tf(na1.y);
            As[buf][ak + 6][ar] = f2tf(na1.z); As[buf][ak + 7][ar] = f2tf(na1.w);
            Bs[buf][bk][bc + 0] = f2tf(nb0.x); Bs[buf][bk][bc + 1] = f2tf(nb0.y);
            Bs[buf][bk][bc + 2] = f2tf(nb0.z); Bs[buf][bk][bc + 3] = f2tf(nb0.w);
            Bs[buf][bk][bc + 4] = f2tf(nb1.x); Bs[buf][bk][bc + 5] = f2tf(nb1.y);
            Bs[buf][bk][bc + 6] = f2tf(nb1.z); Bs[buf][bk][bc + 7] = f2tf(nb1.w);
            __syncthreads();
        }
    }

    // epilogue: c0=(g,2tg) c1=(g,2tg+1) c2=(g+8,2tg) c3=(g+8,2tg+1)
    #pragma unroll
    for (int mi = 0; mi < 2; mi++) {
        int r = row0 + wr * 32 + mi * 16 + g;
        #pragma unroll
        for (int ni = 0; ni < 4; ni++) {
            int cc = col0 + wc * 32 + ni * 8 + 2 * tg;
            float2 v0, v1;
            v0.x = alpha * acc[mi][ni][0]; v0.y = alpha * acc[mi][ni][1];
            v1.x = alpha * acc[mi][ni][2]; v1.y = alpha * acc[mi][ni][3];
            if (bias) {
                float b0 = bias[cc], b1 = bias[cc + 1];
                v0.x += b0; v0.y += b1; v1.x += b0; v1.y += b1;
            }
            if (relu) {
                v0.x = fmaxf(v0.x, 0.0f); v0.y = fmaxf(v0.y, 0.0f);
                v1.x = fmaxf(v1.x, 0.0f); v1.y = fmaxf(v1.y, 0.0f);
            }
            *reinterpret_cast<float2*>(&C[(long long)r * ldc + cc]) = v0;
            *reinterpret_cast<float2*>(&C[(long long)(r + 8) * ldc + cc]) = v1;
        }
    }
}

// ---------------- 128x128 tf32 tensor-core GEMM (double-buffered) --------
// C = alpha*A@B (+bias)(+relu). M,N mult of 128; K mult of 16.
// 256 threads = 8 warps (2x4); warp tile 64x32 via mma.m16n8k8.tf32.
__global__ void __launch_bounds__(256) tgemm(
    const float* __restrict__ A, int lda, long long sA,
    const float* __restrict__ B, int ldb, long long sB,
    float* __restrict__ C, int ldc, long long sC,
    int M, int N, int K, float alpha,
    const float* __restrict__ bias, int relu)
{
    __shared__ unsigned As[2][16][136];
    __shared__ unsigned Bs[2][16][136];
    A += (long long)blockIdx.z * sA;
    B += (long long)blockIdx.z * sB;
    C += (long long)blockIdx.z * sC;
    int tid = threadIdx.x;
    int row0 = blockIdx.y * 128, col0 = blockIdx.x * 128;
    int wid = tid >> 5, lane = tid & 31;
    int wr = wid >> 2, wc = wid & 3;          // 2 x 4 warp grid
    int g = lane >> 2, tg = lane & 3;         // groupID / threadID_in_group
    int ar = tid >> 1, ak = (tid & 1) << 3;   // A: 128 rows x 16 k (8 floats/thread)
    int bk = tid >> 4, bc = (tid & 15) << 3;  // B: 16 k x 128 cols (8 floats/thread)
    const float* Ap = A + (long long)(row0 + ar) * lda + ak;
    const float* Bp = B + (long long)bk * ldb + col0 + bc;
    float acc[4][4][4];
    #pragma unroll
    for (int i = 0; i < 4; i++)
        #pragma unroll
        for (int j = 0; j < 4; j++)
            #pragma unroll
            for (int k = 0; k < 4; k++) acc[i][j][k] = 0.0f;
    int nt = K >> 4;

    // prologue: tile 0 -> buffer 0
    {
        float4 a0 = *reinterpret_cast<const float4*>(Ap);
        float4 a1 = *reinterpret_cast<const float4*>(Ap + 4);
        float4 b0 = *reinterpret_cast<const float4*>(Bp);
        float4 b1 = *reinterpret_cast<const float4*>(Bp + 4);
        As[0][ak + 0][ar] = f2tf(a0.x); As[0][ak + 1][ar] = f2tf(a0.y);
        As[0][ak + 2][ar] = f2tf(a0.z); As[0][ak + 3][ar] = f2tf(a0.w);
        As[0][ak + 4][ar] = f2tf(a1.x); As[0][ak + 5][ar] = f2tf(a1.y);
        As[0][ak + 6][ar] = f2tf(a1.z); As[0][ak + 7][ar] = f2tf(a1.w);
        Bs[0][bk][bc + 0] = f2tf(b0.x); Bs[0][bk][bc + 1] = f2tf(b0.y);
        Bs[0][bk][bc + 2] = f2tf(b0.z); Bs[0][bk][bc + 3] = f2tf(b0.w);
        Bs[0][bk][bc + 4] = f2tf(b1.x); Bs[0][bk][bc + 5] = f2tf(b1.y);
        Bs[0][bk][bc + 6] = f2tf(b1.z); Bs[0][bk][bc + 7] = f2tf(b1.w);
    }
    __syncthreads();

    int buf = 0;
    for (int t = 0; t < nt; t++) {
        float4 na0, na1, nb0, nb1;
        if (t + 1 < nt) {
            na0 = *reinterpret_cast<const float4*>(Ap + (t + 1) * 16);
            na1 = *reinterpret_cast<const float4*>(Ap + (t + 1) * 16 + 4);
            nb0 = *reinterpret_cast<const float4*>(Bp + (long long)(t + 1) * 16 * ldb);
            nb1 = *reinterpret_cast<const float4*>(Bp + (long long)(t + 1) * 16 * ldb + 4);
        }
        #pragma unroll
        for (int kb = 0; kb < 16; kb += 8) {
            unsigned af[4][4], bf[4][2];
            #pragma unroll
            for (int mi = 0; mi < 4; mi++) {
                int r = wr * 64 + mi * 16 + g;
                af[mi][0] = As[buf][kb + tg][r];
                af[mi][1] = As[buf][kb + tg][r + 8];
                af[mi][2] = As[buf][kb + tg + 4][r];
                af[mi][3] = As[buf][kb + tg + 4][r + 8];
            }
            #pragma unroll
            for (int ni = 0; ni < 4; ni++) {
                int cc = wc * 32 + ni * 8 + g;
                bf[ni][0] = Bs[buf][kb + tg][cc];
                bf[ni][1] = Bs[buf][kb + tg + 4][cc];
            }
            #pragma unroll
            for (int mi = 0; mi < 4; mi++)
                #pragma unroll
                for (int ni = 0; ni < 4; ni++)
                    mma_tf32(acc[mi][ni][0], acc[mi][ni][1], acc[mi][ni][2], acc[mi][ni][3],
                             af[mi][0], af[mi][1], af[mi][2], af[mi][3],
                             bf[ni][0], bf[ni][1]);
        }
        if (t + 1 < nt) {
            buf ^= 1;
            As[buf][ak + 0][ar] = f2tf(na0.x); As[buf][ak + 1][ar] = f2tf(na0.y);
            As[buf][ak + 2][ar] = f2tf(na0.z); As[buf][ak + 3][ar] = f2tf(na0.w);
            As[buf][ak + 4][ar] = f2tf(na1.x); As[buf][ak + 5][ar] = f2tf(na1.y);
            As[buf][ak + 6][ar] = f2tf(na1.z); As[buf][ak + 7][ar] = f2tf(na1.w);
            Bs[buf][bk][bc + 0] = f2tf(nb0.x); Bs[buf][bk][bc + 1] = f2tf(nb0.y);
            Bs[buf][bk][bc + 2] = f2tf(nb0.z); Bs[buf][bk][bc + 3] = f2tf(nb0.w);
            Bs[buf][bk][bc + 4] = f2tf(nb1.x); Bs[buf][bk][bc + 5] = f2tf(nb1.y);
            Bs[buf][bk][bc + 6] = f2tf(nb1.z); Bs[buf][bk][bc + 7] = f2tf(nb1.w);
            __syncthreads();
        }
    }

    // epilogue: c0=(g,2tg) c1=(g,2tg+1) c2=(g+8,2tg) c3=(g+8,2tg+1)
    #pragma unroll
    for (int mi = 0; mi < 4; mi++) {
        int r = row0 + wr * 64 + mi * 16 + g;
        #pragma unroll
        for (int ni = 0; ni < 4; ni++) {
            int cc = col0 + wc * 32 + ni * 8 + 2 * tg;
            float2 v0, v1;
            v0.x = alpha * acc[mi][ni][0]; v0.y = alpha * acc[mi][ni][1];
            v1.x = alpha * acc[mi][ni][2]; v1.y = alpha * acc[mi][ni][3];
            if (bias) {
                float b0 = bias[cc], b1 = bias[cc + 1];
                v0.x += b0; v0.y += b1; v1.x += b0; v1.y += b1;
            }
            if (relu) {
                v0.x = fmaxf(v0.x, 0.0f); v0.y = fmaxf(v0.y, 0.0f);
                v1.x = fmaxf(v1.x, 0.0f); v1.y = fmaxf(v1.y, 0.0f);
            }
            *reinterpret_cast<float2*>(&C[(long long)r * ldc + cc]) = v0;
            *reinterpret_cast<float2*>(&C[(long long)(r + 8) * ldc + cc]) = v1;
        }
    }
}

// ---------------- misc kernels ----------------
__global__ void k_zero(float* p, int n) {
    int i = blockIdx.x * 256 + threadIdx.x;
    if (i < n) p[i] = 0.0f;
}

// deterministic reduction of KSPL split-K partials
__global__ void k_redsplit(const float* __restrict__ part, float* __restrict__ out) {
    int i = blockIdx.x * 256 + threadIdx.x;
    if (i >= NH * MLM * DH) return;
    int b = i / (MLM * DH), r = i - b * (MLM * DH);
    const float* p = part + ((long long)b * KSPL) * (MLM * DH) + r;
    float s = 0.0f;
    #pragma unroll 1
    for (int ch = 0; ch < KSPL; ch++) s += p[(long long)ch * (MLM * DH)];
    out[i] = s;
}

// h rows 1..8192 already hold relu(fc1). Set row0=cls, wrap rows 8193..8281 <- rows 1..89.
__global__ void k_build(float* h, const float* cls) {
    int idx = blockIdx.x * 256 + threadIdx.x;
    if (idx < D) h[idx] = cls[idx];
    int j = idx - D;
    if (j >= 0 && j < 89 * D) {
        int r = j / D, c = j - r * D;
        h[(long long)(8193 + r) * D + c] = h[(long long)(1 + r) * D + c];
    }
}

__global__ void k_ln(const float* __restrict__ in, float* __restrict__ out,
                     const float* __restrict__ gg, const float* __restrict__ bb, int rows) {
    __shared__ float sh[32];
    int r = blockIdx.x;
    if (r >= rows) return;
    const float* x = in + (long long)r * D;
    int tid = threadIdx.x;
    float v0 = x[tid], v1 = x[tid + 256];
    float s  = blkSum(v0 + v1, sh, 256);
    float s2 = blkSum(v0 * v0 + v1 * v1, sh, 256);
    float mu = s * (1.0f / 512.0f);
    float var = s2 * (1.0f / 512.0f) - mu * mu;
    float inv = rsqrtf(var + 1e-5f);
    float* o = out + (long long)r * D;
    o[tid]       = (v0 - mu) * inv * gg[tid] + bb[tid];
    o[tid + 256] = (v1 - mu) * inv * gg[tid + 256] + bb[tid + 256];
}

// generic softmax (rows of arbitrary len); exp cached on pass 2
__global__ void k_softmax(float* __restrict__ S, int len) {
    __shared__ float sh[32];
    float* row = S + (long long)blockIdx.x * len;
    int tid = threadIdx.x;
    float m = -INFINITY;
    for (int i = tid; i < len; i += 256) m = fmaxf(m, row[i]);
    m = blkMax(m, sh, 256);
    float s = 0.0f;
    for (int i = tid; i < len; i += 256) {
        float e = __expf(row[i] - m);
        row[i] = e;
        s += e;
    }
    s = blkSum(s, sh, 256);
    float inv = 1.0f / s;
    for (int i = tid; i < len; i += 256) row[i] *= inv;
}

// one-pass softmax for rows of exactly 256 (one element per thread)
__global__ void k_softmax256(float* __restrict__ S) {
    __shared__ float sh[32];
    int tid = threadIdx.x;
    float* row = S + (long long)blockIdx.x * 256;
    float v = row[tid];
    float m = blkMax(v, sh, 256);
    float e = __expf(v - m);
    float s = blkSum(e, sh, 256);
    row[tid] = e / s;
}

// landmark means: ql[h][m][d] = mean_t q[m*33+t][h*64+d]; klT[h][d][m] = mean_t k[...]
__global__ void k_landmark(const float* __restrict__ qkv, float* __restrict__ ql,
                           float* __restrict__ klT) {
    int m = blockIdx.x, h = blockIdx.y, d = threadIdx.x;
    const float* base = qkv + (long long)(m * LWIN) * H3D + h * DH + d;
    float qs = 0.0f, ks = 0.0f;
    for (int t = 0; t < LWIN; t++) {
        qs += base[(long long)t * H3D];
        ks += base[(long long)t * H3D + D];
    }
    ql[((h * MLM) + m) * DH + d]  = qs * (1.0f / 33.0f);
    klT[((h * DH) + d) * MLM + m] = ks * (1.0f / 33.0f);
}

// kT[c][n] = qkv[n][D + c]  (c = h*64+d), tiled transpose
__global__ void k_transpose(const float* __restrict__ src, float* __restrict__ dst) {
    __shared__ float tile[32][33];
    int c0 = blockIdx.x * 32, n0 = blockIdx.y * 32;
    for (int i = threadIdx.y; i < 32; i += 8)
        tile[i][threadIdx.x] = src[(long long)(n0 + i) * H3D + D + c0 + threadIdx.x];
    __syncthreads();
    for (int i = threadIdx.y; i < 32; i += 8)
        dst[(long long)(c0 + i) * NP + n0 + threadIdx.x] = tile[threadIdx.x][i];
}

// per-head reductions: red[h*2]=max row-sum |a2_h|, red[h*2+1]=max col-sum |a2_h|
__global__ void k_pinv_red(const float* __restrict__ a2, float* __restrict__ red) {
    __shared__ float sh[32];
    int h = blockIdx.x;
    const float* A = a2 + (long long)h * MLM * MLM;
    int i = threadIdx.x;
    float rs = 0.0f, cs = 0.0f;
    for (int j = 0; j < MLM; j++) {
        rs += fabsf(A[i * MLM + j]);
        cs += fabsf(A[j * MLM + i]);
    }
    float colv = blkMax(rs, sh, 256);
    float rowv = blkMax(cs, sh, 256);
    if (i == 0) { red[h * 2] = colv; red[h * 2 + 1] = rowv; }
}

// z0 = a2^T / (col*row), col/row are GLOBAL maxima across all heads (matches
// jnp .max() with no axis argument in the reference).
__global__ void k_pinv_zinit(const float* __restrict__ a2, const float* __restrict__ red,
                             float* __restrict__ z) {
    int idx = blockIdx.x * 256 + threadIdx.x;
    if (idx >= NH * MLM * MLM) return;
    float colm = 0.0f, rowm = 0.0f;
    #pragma unroll
    for (int hh = 0; hh < NH; hh++) {
        colm = fmaxf(colm, red[hh * 2]);
        rowm = fmaxf(rowm, red[hh * 2 + 1]);
    }
    int h = idx >> 16;
    int r = (idx >> 8) & 255;
    int c = idx & 255;
    z[idx] = a2[((long long)h << 16) + c * MLM + r] / (colm * rowm);
}

// depthwise 33-tap conv over sequence of v, added to ab (float4: 4 ch/thread)
__global__ void k_conv(const float* __restrict__ qkv, const float* __restrict__ w,
                       float* __restrict__ ab) {
    __shared__ float ws[NH * LWIN];
    int tid = threadIdx.x;   // 128 threads, each handles 4 channels
    for (int i = tid; i < NH * LWIN; i += 128) ws[i] = w[i];
    __syncthreads();
    int n = blockIdx.x;
    int c4 = tid << 2;            // 0,4,...,508 — all 4 within one head
    int h = c4 >> 6;
    const float* wrow = ws + h * LWIN;
    float4 s = make_float4(0.0f, 0.0f, 0.0f, 0.0f);
    #pragma unroll
    for (int t = 0; t < LWIN; t++) {
        int nn = n - 16 + t;
        if (nn >= 0 && nn < NP) {
            float wv = wrow[t];
            float4 v = *reinterpret_cast<const float4*>(
                qkv + (long long)nn * H3D + 2 * D + c4);
            s.x += wv * v.x; s.y += wv * v.y; s.z += wv * v.z; s.w += wv * v.w;
        }
    }
    float4* dst = reinterpret_cast<float4*>(ab + (long long)n * D + c4);
    float4 o = *dst;
    o.x += s.x; o.y += s.y; o.z += s.z; o.w += s.w;
    *dst = o;
}

__global__ void k_resid(float* __restrict__ h, const float* __restrict__ t) {
    int idx = blockIdx.x * 256 + threadIdx.x;   // float4 index
    if (idx < (NTOK * D) / 4) {
        float4 a = reinterpret_cast<float4*>(h)[idx];
        float4 b = reinterpret_cast<const float4*>(t + PAD * D)[idx];
        a.x += b.x; a.y += b.y; a.z += b.z; a.w += b.w;
        reinterpret_cast<float4*>(h)[idx] = a;
    }
}

// PPEG: out row 1+p = center + dw7 + dw5 + dw3 (+biases). 512 threads = channels.
// Block 0 also carries the cls row (row 0) into out.
__global__ void k_ppeg(const float* __restrict__ h, float* __restrict__ out,
                       const float* __restrict__ w7, const float* __restrict__ b7,
                       const float* __restrict__ w5, const float* __restrict__ b5,
                       const float* __restrict__ w3, const float* __restrict__ b3) {
    int p = blockIdx.x;
    int y = p / HS, x = p - y * HS;
    int c = threadIdx.x;
    if (p == 0) out[c] = h[c];
    float acc = h[(long long)(1 + p) * D + c] + b7[c] + b5[c] + b3[c];
    const float* W7 = w7 + c * 49;
    const float* W5 = w5 + c * 25;
    const float* W3 = w3 + c * 9;
    #pragma unroll
    for (int ky = 0; ky < 7; ky++) {
        int yy = y + ky - 3;
        if (yy < 0 || yy >= HS) continue;
        #pragma unroll
        for (int kx = 0; kx < 7; kx++) {
            int xx = x + kx - 3;
            if (xx < 0 || xx >= HS) continue;
            float v = h[(long long)(1 + yy * HS + xx) * D + c];
            float wsum = W7[ky * 7 + kx];
            if (ky >= 1 && ky <= 5 && kx >= 1 && kx <= 5) wsum += W5[(ky - 1) * 5 + (kx - 1)];
            if (ky >= 2 && ky <= 4 && kx >= 2 && kx <= 4) wsum += W3[(ky - 2) * 3 + (kx - 2)];
            acc += v * wsum;
        }
    }
    out[(long long)(1 + p) * D + c] = acc;
}

// final: emb = ln(h[0]); logits = emb@fc2 + b; softmax; argmax
__global__ void k_final(const float* __restrict__ h, const float* __restrict__ gg,
                        const float* __restrict__ bb, const float* __restrict__ fw,
                        const float* __restrict__ fb, float* __restrict__ out, int out_size) {
    __shared__ float sh[32];
    __shared__ float emb[512];
    int tid = threadIdx.x;
    float v = h[tid];
    float s  = blkSum(v, sh, 512);
    float s2 = blkSum(v * v, sh, 512);
    float mu = s * (1.0f / 512.0f);
    float var = s2 * (1.0f / 512.0f) - mu * mu;
    float inv = rsqrtf(var + 1e-5f);
    float e = (v - mu) * inv * gg[tid] + bb[tid];
    emb[tid] = e;
    if (5 + tid < out_size) out[5 + tid] = e;
    __syncthreads();
    if (tid == 0) {
        float l0 = fb[0], l1 = fb[1];
        for (int c = 0; c < 512; c++) { l0 += emb[c] * fw[2 * c]; l1 += emb[c] * fw[2 * c + 1]; }
        if (out_size > 0) out[0] = l0;
        if (out_size > 1) out[1] = l1;
        float m = fmaxf(l0, l1);
        float e0 = __expf(l0 - m), e1 = __expf(l1 - m);
        float ss = e0 + e1;
        if (out_size > 2) out[2] = e0 / ss;
        if (out_size > 3) out[3] = e1 / ss;
        if (out_size > 4) out[4] = (l1 > l0) ? 1.0f : 0.0f;
    }
}

// ---------------- host orchestration ----------------
static inline void gemm(const float* A, int lda, long long sA,
                        const float* B, int ldb, long long sB,
                        float* C, int ldc, long long sC,
                        int M, int N, int K, float alpha,
                        const float* bias, int relu, int batch,
                        int emode = 0, float cval = 0.0f, int ksplit = 1) {
    dim3 g(N / 64, M / 64, batch * ksplit);
    tgemm64<<<g, 128>>>(A, lda, sA, B, ldb, sB, C, ldc, sC, M, N, K, alpha, bias, relu,
                        emode, cval, ksplit);
}

static inline void gemmL(const float* A, int lda, long long sA,
                         const float* B, int ldb, long long sB,
                         float* C, int ldc, long long sC,
                         int M, int N, int K, float alpha,
                         const float* bias, int relu, int batch) {
    dim3 g(N / 128, M / 128, batch);
    tgemm<<<g, 256>>>(A, lda, sA, B, ldb, sB, C, ldc, sC, M, N, K, alpha, bias, relu);
}

struct Bufs {
    float *h, *t, *xp, *qkv, *kT, *s, *ql, *klT, *a2, *z0, *z1, *xz, *u, *tt,
          *part, *a3v, *z2, *ab, *red;
};

static void run_attn(Bufs& b, const float* lng, const float* lnb,
                     const float* qkvw, const float* outw, const float* outb,
                     const float* convw) {
    k_zero<<<(PAD * D + 255) / 256, 256>>>(b.xp, PAD * D);
    k_ln<<<NTOK, 256>>>(b.h, b.xp + (long long)PAD * D, lng, lnb, NTOK);
    gemmL(b.xp, D, 0, qkvw, H3D, 0, b.qkv, H3D, 0, NP, H3D, D, 1.0f, nullptr, 0, 1);
    k_landmark<<<dim3(MLM, NH), DH>>>(b.qkv, b.ql, b.klT);
    k_transpose<<<dim3(D / 32, NP / 32), dim3(32, 8)>>>(b.qkv, b.kT);
    // a2 = softmax(SCALE * ql @ kl^T)
    gemm(b.ql, DH, MLM * DH, b.klT, MLM, DH * MLM, b.a2, MLM, MLM * MLM,
         MLM, MLM, DH, SCALE, nullptr, 0, NH);
    k_softmax256<<<NH * MLM, 256>>>(b.a2);
    // pinv: z = 0.25 * z @ (13I - xz @ (15I - xz @ (7I - xz))), xz = a2@z
    k_pinv_red<<<NH, 256>>>(b.a2, b.red);
    k_pinv_zinit<<<(NH * MLM * MLM + 255) / 256, 256>>>(b.a2, b.red, b.z0);
    float* zc = b.z0; float* zn = b.z1;
    const long long SB = (long long)MLM * MLM;
    for (int it = 0; it < 6; it++) {
        gemm(b.a2, MLM, SB, zc, MLM, SB, b.xz, MLM, SB, MLM, MLM, MLM, 1.0f, nullptr, 0, NH);
        gemm(b.xz, MLM, SB, b.xz, MLM, SB, b.u,  MLM, SB, MLM, MLM, MLM, 1.0f, nullptr, 0, NH, 1, 7.0f);
        gemm(b.xz, MLM, SB, b.u,  MLM, SB, b.tt, MLM, SB, MLM, MLM, MLM, 1.0f, nullptr, 0, NH, 1, 15.0f);
        gemm(zc,   MLM, SB, b.tt, MLM, SB, zn,   MLM, SB, MLM, MLM, MLM, 0.25f, nullptr, 0, NH, 1, 13.0f);
        float* sw = zc; zc = zn; zn = sw;
    }
    // a3 = softmax_n(SCALE * ql @ k^T)
    gemmL(b.ql, DH, MLM * DH, b.kT, NP, (long long)DH * NP, b.s, NP, (long long)MLM * NP,
          MLM, NP, DH, SCALE, nullptr, 0, NH);
    k_softmax<<<NH * MLM, 256>>>(b.s, NP);
    // a3v = a3 @ v  (split-K: 33 chunks of 256, deterministic reduce)
    gemm(b.s, NP, (long long)MLM * NP, b.qkv + 2 * D, H3D, DH,
         b.part, DH, (long long)MLM * DH,
         MLM, DH, NP / KSPL, 1.0f, nullptr, 0, NH, 0, 0.0f, KSPL);
    k_redsplit<<<(NH * MLM * DH + 255) / 256, 256>>>(b.part, b.a3v);
    // z2 = pinv @ a3v
    gemm(zc, MLM, SB, b.a3v, DH, MLM * DH, b.z2, DH, MLM * DH, MLM, DH, MLM, 1.0f, nullptr, 0, NH);
    // a1 = softmax(SCALE * q @ kl^T); ab = a1 @ z2 (per head into column slices)
    gemmL(b.qkv, H3D, DH, b.klT, MLM, DH * MLM, b.s, MLM, (long long)NP * MLM,
          NP, MLM, DH, SCALE, nullptr, 0, NH);
    k_softmax256<<<NH * NP, 256>>>(b.s);
    gemm(b.s, MLM, (long long)NP * MLM, b.z2, DH, MLM * DH, b.ab, D, DH,
         NP, DH, MLM, 1.0f, nullptr, 0, NH);
    // + depthwise conv(v)
    k_conv<<<NP, 128>>>(b.qkv, convw, b.ab);
    // proj + residual (last NTOK rows)
    gemmL(b.ab, D, 0, outw, D, 0, b.t, D, 0, NP, D, D, 1.0f, outb, 0, 1);
    k_resid<<<((NTOK * D / 4) + 255) / 256, 256>>>(b.h, b.t);
}

extern "C" void kernel_launch(void* const* d_in, const int* in_sizes, int n_in,
                              void* d_out, int out_size) {
    const float* x      = (const float*)d_in[0];
    const float* fc1_w  = (const float*)d_in[1];
    const float* fc1_b  = (const float*)d_in[2];
    const float* cls    = (const float*)d_in[3];
    const float* ln1_g  = (const float*)d_in[4];
    const float* ln1_b  = (const float*)d_in[5];
    const float* qkv1_w = (const float*)d_in[6];
    const float* out1_w = (const float*)d_in[7];
    const float* out1_b = (const float*)d_in[8];
    const float* conv1_w= (const float*)d_in[9];
    const float* ln2_g  = (const float*)d_in[10];
    const float* ln2_b  = (const float*)d_in[11];
    const float* qkv2_w = (const float*)d_in[12];
    const float* out2_w = (const float*)d_in[13];
    const float* out2_b = (const float*)d_in[14];
    const float* conv2_w= (const float*)d_in[15];
    const float* pg7_w  = (const float*)d_in[16];
    const float* pg7_b  = (const float*)d_in[17];
    const float* pg5_w  = (const float*)d_in[18];
    const float* pg5_b  = (const float*)d_in[19];
    const float* pg3_w  = (const float*)d_in[20];
    const float* pg3_b  = (const float*)d_in[21];
    const float* norm_g = (const float*)d_in[22];
    const float* norm_b = (const float*)d_in[23];
    const float* fc2_w  = (const float*)d_in[24];
    const float* fc2_b  = (const float*)d_in[25];

    Bufs b;
    cudaGetSymbolAddress((void**)&b.h,    g_h);
    cudaGetSymbolAddress((void**)&b.t,    g_t);
    cudaGetSymbolAddress((void**)&b.xp,   g_xp);
    cudaGetSymbolAddress((void**)&b.qkv,  g_qkv);
    cudaGetSymbolAddress((void**)&b.kT,   g_kT);
    cudaGetSymbolAddress((void**)&b.s,    g_s);
    cudaGetSymbolAddress((void**)&b.ql,   g_ql);
    cudaGetSymbolAddress((void**)&b.klT,  g_klT);
    cudaGetSymbolAddress((void**)&b.a2,   g_a2);
    cudaGetSymbolAddress((void**)&b.z0,   g_z0);
    cudaGetSymbolAddress((void**)&b.z1,   g_z1);
    cudaGetSymbolAddress((void**)&b.xz,   g_xz);
    cudaGetSymbolAddress((void**)&b.u,    g_u);
    cudaGetSymbolAddress((void**)&b.tt,   g_tt);
    cudaGetSymbolAddress((void**)&b.part, g_part);
    cudaGetSymbolAddress((void**)&b.a3v,  g_a3v);
    cudaGetSymbolAddress((void**)&b.z2,   g_z2);
    cudaGetSymbolAddress((void**)&b.ab,   g_ab);
    cudaGetSymbolAddress((void**)&b.red,  g_red);

    // fc1: h rows 1..8192 = relu(x @ fc1_w + b)
    gemmL(x, 1024, 0, fc1_w, D, 0, b.h + D, D, 0, 8192, D, 1024, 1.0f, fc1_b, 1, 1);
    k_build<<<(90 * D + 255) / 256, 256>>>(b.h, cls);

    // layer 1 attention
    run_attn(b, ln1_g, ln1_b, qkv1_w, out1_w, out1_b, conv1_w);

    // PPEG: write into t (incl. cls row), then swap h <-> t
    k_ppeg<<<NPIX, 512>>>(b.h, b.t, pg7_w, pg7_b, pg5_w, pg5_b, pg3_w, pg3_b);
    { float* tmp = b.h; b.h = b.t; b.t = tmp; }

    // layer 2 attention
    run_attn(b, ln2_g, ln2_b, qkv2_w, out2_w, out2_b, conv2_w);

    // head
    k_final<<<1, 512>>>(b.h, norm_g, norm_b, fc2_w, fc2_b, (float*)d_out, out_size);
}

// round 14
// speedup vs baseline: 1.7503x; 1.1446x over previous
#include <cuda_runtime.h>
#include <math.h>

// ---------------- problem constants ----------------
#define NTOK   8282          // tokens incl. cls (1 + 8281)
#define PAD    166           // front zero-pad inside nystrom
#define NP     8448          // padded length = 33*256
#define D      512
#define H3D    1536          // 3*D
#define NH     8             // heads
#define DH     64
#define MLM    256           // landmarks
#define LWIN   33            // tokens per landmark
#define SCALE  0.125f        // DH^-0.5
#define HS     91            // ppeg grid 91x91 = 8281
#define NPIX   8281
#define KSPL   33            // split-K chunks for a3v (8448/33 = 256)

// ---------------- static device scratch ----------------
__device__ float g_h   [NP * D];
__device__ float g_t   [NP * D];
__device__ float g_xp  [NP * D];
__device__ float g_qkv [NP * H3D];
__device__ float g_kT  [NH * DH * NP];
__device__ float g_s   [NH * NP * MLM];      // reused: a3 scores then a1 scores
__device__ float g_ql  [NH * MLM * DH];
__device__ float g_klT [NH * DH * MLM];
__device__ float g_a2  [NH * MLM * MLM];
__device__ float g_z0  [NH * MLM * MLM];
__device__ float g_z1  [NH * MLM * MLM];
__device__ float g_xz  [NH * MLM * MLM];
__device__ float g_u   [NH * MLM * MLM];
__device__ float g_tt  [NH * MLM * MLM];
__device__ float g_part[NH * KSPL * MLM * DH];  // split-K partials for a3v
__device__ float g_a3v [NH * MLM * DH];
__device__ float g_z2  [NH * MLM * DH];
__device__ float g_ab  [NP * D];
__device__ float g_red [NH * 2];

// ---------------- block reductions ----------------
__device__ __forceinline__ float blkSum(float v, float* sh, int nt) {
    int tid = threadIdx.x;
    #pragma unroll
    for (int o = 16; o; o >>= 1) v += __shfl_down_sync(0xffffffffu, v, o);
    __syncthreads();
    if ((tid & 31) == 0) sh[tid >> 5] = v;
    __syncthreads();
    int nw = nt >> 5;
    float r = (tid < nw) ? sh[tid] : 0.0f;
    if (tid < 32) {
        for (int o = nw >> 1; o; o >>= 1) r += __shfl_down_sync(0xffffffffu, r, o);
    }
    if (tid == 0) sh[0] = r;
    __syncthreads();
    float res = sh[0];
    __syncthreads();
    return res;
}

__device__ __forceinline__ float blkMax(float v, float* sh, int nt) {
    int tid = threadIdx.x;
    #pragma unroll
    for (int o = 16; o; o >>= 1) v = fmaxf(v, __shfl_down_sync(0xffffffffu, v, o));
    __syncthreads();
    if ((tid & 31) == 0) sh[tid >> 5] = v;
    __syncthreads();
    int nw = nt >> 5;
    float r = (tid < nw) ? sh[tid] : -INFINITY;
    if (tid < 32) {
        for (int o = nw >> 1; o; o >>= 1) r = fmaxf(r, __shfl_down_sync(0xffffffffu, r, o));
    }
    if (tid == 0) sh[0] = r;
    __syncthreads();
    float res = sh[0];
    __syncthreads();
    return res;
}

// ---------------- bf16 helpers ----------------
// pack (lo, hi) = (k, k+1) into bf16x2; low half = lo.
__device__ __forceinline__ unsigned f2bf2(float lo, float hi) {
    unsigned u;
    asm("cvt.rn.bf16x2.f32 %0, %1, %2;" : "=r"(u) : "f"(hi), "f"(lo));
    return u;
}

__device__ __forceinline__ void mma_bf16(float& c0, float& c1, float& c2, float& c3,
                                         unsigned a0, unsigned a1, unsigned a2, unsigned a3,
                                         unsigned b0, unsigned b1) {
    asm volatile(
        "mma.sync.aligned.m16n8k16.row.col.f32.bf16.bf16.f32 "
        "{%0,%1,%2,%3}, {%4,%5,%6,%7}, {%8,%9}, {%0,%1,%2,%3};"
        : "+f"(c0), "+f"(c1), "+f"(c2), "+f"(c3)
        : "r"(a0), "r"(a1), "r"(a2), "r"(a3), "r"(b0), "r"(b1));
}

// ---------------- 64x64 bf16 tensor GEMM (double-buffered, emode, split-K) --
// C = alpha * A @ B' (+bias)(+relu); B' = B, or (cval*I - B) when emode=1.
// ksplit>1: z = batch*ksplit + chunk; A,B advance chunk*K along k; C indexed
// by z (per-z stride sC). K is PER-CHUNK depth. M,N mult 64; K mult 16.
// 128 threads = 4 warps (2x2); warp tile 32x32 via mma.m16n8k16.bf16.
// Smem holds bf16x2 pairs along k: word [kp][x] = elements (2kp, 2kp+1).
__global__ void __launch_bounds__(128) tgemm64(
    const float* __restrict__ A, int lda, long long sA,
    const float* __restrict__ B, int ldb, long long sB,
    float* __restrict__ C, int ldc, long long sC,
    int M, int N, int K, float alpha,
    const float* __restrict__ bias, int relu,
    int emode, float cval, int ksplit)
{
    __shared__ unsigned As[2][8][72];
    __shared__ unsigned Bs[2][8][72];
    int bz = blockIdx.z / ksplit, ch = blockIdx.z % ksplit;
    A += (long long)bz * sA + (long long)ch * K;
    B += (long long)bz * sB + (long long)ch * K * ldb;
    C += (long long)blockIdx.z * sC;
    int tid = threadIdx.x;
    int row0 = blockIdx.y * 64, col0 = blockIdx.x * 64;
    int wid = tid >> 5, lane = tid & 31;
    int wr = wid >> 1, wc = wid & 1;           // 2x2 warp grid
    int g = lane >> 2, tg = lane & 3;
    int ar = tid >> 1, akp = (tid & 1) << 2;   // A: 64 rows; kpairs akp..akp+3
    int bkp = tid >> 4, bc = (tid & 15) << 2;  // B: kpair row; 4 cols
    const float* Ap = A + (long long)(row0 + ar) * lda + (akp << 1);
    const float* Bp = B + (long long)(bkp << 1) * ldb + col0 + bc;
    float acc[2][4][4];
    #pragma unroll
    for (int i = 0; i < 2; i++)
        #pragma unroll
        for (int j = 0; j < 4; j++)
            #pragma unroll
            for (int k = 0; k < 4; k++) acc[i][j][k] = 0.0f;
    int nt = K >> 4;

    // loader lambda-ish (manual): tile t -> buffer b
    {
        float4 a0 = *reinterpret_cast<const float4*>(Ap);
        float4 a1 = *reinterpret_cast<const float4*>(Ap + 4);
        float4 r0 = *reinterpret_cast<const float4*>(Bp);
        float4 r1 = *reinterpret_cast<const float4*>(Bp + ldb);
        if (emode) {
            int k0 = bkp << 1, cb = col0 + bc;
            r0.x = ((k0 == cb + 0) ? cval : 0.0f) - r0.x;
            r0.y = ((k0 == cb + 1) ? cval : 0.0f) - r0.y;
            r0.z = ((k0 == cb + 2) ? cval : 0.0f) - r0.z;
            r0.w = ((k0 == cb + 3) ? cval : 0.0f) - r0.w;
            r1.x = ((k0 + 1 == cb + 0) ? cval : 0.0f) - r1.x;
            r1.y = ((k0 + 1 == cb + 1) ? cval : 0.0f) - r1.y;
            r1.z = ((k0 + 1 == cb + 2) ? cval : 0.0f) - r1.z;
            r1.w = ((k0 + 1 == cb + 3) ? cval : 0.0f) - r1.w;
        }
        As[0][akp + 0][ar] = f2bf2(a0.x, a0.y);
        As[0][akp + 1][ar] = f2bf2(a0.z, a0.w);
        As[0][akp + 2][ar] = f2bf2(a1.x, a1.y);
        As[0][akp + 3][ar] = f2bf2(a1.z, a1.w);
        Bs[0][bkp][bc + 0] = f2bf2(r0.x, r1.x);
        Bs[0][bkp][bc + 1] = f2bf2(r0.y, r1.y);
        Bs[0][bkp][bc + 2] = f2bf2(r0.z, r1.z);
        Bs[0][bkp][bc + 3] = f2bf2(r0.w, r1.w);
    }
    __syncthreads();

    int buf = 0;
    for (int t = 0; t < nt; t++) {
        float4 na0, na1, nr0, nr1;
        if (t + 1 < nt) {
            na0 = *reinterpret_cast<const float4*>(Ap + (t + 1) * 16);
            na1 = *reinterpret_cast<const float4*>(Ap + (t + 1) * 16 + 4);
            nr0 = *reinterpret_cast<const float4*>(Bp + (long long)(t + 1) * 16 * ldb);
            nr1 = *reinterpret_cast<const float4*>(Bp + (long long)(t + 1) * 16 * ldb + ldb);
            if (emode) {
                int k0 = (t + 1) * 16 + (bkp << 1), cb = col0 + bc;
                nr0.x = ((k0 == cb + 0) ? cval : 0.0f) - nr0.x;
                nr0.y = ((k0 == cb + 1) ? cval : 0.0f) - nr0.y;
                nr0.z = ((k0 == cb + 2) ? cval : 0.0f) - nr0.z;
                nr0.w = ((k0 == cb + 3) ? cval : 0.0f) - nr0.w;
                nr1.x = ((k0 + 1 == cb + 0) ? cval : 0.0f) - nr1.x;
                nr1.y = ((k0 + 1 == cb + 1) ? cval : 0.0f) - nr1.y;
                nr1.z = ((k0 + 1 == cb + 2) ? cval : 0.0f) - nr1.z;
                nr1.w = ((k0 + 1 == cb + 3) ? cval : 0.0f) - nr1.w;
            }
        }
        {
            unsigned af[2][4], bf[4][2];
            #pragma unroll
            for (int mi = 0; mi < 2; mi++) {
                int r = wr * 32 + mi * 16 + g;
                af[mi][0] = As[buf][tg][r];
                af[mi][1] = As[buf][tg][r + 8];
                af[mi][2] = As[buf][tg + 4][r];
                af[mi][3] = As[buf][tg + 4][r + 8];
            }
            #pragma unroll
            for (int ni = 0; ni < 4; ni++) {
                int cc = wc * 32 + ni * 8 + g;
                bf[ni][0] = Bs[buf][tg][cc];
                bf[ni][1] = Bs[buf][tg + 4][cc];
            }
            #pragma unroll
            for (int mi = 0; mi < 2; mi++)
                #pragma unroll
                for (int ni = 0; ni < 4; ni++)
                    mma_bf16(acc[mi][ni][0], acc[mi][ni][1], acc[mi][ni][2], acc[mi][ni][3],
                             af[mi][0], af[mi][1], af[mi][2], af[mi][3],
                             bf[ni][0], bf[ni][1]);
        }
        if (t + 1 < nt) {
            buf ^= 1;
            As[buf][akp + 0][ar] = f2bf2(na0.x, na0.y);
            As[buf][akp + 1][ar] = f2bf2(na0.z, na0.w);
            As[buf][akp + 2][ar] = f2bf2(na1.x, na1.y);
            As[buf][akp + 3][ar] = f2bf2(na1.z, na1.w);
            Bs[buf][bkp][bc + 0] = f2bf2(nr0.x, nr1.x);
            Bs[buf][bkp][bc + 1] = f2bf2(nr0.y, nr1.y);
            Bs[buf][bkp][bc + 2] = f2bf2(nr0.z, nr1.z);
            Bs[buf][bkp][bc + 3] = f2bf2(nr0.w, nr1.w);
            __syncthreads();
        }
    }

    // epilogue: c0=(g,2tg) c1=(g,2tg+1) c2=(g+8,2tg) c3=(g+8,2tg+1)
    #pragma unroll
    for (int mi = 0; mi < 2; mi++) {
        int r = row0 + wr * 32 + mi * 16 + g;
        #pragma unroll
        for (int ni = 0; ni < 4; ni++) {
            int cc = col0 + wc * 32 + ni * 8 + 2 * tg;
            float2 v0, v1;
            v0.x = alpha * acc[mi][ni][0]; v0.y = alpha * acc[mi][ni][1];
            v1.x = alpha * acc[mi][ni][2]; v1.y = alpha * acc[mi][ni][3];
            if (bias) {
                float b0 = bias[cc], b1 = bias[cc + 1];
                v0.x += b0; v0.y += b1; v1.x += b0; v1.y += b1;
            }
            if (relu) {
                v0.x = fmaxf(v0.x, 0.0f); v0.y = fmaxf(v0.y, 0.0f);
                v1.x = fmaxf(v1.x, 0.0f); v1.y = fmaxf(v1.y, 0.0f);
            }
            *reinterpret_cast<float2*>(&C[(long long)r * ldc + cc]) = v0;
            *reinterpret_cast<float2*>(&C[(long long)(r + 8) * ldc + cc]) = v1;
        }
    }
}

// ---------------- 128x128 bf16 tensor-core GEMM (double-buffered) --------
// C = alpha*A@B (+bias)(+relu). M,N mult of 128; K mult of 16.
// 256 threads = 8 warps (2x4); warp tile 64x32 via mma.m16n8k16.bf16.
__global__ void __launch_bounds__(256) tgemm(
    const float* __restrict__ A, int lda, long long sA,
    const float* __restrict__ B, int ldb, long long sB,
    float* __restrict__ C, int ldc, long long sC,
    int M, int N, int K, float alpha,
    const float* __restrict__ bias, int relu)
{
    __shared__ unsigned As[2][8][136];
    __shared__ unsigned Bs[2][8][136];
    A += (long long)blockIdx.z * sA;
    B += (long long)blockIdx.z * sB;
    C += (long long)blockIdx.z * sC;
    int tid = threadIdx.x;
    int row0 = blockIdx.y * 128, col0 = blockIdx.x * 128;
    int wid = tid >> 5, lane = tid & 31;
    int wr = wid >> 2, wc = wid & 3;           // 2 x 4 warp grid
    int g = lane >> 2, tg = lane & 3;
    int ar = tid >> 1, akp = (tid & 1) << 2;   // A: 128 rows; kpairs akp..akp+3
    int bkp = tid >> 5, bc = (tid & 31) << 2;  // B: kpair row; 4 cols
    const float* Ap = A + (long long)(row0 + ar) * lda + (akp << 1);
    const float* Bp = B + (long long)(bkp << 1) * ldb + col0 + bc;
    float acc[4][4][4];
    #pragma unroll
    for (int i = 0; i < 4; i++)
        #pragma unroll
        for (int j = 0; j < 4; j++)
            #pragma unroll
            for (int k = 0; k < 4; k++) acc[i][j][k] = 0.0f;
    int nt = K >> 4;

    {
        float4 a0 = *reinterpret_cast<const float4*>(Ap);
        float4 a1 = *reinterpret_cast<const float4*>(Ap + 4);
        float4 r0 = *reinterpret_cast<const float4*>(Bp);
        float4 r1 = *reinterpret_cast<const float4*>(Bp + ldb);
        As[0][akp + 0][ar] = f2bf2(a0.x, a0.y);
        As[0][akp + 1][ar] = f2bf2(a0.z, a0.w);
        As[0][akp + 2][ar] = f2bf2(a1.x, a1.y);
        As[0][akp + 3][ar] = f2bf2(a1.z, a1.w);
        Bs[0][bkp][bc + 0] = f2bf2(r0.x, r1.x);
        Bs[0][bkp][bc + 1] = f2bf2(r0.y, r1.y);
        Bs[0][bkp][bc + 2] = f2bf2(r0.z, r1.z);
        Bs[0][bkp][bc + 3] = f2bf2(r0.w, r1.w);
    }
    __syncthreads();

    int buf = 0;
    for (int t = 0; t < nt; t++) {
        float4 na0, na1, nr0, nr1;
        if (t + 1 < nt) {
            na0 = *reinterpret_cast<const float4*>(Ap + (t + 1) * 16);
            na1 = *reinterpret_cast<const float4*>(Ap + (t + 1) * 16 + 4);
            nr0 = *reinterpret_cast<const float4*>(Bp + (long long)(t + 1) * 16 * ldb);
            nr1 = *reinterpret_cast<const float4*>(Bp + (long long)(t + 1) * 16 * ldb + ldb);
        }
        {
            unsigned af[4][4], bf[4][2];
            #pragma unroll
            for (int mi = 0; mi < 4; mi++) {
                int r = wr * 64 + mi * 16 + g;
                af[mi][0] = As[buf][tg][r];
                af[mi][1] = As[buf][tg][r + 8];
                af[mi][2] = As[buf][tg + 4][r];
                af[mi][3] = As[buf][tg + 4][r + 8];
            }
            #pragma unroll
            for (int ni = 0; ni < 4; ni++) {
                int cc = wc * 32 + ni * 8 + g;
                bf[ni][0] = Bs[buf][tg][cc];
                bf[ni][1] = Bs[buf][tg + 4][cc];
            }
            #pragma unroll
            for (int mi = 0; mi < 4; mi++)
                #pragma unroll
                for (int ni = 0; ni < 4; ni++)
                    mma_bf16(acc[mi][ni][0], acc[mi][ni][1], acc[mi][ni][2], acc[mi][ni][3],
                             af[mi][0], af[mi][1], af[mi][2], af[mi][3],
                             bf[ni][0], bf[ni][1]);
        }
        if (t + 1 < nt) {
            buf ^= 1;
            As[buf][akp + 0][ar] = f2bf2(na0.x, na0.y);
            As[buf][akp + 1][ar] = f2bf2(na0.z, na0.w);
            As[buf][akp + 2][ar] = f2bf2(na1.x, na1.y);
            As[buf][akp + 3][ar] = f2bf2(na1.z, na1.w);
            Bs[buf][bkp][bc + 0] = f2bf2(nr0.x, nr1.x);
            Bs[buf][bkp][bc + 1] = f2bf2(nr0.y, nr1.y);
            Bs[buf][bkp][bc + 2] = f2bf2(nr0.z, nr1.z);
            Bs[buf][bkp][bc + 3] = f2bf2(nr0.w, nr1.w);
            __syncthreads();
        }
    }

    // epilogue: c0=(g,2tg) c1=(g,2tg+1) c2=(g+8,2tg) c3=(g+8,2tg+1)
    #pragma unroll
    for (int mi = 0; mi < 4; mi++) {
        int r = row0 + wr * 64 + mi * 16 + g;
        #pragma unroll
        for (int ni = 0; ni < 4; ni++) {
            int cc = col0 + wc * 32 + ni * 8 + 2 * tg;
            float2 v0, v1;
            v0.x = alpha * acc[mi][ni][0]; v0.y = alpha * acc[mi][ni][1];
            v1.x = alpha * acc[mi][ni][2]; v1.y = alpha * acc[mi][ni][3];
            if (bias) {
                float b0 = bias[cc], b1 = bias[cc + 1];
                v0.x += b0; v0.y += b1; v1.x += b0; v1.y += b1;
            }
            if (relu) {
                v0.x = fmaxf(v0.x, 0.0f); v0.y = fmaxf(v0.y, 0.0f);
                v1.x = fmaxf(v1.x, 0.0f); v1.y = fmaxf(v1.y, 0.0f);
            }
            *reinterpret_cast<float2*>(&C[(long long)r * ldc + cc]) = v0;
            *reinterpret_cast<float2*>(&C[(long long)(r + 8) * ldc + cc]) = v1;
        }
    }
}

// ---------------- misc kernels ----------------
__global__ void k_zero(float* p, int n) {
    int i = blockIdx.x * 256 + threadIdx.x;
    if (i < n) p[i] = 0.0f;
}

// deterministic reduction of KSPL split-K partials
__global__ void k_redsplit(const float* __restrict__ part, float* __restrict__ out) {
    int i = blockIdx.x * 256 + threadIdx.x;
    if (i >= NH * MLM * DH) return;
    int b = i / (MLM * DH), r = i - b * (MLM * DH);
    const float* p = part + ((long long)b * KSPL) * (MLM * DH) + r;
    float s = 0.0f;
    #pragma unroll 1
    for (int ch = 0; ch < KSPL; ch++) s += p[(long long)ch * (MLM * DH)];
    out[i] = s;
}

// h rows 1..8192 already hold relu(fc1). Set row0=cls, wrap rows 8193..8281 <- rows 1..89.
__global__ void k_build(float* h, const float* cls) {
    int idx = blockIdx.x * 256 + threadIdx.x;
    if (idx < D) h[idx] = cls[idx];
    int j = idx - D;
    if (j >= 0 && j < 89 * D) {
        int r = j / D, c = j - r * D;
        h[(long long)(8193 + r) * D + c] = h[(long long)(1 + r) * D + c];
    }
}

__global__ void k_ln(const float* __restrict__ in, float* __restrict__ out,
                     const float* __restrict__ gg, const float* __restrict__ bb, int rows) {
    __shared__ float sh[32];
    int r = blockIdx.x;
    if (r >= rows) return;
    const float* x = in + (long long)r * D;
    int tid = threadIdx.x;
    float v0 = x[tid], v1 = x[tid + 256];
    float s  = blkSum(v0 + v1, sh, 256);
    float s2 = blkSum(v0 * v0 + v1 * v1, sh, 256);
    float mu = s * (1.0f / 512.0f);
    float var = s2 * (1.0f / 512.0f) - mu * mu;
    float inv = rsqrtf(var + 1e-5f);
    float* o = out + (long long)r * D;
    o[tid]       = (v0 - mu) * inv * gg[tid] + bb[tid];
    o[tid + 256] = (v1 - mu) * inv * gg[tid + 256] + bb[tid + 256];
}

// generic softmax (rows of arbitrary len); exp cached on pass 2
__global__ void k_softmax(float* __restrict__ S, int len) {
    __shared__ float sh[32];
    float* row = S + (long long)blockIdx.x * len;
    int tid = threadIdx.x;
    float m = -INFINITY;
    for (int i = tid; i < len; i += 256) m = fmaxf(m, row[i]);
    m = blkMax(m, sh, 256);
    float s = 0.0f;
    for (int i = tid; i < len; i += 256) {
        float e = __expf(row[i] - m);
        row[i] = e;
        s += e;
    }
    s = blkSum(s, sh, 256);
    float inv = 1.0f / s;
    for (int i = tid; i < len; i += 256) row[i] *= inv;
}

// one-pass softmax for rows of exactly 256 (one element per thread)
__global__ void k_softmax256(float* __restrict__ S) {
    __shared__ float sh[32];
    int tid = threadIdx.x;
    float* row = S + (long long)blockIdx.x * 256;
    float v = row[tid];
    float m = blkMax(v, sh, 256);
    float e = __expf(v - m);
    float s = blkSum(e, sh, 256);
    row[tid] = e / s;
}

// landmark means: ql[h][m][d] = mean_t q[m*33+t][h*64+d]; klT[h][d][m] = mean_t k[...]
__global__ void k_landmark(const float* __restrict__ qkv, float* __restrict__ ql,
                           float* __restrict__ klT) {
    int m = blockIdx.x, h = blockIdx.y, d = threadIdx.x;
    const float* base = qkv + (long long)(m * LWIN) * H3D + h * DH + d;
    float qs = 0.0f, ks = 0.0f;
    for (int t = 0; t < LWIN; t++) {
        qs += base[(long long)t * H3D];
        ks += base[(long long)t * H3D + D];
    }
    ql[((h * MLM) + m) * DH + d]  = qs * (1.0f / 33.0f);
    klT[((h * DH) + d) * MLM + m] = ks * (1.0f / 33.0f);
}

// kT[c][n] = qkv[n][D + c]  (c = h*64+d), tiled transpose
__global__ void k_transpose(const float* __restrict__ src, float* __restrict__ dst) {
    __shared__ float tile[32][33];
    int c0 = blockIdx.x * 32, n0 = blockIdx.y * 32;
    for (int i = threadIdx.y; i < 32; i += 8)
        tile[i][threadIdx.x] = src[(long long)(n0 + i) * H3D + D + c0 + threadIdx.x];
    __syncthreads();
    for (int i = threadIdx.y; i < 32; i += 8)
        dst[(long long)(c0 + i) * NP + n0 + threadIdx.x] = tile[threadIdx.x][i];
}

// per-head reductions: red[h*2]=max row-sum |a2_h|, red[h*2+1]=max col-sum |a2_h|
__global__ void k_pinv_red(const float* __restrict__ a2, float* __restrict__ red) {
    __shared__ float sh[32];
    int h = blockIdx.x;
    const float* A = a2 + (long long)h * MLM * MLM;
    int i = threadIdx.x;
    float rs = 0.0f, cs = 0.0f;
    for (int j = 0; j < MLM; j++) {
        rs += fabsf(A[i * MLM + j]);
        cs += fabsf(A[j * MLM + i]);
    }
    float colv = blkMax(rs, sh, 256);
    float rowv = blkMax(cs, sh, 256);
    if (i == 0) { red[h * 2] = colv; red[h * 2 + 1] = rowv; }
}

// z0 = a2^T / (col*row), col/row are GLOBAL maxima across all heads (matches
// jnp .max() with no axis argument in the reference).
__global__ void k_pinv_zinit(const float* __restrict__ a2, const float* __restrict__ red,
                             float* __restrict__ z) {
    int idx = blockIdx.x * 256 + threadIdx.x;
    if (idx >= NH * MLM * MLM) return;
    float colm = 0.0f, rowm = 0.0f;
    #pragma unroll
    for (int hh = 0; hh < NH; hh++) {
        colm = fmaxf(colm, red[hh * 2]);
        rowm = fmaxf(rowm, red[hh * 2 + 1]);
    }
    int h = idx >> 16;
    int r = (idx >> 8) & 255;
    int c = idx & 255;
    z[idx] = a2[((long long)h << 16) + c * MLM + r] / (colm * rowm);
}

// depthwise 33-tap conv over sequence of v, added to ab (float4: 4 ch/thread)
__global__ void k_conv(const float* __restrict__ qkv, const float* __restrict__ w,
                       float* __restrict__ ab) {
    __shared__ float ws[NH * LWIN];
    int tid = threadIdx.x;   // 128 threads, each handles 4 channels
    for (int i = tid; i < NH * LWIN; i += 128) ws[i] = w[i];
    __syncthreads();
    int n = blockIdx.x;
    int c4 = tid << 2;            // 0,4,...,508 — all 4 within one head
    int h = c4 >> 6;
    const float* wrow = ws + h * LWIN;
    float4 s = make_float4(0.0f, 0.0f, 0.0f, 0.0f);
    #pragma unroll
    for (int t = 0; t < LWIN; t++) {
        int nn = n - 16 + t;
        if (nn >= 0 && nn < NP) {
            float wv = wrow[t];
            float4 v = *reinterpret_cast<const float4*>(
                qkv + (long long)nn * H3D + 2 * D + c4);
            s.x += wv * v.x; s.y += wv * v.y; s.z += wv * v.z; s.w += wv * v.w;
        }
    }
    float4* dst = reinterpret_cast<float4*>(ab + (long long)n * D + c4);
    float4 o = *dst;
    o.x += s.x; o.y += s.y; o.z += s.z; o.w += s.w;
    *dst = o;
}

__global__ void k_resid(float* __restrict__ h, const float* __restrict__ t) {
    int idx = blockIdx.x * 256 + threadIdx.x;   // float4 index
    if (idx < (NTOK * D) / 4) {
        float4 a = reinterpret_cast<float4*>(h)[idx];
        float4 b = reinterpret_cast<const float4*>(t + PAD * D)[idx];
        a.x += b.x; a.y += b.y; a.z += b.z; a.w += b.w;
        reinterpret_cast<float4*>(h)[idx] = a;
    }
}

// PPEG: out row 1+p = center + dw7 + dw5 + dw3 (+biases). 512 threads = channels.
// Block 0 also carries the cls row (row 0) into out.
__global__ void k_ppeg(const float* __restrict__ h, float* __restrict__ out,
                       const float* __restrict__ w7, const float* __restrict__ b7,
                       const float* __restrict__ w5, const float* __restrict__ b5,
                       const float* __restrict__ w3, const float* __restrict__ b3) {
    int p = blockIdx.x;
    int y = p / HS, x = p - y * HS;
    int c = threadIdx.x;
    if (p == 0) out[c] = h[c];
    float acc = h[(long long)(1 + p) * D + c] + b7[c] + b5[c] + b3[c];
    const float* W7 = w7 + c * 49;
    const float* W5 = w5 + c * 25;
    const float* W3 = w3 + c * 9;
    #pragma unroll
    for (int ky = 0; ky < 7; ky++) {
        int yy = y + ky - 3;
        if (yy < 0 || yy >= HS) continue;
        #pragma unroll
        for (int kx = 0; kx < 7; kx++) {
            int xx = x + kx - 3;
            if (xx < 0 || xx >= HS) continue;
            float v = h[(long long)(1 + yy * HS + xx) * D + c];
            float wsum = W7[ky * 7 + kx];
            if (ky >= 1 && ky <= 5 && kx >= 1 && kx <= 5) wsum += W5[(ky - 1) * 5 + (kx - 1)];
            if (ky >= 2 && ky <= 4 && kx >= 2 && kx <= 4) wsum += W3[(ky - 2) * 3 + (kx - 2)];
            acc += v * wsum;
        }
    }
    out[(long long)(1 + p) * D + c] = acc;
}

// final: emb = ln(h[0]); logits = emb@fc2 + b; softmax; argmax
__global__ void k_final(const float* __restrict__ h, const float* __restrict__ gg,
                        const float* __restrict__ bb, const float* __restrict__ fw,
                        const float* __restrict__ fb, float* __restrict__ out, int out_size) {
    __shared__ float sh[32];
    __shared__ float emb[512];
    int tid = threadIdx.x;
    float v = h[tid];
    float s  = blkSum(v, sh, 512);
    float s2 = blkSum(v * v, sh, 512);
    float mu = s * (1.0f / 512.0f);
    float var = s2 * (1.0f / 512.0f) - mu * mu;
    float inv = rsqrtf(var + 1e-5f);
    float e = (v - mu) * inv * gg[tid] + bb[tid];
    emb[tid] = e;
    if (5 + tid < out_size) out[5 + tid] = e;
    __syncthreads();
    if (tid == 0) {
        float l0 = fb[0], l1 = fb[1];
        for (int c = 0; c < 512; c++) { l0 += emb[c] * fw[2 * c]; l1 += emb[c] * fw[2 * c + 1]; }
        if (out_size > 0) out[0] = l0;
        if (out_size > 1) out[1] = l1;
        float m = fmaxf(l0, l1);
        float e0 = __expf(l0 - m), e1 = __expf(l1 - m);
        float ss = e0 + e1;
        if (out_size > 2) out[2] = e0 / ss;
        if (out_size > 3) out[3] = e1 / ss;
        if (out_size > 4) out[4] = (l1 > l0) ? 1.0f : 0.0f;
    }
}

// ---------------- host orchestration ----------------
static inline void gemm(const float* A, int lda, long long sA,
                        const float* B, int ldb, long long sB,
                        float* C, int ldc, long long sC,
                        int M, int N, int K, float alpha,
                        const float* bias, int relu, int batch,
                        int emode = 0, float cval = 0.0f, int ksplit = 1) {
    dim3 g(N / 64, M / 64, batch * ksplit);
    tgemm64<<<g, 128>>>(A, lda, sA, B, ldb, sB, C, ldc, sC, M, N, K, alpha, bias, relu,
                        emode, cval, ksplit);
}

static inline void gemmL(const float* A, int lda, long long sA,
                         const float* B, int ldb, long long sB,
                         float* C, int ldc, long long sC,
                         int M, int N, int K, float alpha,
                         const float* bias, int relu, int batch) {
    dim3 g(N / 128, M / 128, batch);
    tgemm<<<g, 256>>>(A, lda, sA, B, ldb, sB, C, ldc, sC, M, N, K, alpha, bias, relu);
}

struct Bufs {
    float *h, *t, *xp, *qkv, *kT, *s, *ql, *klT, *a2, *z0, *z1, *xz, *u, *tt,
          *part, *a3v, *z2, *ab, *red;
};

static void run_attn(Bufs& b, const float* lng, const float* lnb,
                     const float* qkvw, const float* outw, const float* outb,
                     const float* convw) {
    k_zero<<<(PAD * D + 255) / 256, 256>>>(b.xp, PAD * D);
    k_ln<<<NTOK, 256>>>(b.h, b.xp + (long long)PAD * D, lng, lnb, NTOK);
    gemmL(b.xp, D, 0, qkvw, H3D, 0, b.qkv, H3D, 0, NP, H3D, D, 1.0f, nullptr, 0, 1);
    k_landmark<<<dim3(MLM, NH), DH>>>(b.qkv, b.ql, b.klT);
    k_transpose<<<dim3(D / 32, NP / 32), dim3(32, 8)>>>(b.qkv, b.kT);
    // a2 = softmax(SCALE * ql @ kl^T)
    gemm(b.ql, DH, MLM * DH, b.klT, MLM, DH * MLM, b.a2, MLM, MLM * MLM,
         MLM, MLM, DH, SCALE, nullptr, 0, NH);
    k_softmax256<<<NH * MLM, 256>>>(b.a2);
    // pinv: z = 0.25 * z @ (13I - xz @ (15I - xz @ (7I - xz))), xz = a2@z
    k_pinv_red<<<NH, 256>>>(b.a2, b.red);
    k_pinv_zinit<<<(NH * MLM * MLM + 255) / 256, 256>>>(b.a2, b.red, b.z0);
    float* zc = b.z0; float* zn = b.z1;
    const long long SB = (long long)MLM * MLM;
    for (int it = 0; it < 6; it++) {
        gemm(b.a2, MLM, SB, zc, MLM, SB, b.xz, MLM, SB, MLM, MLM, MLM, 1.0f, nullptr, 0, NH);
        gemm(b.xz, MLM, SB, b.xz, MLM, SB, b.u,  MLM, SB, MLM, MLM, MLM, 1.0f, nullptr, 0, NH, 1, 7.0f);
        gemm(b.xz, MLM, SB, b.u,  MLM, SB, b.tt, MLM, SB, MLM, MLM, MLM, 1.0f, nullptr, 0, NH, 1, 15.0f);
        gemm(zc,   MLM, SB, b.tt, MLM, SB, zn,   MLM, SB, MLM, MLM, MLM, 0.25f, nullptr, 0, NH, 1, 13.0f);
        float* sw = zc; zc = zn; zn = sw;
    }
    // a3 = softmax_n(SCALE * ql @ k^T)
    gemmL(b.ql, DH, MLM * DH, b.kT, NP, (long long)DH * NP, b.s, NP, (long long)MLM * NP,
          MLM, NP, DH, SCALE, nullptr, 0, NH);
    k_softmax<<<NH * MLM, 256>>>(b.s, NP);
    // a3v = a3 @ v  (split-K: 33 chunks of 256, deterministic reduce)
    gemm(b.s, NP, (long long)MLM * NP, b.qkv + 2 * D, H3D, DH,
         b.part, DH, (long long)MLM * DH,
         MLM, DH, NP / KSPL, 1.0f, nullptr, 0, NH, 0, 0.0f, KSPL);
    k_redsplit<<<(NH * MLM * DH + 255) / 256, 256>>>(b.part, b.a3v);
    // z2 = pinv @ a3v
    gemm(zc, MLM, SB, b.a3v, DH, MLM * DH, b.z2, DH, MLM * DH, MLM, DH, MLM, 1.0f, nullptr, 0, NH);
    // a1 = softmax(SCALE * q @ kl^T); ab = a1 @ z2 (per head into column slices)
    gemmL(b.qkv, H3D, DH, b.klT, MLM, DH * MLM, b.s, MLM, (long long)NP * MLM,
          NP, MLM, DH, SCALE, nullptr, 0, NH);
    k_softmax256<<<NH * NP, 256>>>(b.s);
    gemm(b.s, MLM, (long long)NP * MLM, b.z2, DH, MLM * DH, b.ab, D, DH,
         NP, DH, MLM, 1.0f, nullptr, 0, NH);
    // + depthwise conv(v)
    k_conv<<<NP, 128>>>(b.qkv, convw, b.ab);
    // proj + residual (last NTOK rows)
    gemmL(b.ab, D, 0, outw, D, 0, b.t, D, 0, NP, D, D, 1.0f, outb, 0, 1);
    k_resid<<<((NTOK * D / 4) + 255) / 256, 256>>>(b.h, b.t);
}

extern "C" void kernel_launch(void* const* d_in, const int* in_sizes, int n_in,
                              void* d_out, int out_size) {
    const float* x      = (const float*)d_in[0];
    const float* fc1_w  = (const float*)d_in[1];
    const float* fc1_b  = (const float*)d_in[2];
    const float* cls    = (const float*)d_in[3];
    const float* ln1_g  = (const float*)d_in[4];
    const float* ln1_b  = (const float*)d_in[5];
    const float* qkv1_w = (const float*)d_in[6];
    const float* out1_w = (const float*)d_in[7];
    const float* out1_b = (const float*)d_in[8];
    const float* conv1_w= (const float*)d_in[9];
    const float* ln2_g  = (const float*)d_in[10];
    const float* ln2_b  = (const float*)d_in[11];
    const float* qkv2_w = (const float*)d_in[12];
    const float* out2_w = (const float*)d_in[13];
    const float* out2_b = (const float*)d_in[14];
    const float* conv2_w= (const float*)d_in[15];
    const float* pg7_w  = (const float*)d_in[16];
    const float* pg7_b  = (const float*)d_in[17];
    const float* pg5_w  = (const float*)d_in[18];
    const float* pg5_b  = (const float*)d_in[19];
    const float* pg3_w  = (const float*)d_in[20];
    const float* pg3_b  = (const float*)d_in[21];
    const float* norm_g = (const float*)d_in[22];
    const float* norm_b = (const float*)d_in[23];
    const float* fc2_w  = (const float*)d_in[24];
    const float* fc2_b  = (const float*)d_in[25];

    Bufs b;
    cudaGetSymbolAddress((void**)&b.h,    g_h);
    cudaGetSymbolAddress((void**)&b.t,    g_t);
    cudaGetSymbolAddress((void**)&b.xp,   g_xp);
    cudaGetSymbolAddress((void**)&b.qkv,  g_qkv);
    cudaGetSymbolAddress((void**)&b.kT,   g_kT);
    cudaGetSymbolAddress((void**)&b.s,    g_s);
    cudaGetSymbolAddress((void**)&b.ql,   g_ql);
    cudaGetSymbolAddress((void**)&b.klT,  g_klT);
    cudaGetSymbolAddress((void**)&b.a2,   g_a2);
    cudaGetSymbolAddress((void**)&b.z0,   g_z0);
    cudaGetSymbolAddress((void**)&b.z1,   g_z1);
    cudaGetSymbolAddress((void**)&b.xz,   g_xz);
    cudaGetSymbolAddress((void**)&b.u,    g_u);
    cudaGetSymbolAddress((void**)&b.tt,   g_tt);
    cudaGetSymbolAddress((void**)&b.part, g_part);
    cudaGetSymbolAddress((void**)&b.a3v,  g_a3v);
    cudaGetSymbolAddress((void**)&b.z2,   g_z2);
    cudaGetSymbolAddress((void**)&b.ab,   g_ab);
    cudaGetSymbolAddress((void**)&b.red,  g_red);

    // fc1: h rows 1..8192 = relu(x @ fc1_w + b)
    gemmL(x, 1024, 0, fc1_w, D, 0, b.h + D, D, 0, 8192, D, 1024, 1.0f, fc1_b, 1, 1);
    k_build<<<(90 * D + 255) / 256, 256>>>(b.h, cls);

    // layer 1 attention
    run_attn(b, ln1_g, ln1_b, qkv1_w, out1_w, out1_b, conv1_w);

    // PPEG: write into t (incl. cls row), then swap h <-> t
    k_ppeg<<<NPIX, 512>>>(b.h, b.t, pg7_w, pg7_b, pg5_w, pg5_b, pg3_w, pg3_b);
    { float* tmp = b.h; b.h = b.t; b.t = tmp; }

    // layer 2 attention
    run_attn(b, ln2_g, ln2_b, qkv2_w, out2_w, out2_b, conv2_w);

    // head
    k_final<<<1, 512>>>(b.h, norm_g, norm_b, fc2_w, fc2_b, (float*)d_out, out_size);
}

// round 15
// speedup vs baseline: 1.8616x; 1.0636x over previous
#include <cuda_runtime.h>
#include <math.h>

// ---------------- problem constants ----------------
#define NTOK   8282          // tokens incl. cls (1 + 8281)
#define PAD    166           // front zero-pad inside nystrom
#define NP     8448          // padded length = 33*256
#define D      512
#define H3D    1536          // 3*D
#define NH     8             // heads
#define DH     64
#define MLM    256           // landmarks
#define LWIN   33            // tokens per landmark
#define SCALE  0.125f        // DH^-0.5
#define HS     91            // ppeg grid 91x91 = 8281
#define NPIX   8281
#define KSPL   33            // split-K chunks for a3v (8448/33 = 256)

// ---------------- static device scratch ----------------
__device__ float g_h   [NP * D];
__device__ float g_t   [NP * D];
__device__ float g_xp  [NP * D];
__device__ float g_qkv [NP * H3D];
__device__ float g_kT  [NH * DH * NP];
__device__ float g_s   [NH * NP * MLM];      // a3 scores
__device__ float g_ql  [NH * MLM * DH];
__device__ float g_klT [NH * DH * MLM];
__device__ float g_a2  [NH * MLM * MLM];
__device__ float g_z0  [NH * MLM * MLM];
__device__ float g_z1  [NH * MLM * MLM];
__device__ float g_xz  [NH * MLM * MLM];
__device__ float g_u   [NH * MLM * MLM];
__device__ float g_tt  [NH * MLM * MLM];
__device__ float g_part[NH * KSPL * MLM * DH];  // split-K partials for a3v
__device__ float g_a3v [NH * MLM * DH];
__device__ float g_z2  [NH * MLM * DH];
__device__ float g_ab  [NP * D];
__device__ float g_red [NH * 2];

// ---------------- block reductions ----------------
__device__ __forceinline__ float blkSum(float v, float* sh, int nt) {
    int tid = threadIdx.x;
    #pragma unroll
    for (int o = 16; o; o >>= 1) v += __shfl_down_sync(0xffffffffu, v, o);
    __syncthreads();
    if ((tid & 31) == 0) sh[tid >> 5] = v;
    __syncthreads();
    int nw = nt >> 5;
    float r = (tid < nw) ? sh[tid] : 0.0f;
    if (tid < 32) {
        for (int o = nw >> 1; o; o >>= 1) r += __shfl_down_sync(0xffffffffu, r, o);
    }
    if (tid == 0) sh[0] = r;
    __syncthreads();
    float res = sh[0];
    __syncthreads();
    return res;
}

__device__ __forceinline__ float blkMax(float v, float* sh, int nt) {
    int tid = threadIdx.x;
    #pragma unroll
    for (int o = 16; o; o >>= 1) v = fmaxf(v, __shfl_down_sync(0xffffffffu, v, o));
    __syncthreads();
    if ((tid & 31) == 0) sh[tid >> 5] = v;
    __syncthreads();
    int nw = nt >> 5;
    float r = (tid < nw) ? sh[tid] : -INFINITY;
    if (tid < 32) {
        for (int o = nw >> 1; o; o >>= 1) r = fmaxf(r, __shfl_down_sync(0xffffffffu, r, o));
    }
    if (tid == 0) sh[0] = r;
    __syncthreads();
    float res = sh[0];
    __syncthreads();
    return res;
}

// ---------------- bf16 helpers ----------------
// pack (lo, hi) = (k, k+1) into bf16x2; low half = lo.
__device__ __forceinline__ unsigned f2bf2(float lo, float hi) {
    unsigned u;
    asm("cvt.rn.bf16x2.f32 %0, %1, %2;" : "=r"(u) : "f"(hi), "f"(lo));
    return u;
}

__device__ __forceinline__ void mma_bf16(float& c0, float& c1, float& c2, float& c3,
                                         unsigned a0, unsigned a1, unsigned a2, unsigned a3,
                                         unsigned b0, unsigned b1) {
    asm volatile(
        "mma.sync.aligned.m16n8k16.row.col.f32.bf16.bf16.f32 "
        "{%0,%1,%2,%3}, {%4,%5,%6,%7}, {%8,%9}, {%0,%1,%2,%3};"
        : "+f"(c0), "+f"(c1), "+f"(c2), "+f"(c3)
        : "r"(a0), "r"(a1), "r"(a2), "r"(a3), "r"(b0), "r"(b1));
}

// ---------------- 64x64 bf16 tensor GEMM (double-buffered, emode, split-K) --
__global__ void __launch_bounds__(128) tgemm64(
    const float* __restrict__ A, int lda, long long sA,
    const float* __restrict__ B, int ldb, long long sB,
    float* __restrict__ C, int ldc, long long sC,
    int M, int N, int K, float alpha,
    const float* __restrict__ bias, int relu,
    int emode, float cval, int ksplit)
{
    __shared__ unsigned As[2][8][72];
    __shared__ unsigned Bs[2][8][72];
    int bz = blockIdx.z / ksplit, ch = blockIdx.z % ksplit;
    A += (long long)bz * sA + (long long)ch * K;
    B += (long long)bz * sB + (long long)ch * K * ldb;
    C += (long long)blockIdx.z * sC;
    int tid = threadIdx.x;
    int row0 = blockIdx.y * 64, col0 = blockIdx.x * 64;
    int wid = tid >> 5, lane = tid & 31;
    int wr = wid >> 1, wc = wid & 1;           // 2x2 warp grid
    int g = lane >> 2, tg = lane & 3;
    int ar = tid >> 1, akp = (tid & 1) << 2;   // A: 64 rows; kpairs akp..akp+3
    int bkp = tid >> 4, bc = (tid & 15) << 2;  // B: kpair row; 4 cols
    const float* Ap = A + (long long)(row0 + ar) * lda + (akp << 1);
    const float* Bp = B + (long long)(bkp << 1) * ldb + col0 + bc;
    float acc[2][4][4];
    #pragma unroll
    for (int i = 0; i < 2; i++)
        #pragma unroll
        for (int j = 0; j < 4; j++)
            #pragma unroll
            for (int k = 0; k < 4; k++) acc[i][j][k] = 0.0f;
    int nt = K >> 4;

    {
        float4 a0 = *reinterpret_cast<const float4*>(Ap);
        float4 a1 = *reinterpret_cast<const float4*>(Ap + 4);
        float4 r0 = *reinterpret_cast<const float4*>(Bp);
        float4 r1 = *reinterpret_cast<const float4*>(Bp + ldb);
        if (emode) {
            int k0 = bkp << 1, cb = col0 + bc;
            r0.x = ((k0 == cb + 0) ? cval : 0.0f) - r0.x;
            r0.y = ((k0 == cb + 1) ? cval : 0.0f) - r0.y;
            r0.z = ((k0 == cb + 2) ? cval : 0.0f) - r0.z;
            r0.w = ((k0 == cb + 3) ? cval : 0.0f) - r0.w;
            r1.x = ((k0 + 1 == cb + 0) ? cval : 0.0f) - r1.x;
            r1.y = ((k0 + 1 == cb + 1) ? cval : 0.0f) - r1.y;
            r1.z = ((k0 + 1 == cb + 2) ? cval : 0.0f) - r1.z;
            r1.w = ((k0 + 1 == cb + 3) ? cval : 0.0f) - r1.w;
        }
        As[0][akp + 0][ar] = f2bf2(a0.x, a0.y);
        As[0][akp + 1][ar] = f2bf2(a0.z, a0.w);
        As[0][akp + 2][ar] = f2bf2(a1.x, a1.y);
        As[0][akp + 3][ar] = f2bf2(a1.z, a1.w);
        Bs[0][bkp][bc + 0] = f2bf2(r0.x, r1.x);
        Bs[0][bkp][bc + 1] = f2bf2(r0.y, r1.y);
        Bs[0][bkp][bc + 2] = f2bf2(r0.z, r1.z);
        Bs[0][bkp][bc + 3] = f2bf2(r0.w, r1.w);
    }
    __syncthreads();

    int buf = 0;
    for (int t = 0; t < nt; t++) {
        float4 na0, na1, nr0, nr1;
        if (t + 1 < nt) {
            na0 = *reinterpret_cast<const float4*>(Ap + (t + 1) * 16);
            na1 = *reinterpret_cast<const float4*>(Ap + (t + 1) * 16 + 4);
            nr0 = *reinterpret_cast<const float4*>(Bp + (long long)(t + 1) * 16 * ldb);
            nr1 = *reinterpret_cast<const float4*>(Bp + (long long)(t + 1) * 16 * ldb + ldb);
            if (emode) {
                int k0 = (t + 1) * 16 + (bkp << 1), cb = col0 + bc;
                nr0.x = ((k0 == cb + 0) ? cval : 0.0f) - nr0.x;
                nr0.y = ((k0 == cb + 1) ? cval : 0.0f) - nr0.y;
                nr0.z = ((k0 == cb + 2) ? cval : 0.0f) - nr0.z;
                nr0.w = ((k0 == cb + 3) ? cval : 0.0f) - nr0.w;
                nr1.x = ((k0 + 1 == cb + 0) ? cval : 0.0f) - nr1.x;
                nr1.y = ((k0 + 1 == cb + 1) ? cval : 0.0f) - nr1.y;
                nr1.z = ((k0 + 1 == cb + 2) ? cval : 0.0f) - nr1.z;
                nr1.w = ((k0 + 1 == cb + 3) ? cval : 0.0f) - nr1.w;
            }
        }
        {
            unsigned af[2][4], bf[4][2];
            #pragma unroll
            for (int mi = 0; mi < 2; mi++) {
                int r = wr * 32 + mi * 16 + g;
                af[mi][0] = As[buf][tg][r];
                af[mi][1] = As[buf][tg][r + 8];
                af[mi][2] = As[buf][tg + 4][r];
                af[mi][3] = As[buf][tg + 4][r + 8];
            }
            #pragma unroll
            for (int ni = 0; ni < 4; ni++) {
                int cc = wc * 32 + ni * 8 + g;
                bf[ni][0] = Bs[buf][tg][cc];
                bf[ni][1] = Bs[buf][tg + 4][cc];
            }
            #pragma unroll
            for (int mi = 0; mi < 2; mi++)
                #pragma unroll
                for (int ni = 0; ni < 4; ni++)
                    mma_bf16(acc[mi][ni][0], acc[mi][ni][1], acc[mi][ni][2], acc[mi][ni][3],
                             af[mi][0], af[mi][1], af[mi][2], af[mi][3],
                             bf[ni][0], bf[ni][1]);
        }
        if (t + 1 < nt) {
            buf ^= 1;
            As[buf][akp + 0][ar] = f2bf2(na0.x, na0.y);
            As[buf][akp + 1][ar] = f2bf2(na0.z, na0.w);
            As[buf][akp + 2][ar] = f2bf2(na1.x, na1.y);
            As[buf][akp + 3][ar] = f2bf2(na1.z, na1.w);
            Bs[buf][bkp][bc + 0] = f2bf2(nr0.x, nr1.x);
            Bs[buf][bkp][bc + 1] = f2bf2(nr0.y, nr1.y);
            Bs[buf][bkp][bc + 2] = f2bf2(nr0.z, nr1.z);
            Bs[buf][bkp][bc + 3] = f2bf2(nr0.w, nr1.w);
            __syncthreads();
        }
    }

    #pragma unroll
    for (int mi = 0; mi < 2; mi++) {
        int r = row0 + wr * 32 + mi * 16 + g;
        #pragma unroll
        for (int ni = 0; ni < 4; ni++) {
            int cc = col0 + wc * 32 + ni * 8 + 2 * tg;
            float2 v0, v1;
            v0.x = alpha * acc[mi][ni][0]; v0.y = alpha * acc[mi][ni][1];
            v1.x = alpha * acc[mi][ni][2]; v1.y = alpha * acc[mi][ni][3];
            if (bias) {
                float b0 = bias[cc], b1 = bias[cc + 1];
                v0.x += b0; v0.y += b1; v1.x += b0; v1.y += b1;
            }
            if (relu) {
                v0.x = fmaxf(v0.x, 0.0f); v0.y = fmaxf(v0.y, 0.0f);
                v1.x = fmaxf(v1.x, 0.0f); v1.y = fmaxf(v1.y, 0.0f);
            }
            *reinterpret_cast<float2*>(&C[(long long)r * ldc + cc]) = v0;
            *reinterpret_cast<float2*>(&C[(long long)(r + 8) * ldc + cc]) = v1;
        }
    }
}

// ---------------- 128x128 bf16 tensor-core GEMM (double-buffered) --------
__global__ void __launch_bounds__(256) tgemm(
    const float* __restrict__ A, int lda, long long sA,
    const float* __restrict__ B, int ldb, long long sB,
    float* __restrict__ C, int ldc, long long sC,
    int M, int N, int K, float alpha,
    const float* __restrict__ bias, int relu)
{
    __shared__ unsigned As[2][8][136];
    __shared__ unsigned Bs[2][8][136];
    A += (long long)blockIdx.z * sA;
    B += (long long)blockIdx.z * sB;
    C += (long long)blockIdx.z * sC;
    int tid = threadIdx.x;
    int row0 = blockIdx.y * 128, col0 = blockIdx.x * 128;
    int wid = tid >> 5, lane = tid & 31;
    int wr = wid >> 2, wc = wid & 3;           // 2 x 4 warp grid
    int g = lane >> 2, tg = lane & 3;
    int ar = tid >> 1, akp = (tid & 1) << 2;   // A: 128 rows; kpairs akp..akp+3
    int bkp = tid >> 5, bc = (tid & 31) << 2;  // B: kpair row; 4 cols
    const float* Ap = A + (long long)(row0 + ar) * lda + (akp << 1);
    const float* Bp = B + (long long)(bkp << 1) * ldb + col0 + bc;
    float acc[4][4][4];
    #pragma unroll
    for (int i = 0; i < 4; i++)
        #pragma unroll
        for (int j = 0; j < 4; j++)
            #pragma unroll
            for (int k = 0; k < 4; k++) acc[i][j][k] = 0.0f;
    int nt = K >> 4;

    {
        float4 a0 = *reinterpret_cast<const float4*>(Ap);
        float4 a1 = *reinterpret_cast<const float4*>(Ap + 4);
        float4 r0 = *reinterpret_cast<const float4*>(Bp);
        float4 r1 = *reinterpret_cast<const float4*>(Bp + ldb);
        As[0][akp + 0][ar] = f2bf2(a0.x, a0.y);
        As[0][akp + 1][ar] = f2bf2(a0.z, a0.w);
        As[0][akp + 2][ar] = f2bf2(a1.x, a1.y);
        As[0][akp + 3][ar] = f2bf2(a1.z, a1.w);
        Bs[0][bkp][bc + 0] = f2bf2(r0.x, r1.x);
        Bs[0][bkp][bc + 1] = f2bf2(r0.y, r1.y);
        Bs[0][bkp][bc + 2] = f2bf2(r0.z, r1.z);
        Bs[0][bkp][bc + 3] = f2bf2(r0.w, r1.w);
    }
    __syncthreads();

    int buf = 0;
    for (int t = 0; t < nt; t++) {
        float4 na0, na1, nr0, nr1;
        if (t + 1 < nt) {
            na0 = *reinterpret_cast<const float4*>(Ap + (t + 1) * 16);
            na1 = *reinterpret_cast<const float4*>(Ap + (t + 1) * 16 + 4);
            nr0 = *reinterpret_cast<const float4*>(Bp + (long long)(t + 1) * 16 * ldb);
            nr1 = *reinterpret_cast<const float4*>(Bp + (long long)(t + 1) * 16 * ldb + ldb);
        }
        {
            unsigned af[4][4], bf[4][2];
            #pragma unroll
            for (int mi = 0; mi < 4; mi++) {
                int r = wr * 64 + mi * 16 + g;
                af[mi][0] = As[buf][tg][r];
                af[mi][1] = As[buf][tg][r + 8];
                af[mi][2] = As[buf][tg + 4][r];
                af[mi][3] = As[buf][tg + 4][r + 8];
            }
            #pragma unroll
            for (int ni = 0; ni < 4; ni++) {
                int cc = wc * 32 + ni * 8 + g;
                bf[ni][0] = Bs[buf][tg][cc];
                bf[ni][1] = Bs[buf][tg + 4][cc];
            }
            #pragma unroll
            for (int mi = 0; mi < 4; mi++)
                #pragma unroll
                for (int ni = 0; ni < 4; ni++)
                    mma_bf16(acc[mi][ni][0], acc[mi][ni][1], acc[mi][ni][2], acc[mi][ni][3],
                             af[mi][0], af[mi][1], af[mi][2], af[mi][3],
                             bf[ni][0], bf[ni][1]);
        }
        if (t + 1 < nt) {
            buf ^= 1;
            As[buf][akp + 0][ar] = f2bf2(na0.x, na0.y);
            As[buf][akp + 1][ar] = f2bf2(na0.z, na0.w);
            As[buf][akp + 2][ar] = f2bf2(na1.x, na1.y);
            As[buf][akp + 3][ar] = f2bf2(na1.z, na1.w);
            Bs[buf][bkp][bc + 0] = f2bf2(nr0.x, nr1.x);
            Bs[buf][bkp][bc + 1] = f2bf2(nr0.y, nr1.y);
            Bs[buf][bkp][bc + 2] = f2bf2(nr0.z, nr1.z);
            Bs[buf][bkp][bc + 3] = f2bf2(nr0.w, nr1.w);
            __syncthreads();
        }
    }

    #pragma unroll
    for (int mi = 0; mi < 4; mi++) {
        int r = row0 + wr * 64 + mi * 16 + g;
        #pragma unroll
        for (int ni = 0; ni < 4; ni++) {
            int cc = col0 + wc * 32 + ni * 8 + 2 * tg;
            float2 v0, v1;
            v0.x = alpha * acc[mi][ni][0]; v0.y = alpha * acc[mi][ni][1];
            v1.x = alpha * acc[mi][ni][2]; v1.y = alpha * acc[mi][ni][3];
            if (bias) {
                float b0 = bias[cc], b1 = bias[cc + 1];
                v0.x += b0; v0.y += b1; v1.x += b0; v1.y += b1;
            }
            if (relu) {
                v0.x = fmaxf(v0.x, 0.0f); v0.y = fmaxf(v0.y, 0.0f);
                v1.x = fmaxf(v1.x, 0.0f); v1.y = fmaxf(v1.y, 0.0f);
            }
            *reinterpret_cast<float2*>(&C[(long long)r * ldc + cc]) = v0;
            *reinterpret_cast<float2*>(&C[(long long)(r + 8) * ldc + cc]) = v1;
        }
    }
}

// ---------------- fused a1 chain -----------------------------------------
// Per CTA: head h, 64 q-rows. S = SCALE * q@klT_h (64x256); P = softmax(S);
// ab[rows, h*64:+64] = P @ z2_h. 256 threads = 8 warps (2x4).
__global__ void __launch_bounds__(256) k_a1fused(
    const float* __restrict__ qkv, const float* __restrict__ klT,
    const float* __restrict__ z2, float* __restrict__ ab)
{
    __shared__ unsigned SM[10752];        // Aq[32][72] + Bk[32][264]; reused as PA[128][72]
    __shared__ unsigned Bzb[8][72];
    __shared__ float red[2][32][4];
    unsigned (*Aq)[72]  = reinterpret_cast<unsigned(*)[72]>(SM);
    unsigned (*Bk)[264] = reinterpret_cast<unsigned(*)[264]>(SM + 2304);
    unsigned (*PA)[72]  = reinterpret_cast<unsigned(*)[72]>(SM);

    int h = blockIdx.y;
    int n0 = blockIdx.x * 64;
    int tid = threadIdx.x;
    int wid = tid >> 5, lane = tid & 31;
    int wr = wid >> 2, wc = wid & 3;
    int g = lane >> 2, tg = lane & 3;

    // load q tile (64 rows x 64 d): Aq[d/2][row]
    {
        int ar = tid >> 2, d0 = (tid & 3) << 4;
        const float* qp = qkv + (long long)(n0 + ar) * H3D + h * DH + d0;
        #pragma unroll
        for (int j = 0; j < 4; j++) {
            float4 v = *reinterpret_cast<const float4*>(qp + 4 * j);
            Aq[(d0 >> 1) + 2 * j + 0][ar] = f2bf2(v.x, v.y);
            Aq[(d0 >> 1) + 2 * j + 1][ar] = f2bf2(v.z, v.w);
        }
    }
    // load klT_h (64 d x 256 m): Bk[d/2][m]
    {
        int dp = tid >> 3, mc = (tid & 7) << 5;
        const float* k0 = klT + ((long long)h * DH + 2 * dp) * MLM + mc;
        const float* k1 = k0 + MLM;
        #pragma unroll
        for (int j = 0; j < 8; j++) {
            float4 u0 = *reinterpret_cast<const float4*>(k0 + 4 * j);
            float4 u1 = *reinterpret_cast<const float4*>(k1 + 4 * j);
            Bk[dp][mc + 4 * j + 0] = f2bf2(u0.x, u1.x);
            Bk[dp][mc + 4 * j + 1] = f2bf2(u0.y, u1.y);
            Bk[dp][mc + 4 * j + 2] = f2bf2(u0.z, u1.z);
            Bk[dp][mc + 4 * j + 3] = f2bf2(u0.w, u1.w);
        }
    }
    __syncthreads();

    // stage 1: scores (warp tile 32 x 64), k = 64
    float acc[2][8][4];
    #pragma unroll
    for (int i = 0; i < 2; i++)
        #pragma unroll
        for (int j = 0; j < 8; j++)
            #pragma unroll
            for (int k = 0; k < 4; k++) acc[i][j][k] = 0.0f;
    #pragma unroll
    for (int kb = 0; kb < 4; kb++) {
        unsigned af[2][4], bf[8][2];
        #pragma unroll
        for (int mi = 0; mi < 2; mi++) {
            int r = wr * 32 + mi * 16 + g;
            af[mi][0] = Aq[kb * 8 + tg][r];
            af[mi][1] = Aq[kb * 8 + tg][r + 8];
            af[mi][2] = Aq[kb * 8 + tg + 4][r];
            af[mi][3] = Aq[kb * 8 + tg + 4][r + 8];
        }
        #pragma unroll
        for (int ni = 0; ni < 8; ni++) {
            int cc = wc * 64 + ni * 8 + g;
            bf[ni][0] = Bk[kb * 8 + tg][cc];
            bf[ni][1] = Bk[kb * 8 + tg + 4][cc];
        }
        #pragma unroll
        for (int mi = 0; mi < 2; mi++)
            #pragma unroll
            for (int ni = 0; ni < 8; ni++)
                mma_bf16(acc[mi][ni][0], acc[mi][ni][1], acc[mi][ni][2], acc[mi][ni][3],
                         af[mi][0], af[mi][1], af[mi][2], af[mi][3],
                         bf[ni][0], bf[ni][1]);
    }
    // apply SCALE
    #pragma unroll
    for (int i = 0; i < 2; i++)
        #pragma unroll
        for (int j = 0; j < 8; j++)
            #pragma unroll
            for (int k = 0; k < 4; k++) acc[i][j][k] *= SCALE;
    __syncthreads();  // all Aq/Bk reads done (PA may overwrite later)

    // softmax: rows per thread: (mi,half): row = wr*32 + mi*16 + half*8 + g
    float mx[2][2];
    #pragma unroll
    for (int mi = 0; mi < 2; mi++)
        #pragma unroll
        for (int hf = 0; hf < 2; hf++) {
            float m = -INFINITY;
            #pragma unroll
            for (int ni = 0; ni < 8; ni++)
                m = fmaxf(m, fmaxf(acc[mi][ni][2 * hf], acc[mi][ni][2 * hf + 1]));
            m = fmaxf(m, __shfl_xor_sync(0xffffffffu, m, 1));
            m = fmaxf(m, __shfl_xor_sync(0xffffffffu, m, 2));
            mx[mi][hf] = m;
        }
    if (tg == 0) {
        #pragma unroll
        for (int mi = 0; mi < 2; mi++)
            #pragma unroll
            for (int hf = 0; hf < 2; hf++)
                red[wr][mi * 16 + hf * 8 + g][wc] = mx[mi][hf];
    }
    __syncthreads();
    #pragma unroll
    for (int mi = 0; mi < 2; mi++)
        #pragma unroll
        for (int hf = 0; hf < 2; hf++) {
            int rl = mi * 16 + hf * 8 + g;
            mx[mi][hf] = fmaxf(fmaxf(red[wr][rl][0], red[wr][rl][1]),
                               fmaxf(red[wr][rl][2], red[wr][rl][3]));
        }
    __syncthreads();  // before red reuse
    float sm[2][2];
    #pragma unroll
    for (int mi = 0; mi < 2; mi++)
        #pragma unroll
        for (int hf = 0; hf < 2; hf++) {
            float s = 0.0f;
            #pragma unroll
            for (int ni = 0; ni < 8; ni++) {
                float e0 = __expf(acc[mi][ni][2 * hf]     - mx[mi][hf]);
                float e1 = __expf(acc[mi][ni][2 * hf + 1] - mx[mi][hf]);
                acc[mi][ni][2 * hf]     = e0;
                acc[mi][ni][2 * hf + 1] = e1;
                s += e0 + e1;
            }
            s += __shfl_xor_sync(0xffffffffu, s, 1);
            s += __shfl_xor_sync(0xffffffffu, s, 2);
            sm[mi][hf] = s;
        }
    if (tg == 0) {
        #pragma unroll
        for (int mi = 0; mi < 2; mi++)
            #pragma unroll
            for (int hf = 0; hf < 2; hf++)
                red[wr][mi * 16 + hf * 8 + g][wc] = sm[mi][hf];
    }
    __syncthreads();
    #pragma unroll
    for (int mi = 0; mi < 2; mi++)
        #pragma unroll
        for (int hf = 0; hf < 2; hf++) {
            int rl = mi * 16 + hf * 8 + g;
            float s = red[wr][rl][0] + red[wr][rl][1] + red[wr][rl][2] + red[wr][rl][3];
            sm[mi][hf] = 1.0f / s;
        }
    // P = e * inv; pack into PA (A-fragment layout, overwrites Aq/Bk)
    #pragma unroll
    for (int mi = 0; mi < 2; mi++) {
        int r = wr * 32 + mi * 16 + g;
        #pragma unroll
        for (int ni = 0; ni < 8; ni++) {
            int kp = wc * 32 + ni * 4 + tg;
            PA[kp][r]     = f2bf2(acc[mi][ni][0] * sm[mi][0], acc[mi][ni][1] * sm[mi][0]);
            PA[kp][r + 8] = f2bf2(acc[mi][ni][2] * sm[mi][1], acc[mi][ni][3] * sm[mi][1]);
        }
    }
    __syncthreads();

    // stage 2: out = P (64x256) @ z2_h (256x64); warp tile 32 x 16
    float o2[2][2][4];
    #pragma unroll
    for (int i = 0; i < 2; i++)
        #pragma unroll
        for (int j = 0; j < 2; j++)
            #pragma unroll
            for (int k = 0; k < 4; k++) o2[i][j][k] = 0.0f;
    for (int kb = 0; kb < 16; kb++) {
        {
            int kp = tid >> 5, c0 = (tid & 31) * 2;
            const float* zp = z2 + ((long long)h * MLM + kb * 16 + 2 * kp) * DH + c0;
            float2 r0 = *reinterpret_cast<const float2*>(zp);
            float2 r1 = *reinterpret_cast<const float2*>(zp + DH);
            Bzb[kp][c0 + 0] = f2bf2(r0.x, r1.x);
            Bzb[kp][c0 + 1] = f2bf2(r0.y, r1.y);
        }
        __syncthreads();
        unsigned af[2][4], bf[2][2];
        #pragma unroll
        for (int mi = 0; mi < 2; mi++) {
            int r = wr * 32 + mi * 16 + g;
            af[mi][0] = PA[kb * 8 + tg][r];
            af[mi][1] = PA[kb * 8 + tg][r + 8];
            af[mi][2] = PA[kb * 8 + tg + 4][r];
            af[mi][3] = PA[kb * 8 + tg + 4][r + 8];
        }
        #pragma unroll
        for (int nj = 0; nj < 2; nj++) {
            int cc = wc * 16 + nj * 8 + g;
            bf[nj][0] = Bzb[tg][cc];
            bf[nj][1] = Bzb[tg + 4][cc];
        }
        #pragma unroll
        for (int mi = 0; mi < 2; mi++)
            #pragma unroll
            for (int nj = 0; nj < 2; nj++)
                mma_bf16(o2[mi][nj][0], o2[mi][nj][1], o2[mi][nj][2], o2[mi][nj][3],
                         af[mi][0], af[mi][1], af[mi][2], af[mi][3],
                         bf[nj][0], bf[nj][1]);
        __syncthreads();
    }
    // epilogue: write ab[n0+r][h*64 + cc]
    #pragma unroll
    for (int mi = 0; mi < 2; mi++) {
        int r = n0 + wr * 32 + mi * 16 + g;
        #pragma unroll
        for (int nj = 0; nj < 2; nj++) {
            int cc = h * 64 + wc * 16 + nj * 8 + 2 * tg;
            float2 v0, v1;
            v0.x = o2[mi][nj][0]; v0.y = o2[mi][nj][1];
            v1.x = o2[mi][nj][2]; v1.y = o2[mi][nj][3];
            *reinterpret_cast<float2*>(&ab[(long long)r * D + cc]) = v0;
            *reinterpret_cast<float2*>(&ab[(long long)(r + 8) * D + cc]) = v1;
        }
    }
}

// ---------------- misc kernels ----------------
__global__ void k_zero(float* p, int n) {
    int i = blockIdx.x * 256 + threadIdx.x;
    if (i < n) p[i] = 0.0f;
}

// deterministic reduction of KSPL split-K partials
__global__ void k_redsplit(const float* __restrict__ part, float* __restrict__ out) {
    int i = blockIdx.x * 256 + threadIdx.x;
    if (i >= NH * MLM * DH) return;
    int b = i / (MLM * DH), r = i - b * (MLM * DH);
    const float* p = part + ((long long)b * KSPL) * (MLM * DH) + r;
    float s = 0.0f;
    #pragma unroll 1
    for (int ch = 0; ch < KSPL; ch++) s += p[(long long)ch * (MLM * DH)];
    out[i] = s;
}

// h rows 1..8192 already hold relu(fc1). Set row0=cls, wrap rows 8193..8281 <- rows 1..89.
__global__ void k_build(float* h, const float* cls) {
    int idx = blockIdx.x * 256 + threadIdx.x;
    if (idx < D) h[idx] = cls[idx];
    int j = idx - D;
    if (j >= 0 && j < 89 * D) {
        int r = j / D, c = j - r * D;
        h[(long long)(8193 + r) * D + c] = h[(long long)(1 + r) * D + c];
    }
}

__global__ void k_ln(const float* __restrict__ in, float* __restrict__ out,
                     const float* __restrict__ gg, const float* __restrict__ bb, int rows) {
    __shared__ float sh[32];
    int r = blockIdx.x;
    if (r >= rows) return;
    const float* x = in + (long long)r * D;
    int tid = threadIdx.x;
    float v0 = x[tid], v1 = x[tid + 256];
    float s  = blkSum(v0 + v1, sh, 256);
    float s2 = blkSum(v0 * v0 + v1 * v1, sh, 256);
    float mu = s * (1.0f / 512.0f);
    float var = s2 * (1.0f / 512.0f) - mu * mu;
    float inv = rsqrtf(var + 1e-5f);
    float* o = out + (long long)r * D;
    o[tid]       = (v0 - mu) * inv * gg[tid] + bb[tid];
    o[tid + 256] = (v1 - mu) * inv * gg[tid + 256] + bb[tid + 256];
}

// generic softmax (rows of arbitrary len); exp cached on pass 2
__global__ void k_softmax(float* __restrict__ S, int len) {
    __shared__ float sh[32];
    float* row = S + (long long)blockIdx.x * len;
    int tid = threadIdx.x;
    float m = -INFINITY;
    for (int i = tid; i < len; i += 256) m = fmaxf(m, row[i]);
    m = blkMax(m, sh, 256);
    float s = 0.0f;
    for (int i = tid; i < len; i += 256) {
        float e = __expf(row[i] - m);
        row[i] = e;
        s += e;
    }
    s = blkSum(s, sh, 256);
    float inv = 1.0f / s;
    for (int i = tid; i < len; i += 256) row[i] *= inv;
}

// one-pass softmax for rows of exactly 256 (one element per thread)
__global__ void k_softmax256(float* __restrict__ S) {
    __shared__ float sh[32];
    int tid = threadIdx.x;
    float* row = S + (long long)blockIdx.x * 256;
    float v = row[tid];
    float m = blkMax(v, sh, 256);
    float e = __expf(v - m);
    float s = blkSum(e, sh, 256);
    row[tid] = e / s;
}

// landmark means: ql[h][m][d] = mean_t q[m*33+t][h*64+d]; klT[h][d][m] = mean_t k[...]
__global__ void k_landmark(const float* __restrict__ qkv, float* __restrict__ ql,
                           float* __restrict__ klT) {
    int m = blockIdx.x, h = blockIdx.y, d = threadIdx.x;
    const float* base = qkv + (long long)(m * LWIN) * H3D + h * DH + d;
    float qs = 0.0f, ks = 0.0f;
    for (int t = 0; t < LWIN; t++) {
        qs += base[(long long)t * H3D];
        ks += base[(long long)t * H3D + D];
    }
    ql[((h * MLM) + m) * DH + d]  = qs * (1.0f / 33.0f);
    klT[((h * DH) + d) * MLM + m] = ks * (1.0f / 33.0f);
}

// kT[c][n] = qkv[n][D + c]  (c = h*64+d), tiled transpose
__global__ void k_transpose(const float* __restrict__ src, float* __restrict__ dst) {
    __shared__ float tile[32][33];
    int c0 = blockIdx.x * 32, n0 = blockIdx.y * 32;
    for (int i = threadIdx.y; i < 32; i += 8)
        tile[i][threadIdx.x] = src[(long long)(n0 + i) * H3D + D + c0 + threadIdx.x];
    __syncthreads();
    for (int i = threadIdx.y; i < 32; i += 8)
        dst[(long long)(c0 + i) * NP + n0 + threadIdx.x] = tile[threadIdx.x][i];
}

// per-head reductions: red[h*2]=max row-sum |a2_h|, red[h*2+1]=max col-sum |a2_h|
__global__ void k_pinv_red(const float* __restrict__ a2, float* __restrict__ red) {
    __shared__ float sh[32];
    int h = blockIdx.x;
    const float* A = a2 + (long long)h * MLM * MLM;
    int i = threadIdx.x;
    float rs = 0.0f, cs = 0.0f;
    for (int j = 0; j < MLM; j++) {
        rs += fabsf(A[i * MLM + j]);
        cs += fabsf(A[j * MLM + i]);
    }
    float colv = blkMax(rs, sh, 256);
    float rowv = blkMax(cs, sh, 256);
    if (i == 0) { red[h * 2] = colv; red[h * 2 + 1] = rowv; }
}

// z0 = a2^T / (col*row), col/row GLOBAL maxima across heads
__global__ void k_pinv_zinit(const float* __restrict__ a2, const float* __restrict__ red,
                             float* __restrict__ z) {
    int idx = blockIdx.x * 256 + threadIdx.x;
    if (idx >= NH * MLM * MLM) return;
    float colm = 0.0f, rowm = 0.0f;
    #pragma unroll
    for (int hh = 0; hh < NH; hh++) {
        colm = fmaxf(colm, red[hh * 2]);
        rowm = fmaxf(rowm, red[hh * 2 + 1]);
    }
    int h = idx >> 16;
    int r = (idx >> 8) & 255;
    int c = idx & 255;
    z[idx] = a2[((long long)h << 16) + c * MLM + r] / (colm * rowm);
}

// depthwise 33-tap conv over sequence of v, added to ab (float4: 4 ch/thread)
__global__ void k_conv(const float* __restrict__ qkv, const float* __restrict__ w,
                       float* __restrict__ ab) {
    __shared__ float ws[NH * LWIN];
    int tid = threadIdx.x;
    for (int i = tid; i < NH * LWIN; i += 128) ws[i] = w[i];
    __syncthreads();
    int n = blockIdx.x;
    int c4 = tid << 2;
    int h = c4 >> 6;
    const float* wrow = ws + h * LWIN;
    float4 s = make_float4(0.0f, 0.0f, 0.0f, 0.0f);
    #pragma unroll
    for (int t = 0; t < LWIN; t++) {
        int nn = n - 16 + t;
        if (nn >= 0 && nn < NP) {
            float wv = wrow[t];
            float4 v = *reinterpret_cast<const float4*>(
                qkv + (long long)nn * H3D + 2 * D + c4);
            s.x += wv * v.x; s.y += wv * v.y; s.z += wv * v.z; s.w += wv * v.w;
        }
    }
    float4* dst = reinterpret_cast<float4*>(ab + (long long)n * D + c4);
    float4 o = *dst;
    o.x += s.x; o.y += s.y; o.z += s.z; o.w += s.w;
    *dst = o;
}

__global__ void k_resid(float* __restrict__ h, const float* __restrict__ t) {
    int idx = blockIdx.x * 256 + threadIdx.x;   // float4 index
    if (idx < (NTOK * D) / 4) {
        float4 a = reinterpret_cast<float4*>(h)[idx];
        float4 b = reinterpret_cast<const float4*>(t + PAD * D)[idx];
        a.x += b.x; a.y += b.y; a.z += b.z; a.w += b.w;
        reinterpret_cast<float4*>(h)[idx] = a;
    }
}

// PPEG: out row 1+p = center + dw7 + dw5 + dw3 (+biases). Block 0 carries cls row.
__global__ void k_ppeg(const float* __restrict__ h, float* __restrict__ out,
                       const float* __restrict__ w7, const float* __restrict__ b7,
                       const float* __restrict__ w5, const float* __restrict__ b5,
                       const float* __restrict__ w3, const float* __restrict__ b3) {
    int p = blockIdx.x;
    int y = p / HS, x = p - y * HS;
    int c = threadIdx.x;
    if (p == 0) out[c] = h[c];
    float acc = h[(long long)(1 + p) * D + c] + b7[c] + b5[c] + b3[c];
    const float* W7 = w7 + c * 49;
    const float* W5 = w5 + c * 25;
    const float* W3 = w3 + c * 9;
    #pragma unroll
    for (int ky = 0; ky < 7; ky++) {
        int yy = y + ky - 3;
        if (yy < 0 || yy >= HS) continue;
        #pragma unroll
        for (int kx = 0; kx < 7; kx++) {
            int xx = x + kx - 3;
            if (xx < 0 || xx >= HS) continue;
            float v = h[(long long)(1 + yy * HS + xx) * D + c];
            float wsum = W7[ky * 7 + kx];
            if (ky >= 1 && ky <= 5 && kx >= 1 && kx <= 5) wsum += W5[(ky - 1) * 5 + (kx - 1)];
            if (ky >= 2 && ky <= 4 && kx >= 2 && kx <= 4) wsum += W3[(ky - 2) * 3 + (kx - 2)];
            acc += v * wsum;
        }
    }
    out[(long long)(1 + p) * D + c] = acc;
}

// final: emb = ln(h[0]); logits = emb@fc2 + b; softmax; argmax
__global__ void k_final(const float* __restrict__ h, const float* __restrict__ gg,
                        const float* __restrict__ bb, const float* __restrict__ fw,
                        const float* __restrict__ fb, float* __restrict__ out, int out_size) {
    __shared__ float sh[32];
    __shared__ float emb[512];
    int tid = threadIdx.x;
    float v = h[tid];
    float s  = blkSum(v, sh, 512);
    float s2 = blkSum(v * v, sh, 512);
    float mu = s * (1.0f / 512.0f);
    float var = s2 * (1.0f / 512.0f) - mu * mu;
    float inv = rsqrtf(var + 1e-5f);
    float e = (v - mu) * inv * gg[tid] + bb[tid];
    emb[tid] = e;
    if (5 + tid < out_size) out[5 + tid] = e;
    __syncthreads();
    if (tid == 0) {
        float l0 = fb[0], l1 = fb[1];
        for (int c = 0; c < 512; c++) { l0 += emb[c] * fw[2 * c]; l1 += emb[c] * fw[2 * c + 1]; }
        if (out_size > 0) out[0] = l0;
        if (out_size > 1) out[1] = l1;
        float m = fmaxf(l0, l1);
        float e0 = __expf(l0 - m), e1 = __expf(l1 - m);
        float ss = e0 + e1;
        if (out_size > 2) out[2] = e0 / ss;
        if (out_size > 3) out[3] = e1 / ss;
        if (out_size > 4) out[4] = (l1 > l0) ? 1.0f : 0.0f;
    }
}

// ---------------- host orchestration ----------------
static inline void gemm(const float* A, int lda, long long sA,
                        const float* B, int ldb, long long sB,
                        float* C, int ldc, long long sC,
                        int M, int N, int K, float alpha,
                        const float* bias, int relu, int batch,
                        int emode = 0, float cval = 0.0f, int ksplit = 1) {
    dim3 g(N / 64, M / 64, batch * ksplit);
    tgemm64<<<g, 128>>>(A, lda, sA, B, ldb, sB, C, ldc, sC, M, N, K, alpha, bias, relu,
                        emode, cval, ksplit);
}

static inline void gemmL(const float* A, int lda, long long sA,
                         const float* B, int ldb, long long sB,
                         float* C, int ldc, long long sC,
                         int M, int N, int K, float alpha,
                         const float* bias, int relu, int batch) {
    dim3 g(N / 128, M / 128, batch);
    tgemm<<<g, 256>>>(A, lda, sA, B, ldb, sB, C, ldc, sC, M, N, K, alpha, bias, relu);
}

struct Bufs {
    float *h, *t, *xp, *qkv, *kT, *s, *ql, *klT, *a2, *z0, *z1, *xz, *u, *tt,
          *part, *a3v, *z2, *ab, *red;
};

static void run_attn(Bufs& b, const float* lng, const float* lnb,
                     const float* qkvw, const float* outw, const float* outb,
                     const float* convw) {
    k_zero<<<(PAD * D + 255) / 256, 256>>>(b.xp, PAD * D);
    k_ln<<<NTOK, 256>>>(b.h, b.xp + (long long)PAD * D, lng, lnb, NTOK);
    gemmL(b.xp, D, 0, qkvw, H3D, 0, b.qkv, H3D, 0, NP, H3D, D, 1.0f, nullptr, 0, 1);
    k_landmark<<<dim3(MLM, NH), DH>>>(b.qkv, b.ql, b.klT);
    k_transpose<<<dim3(D / 32, NP / 32), dim3(32, 8)>>>(b.qkv, b.kT);
    // a2 = softmax(SCALE * ql @ kl^T)
    gemm(b.ql, DH, MLM * DH, b.klT, MLM, DH * MLM, b.a2, MLM, MLM * MLM,
         MLM, MLM, DH, SCALE, nullptr, 0, NH);
    k_softmax256<<<NH * MLM, 256>>>(b.a2);
    // pinv
    k_pinv_red<<<NH, 256>>>(b.a2, b.red);
    k_pinv_zinit<<<(NH * MLM * MLM + 255) / 256, 256>>>(b.a2, b.red, b.z0);
    float* zc = b.z0; float* zn = b.z1;
    const long long SB = (long long)MLM * MLM;
    for (int it = 0; it < 6; it++) {
        gemm(b.a2, MLM, SB, zc, MLM, SB, b.xz, MLM, SB, MLM, MLM, MLM, 1.0f, nullptr, 0, NH);
        gemm(b.xz, MLM, SB, b.xz, MLM, SB, b.u,  MLM, SB, MLM, MLM, MLM, 1.0f, nullptr, 0, NH, 1, 7.0f);
        gemm(b.xz, MLM, SB, b.u,  MLM, SB, b.tt, MLM, SB, MLM, MLM, MLM, 1.0f, nullptr, 0, NH, 1, 15.0f);
        gemm(zc,   MLM, SB, b.tt, MLM, SB, zn,   MLM, SB, MLM, MLM, MLM, 0.25f, nullptr, 0, NH, 1, 13.0f);
        float* sw = zc; zc = zn; zn = sw;
    }
    // a3 = softmax_n(SCALE * ql @ k^T)
    gemmL(b.ql, DH, MLM * DH, b.kT, NP, (long long)DH * NP, b.s, NP, (long long)MLM * NP,
          MLM, NP, DH, SCALE, nullptr, 0, NH);
    k_softmax<<<NH * MLM, 256>>>(b.s, NP);
    // a3v = a3 @ v  (split-K: 33 chunks of 256, deterministic reduce)
    gemm(b.s, NP, (long long)MLM * NP, b.qkv + 2 * D, H3D, DH,
         b.part, DH, (long long)MLM * DH,
         MLM, DH, NP / KSPL, 1.0f, nullptr, 0, NH, 0, 0.0f, KSPL);
    k_redsplit<<<(NH * MLM * DH + 255) / 256, 256>>>(b.part, b.a3v);
    // z2 = pinv @ a3v
    gemm(zc, MLM, SB, b.a3v, DH, MLM * DH, b.z2, DH, MLM * DH, MLM, DH, MLM, 1.0f, nullptr, 0, NH);
    // fused a1 chain: ab = softmax(SCALE*q@klT) @ z2 per head
    k_a1fused<<<dim3(NP / 64, NH), 256>>>(b.qkv, b.klT, b.z2, b.ab);
    // + depthwise conv(v)
    k_conv<<<NP, 128>>>(b.qkv, convw, b.ab);
    // proj + residual (last NTOK rows)
    gemmL(b.ab, D, 0, outw, D, 0, b.t, D, 0, NP, D, D, 1.0f, outb, 0, 1);
    k_resid<<<((NTOK * D / 4) + 255) / 256, 256>>>(b.h, b.t);
}

extern "C" void kernel_launch(void* const* d_in, const int* in_sizes, int n_in,
                              void* d_out, int out_size) {
    const float* x      = (const float*)d_in[0];
    const float* fc1_w  = (const float*)d_in[1];
    const float* fc1_b  = (const float*)d_in[2];
    const float* cls    = (const float*)d_in[3];
    const float* ln1_g  = (const float*)d_in[4];
    const float* ln1_b  = (const float*)d_in[5];
    const float* qkv1_w = (const float*)d_in[6];
    const float* out1_w = (const float*)d_in[7];
    const float* out1_b = (const float*)d_in[8];
    const float* conv1_w= (const float*)d_in[9];
    const float* ln2_g  = (const float*)d_in[10];
    const float* ln2_b  = (const float*)d_in[11];
    const float* qkv2_w = (const float*)d_in[12];
    const float* out2_w = (const float*)d_in[13];
    const float* out2_b = (const float*)d_in[14];
    const float* conv2_w= (const float*)d_in[15];
    const float* pg7_w  = (const float*)d_in[16];
    const float* pg7_b  = (const float*)d_in[17];
    const float* pg5_w  = (const float*)d_in[18];
    const float* pg5_b  = (const float*)d_in[19];
    const float* pg3_w  = (const float*)d_in[20];
    const float* pg3_b  = (const float*)d_in[21];
    const float* norm_g = (const float*)d_in[22];
    const float* norm_b = (const float*)d_in[23];
    const float* fc2_w  = (const float*)d_in[24];
    const float* fc2_b  = (const float*)d_in[25];

    Bufs b;
    cudaGetSymbolAddress((void**)&b.h,    g_h);
    cudaGetSymbolAddress((void**)&b.t,    g_t);
    cudaGetSymbolAddress((void**)&b.xp,   g_xp);
    cudaGetSymbolAddress((void**)&b.qkv,  g_qkv);
    cudaGetSymbolAddress((void**)&b.kT,   g_kT);
    cudaGetSymbolAddress((void**)&b.s,    g_s);
    cudaGetSymbolAddress((void**)&b.ql,   g_ql);
    cudaGetSymbolAddress((void**)&b.klT,  g_klT);
    cudaGetSymbolAddress((void**)&b.a2,   g_a2);
    cudaGetSymbolAddress((void**)&b.z0,   g_z0);
    cudaGetSymbolAddress((void**)&b.z1,   g_z1);
    cudaGetSymbolAddress((void**)&b.xz,   g_xz);
    cudaGetSymbolAddress((void**)&b.u,    g_u);
    cudaGetSymbolAddress((void**)&b.tt,   g_tt);
    cudaGetSymbolAddress((void**)&b.part, g_part);
    cudaGetSymbolAddress((void**)&b.a3v,  g_a3v);
    cudaGetSymbolAddress((void**)&b.z2,   g_z2);
    cudaGetSymbolAddress((void**)&b.ab,   g_ab);
    cudaGetSymbolAddress((void**)&b.red,  g_red);

    // fc1: h rows 1..8192 = relu(x @ fc1_w + b)
    gemmL(x, 1024, 0, fc1_w, D, 0, b.h + D, D, 0, 8192, D, 1024, 1.0f, fc1_b, 1, 1);
    k_build<<<(90 * D + 255) / 256, 256>>>(b.h, cls);

    // layer 1 attention
    run_attn(b, ln1_g, ln1_b, qkv1_w, out1_w, out1_b, conv1_w);

    // PPEG: write into t (incl. cls row), then swap h <-> t
    k_ppeg<<<NPIX, 512>>>(b.h, b.t, pg7_w, pg7_b, pg5_w, pg5_b, pg3_w, pg3_b);
    { float* tmp = b.h; b.h = b.t; b.t = tmp; }

    // layer 2 attention
    run_attn(b, ln2_g, ln2_b, qkv2_w, out2_w, out2_b, conv2_w);

    // head
    k_final<<<1, 512>>>(b.h, norm_g, norm_b, fc2_w, fc2_b, (float*)d_out, out_size);
}

// round 16
// speedup vs baseline: 1.9461x; 1.0454x over previous
#include <cuda_runtime.h>
#include <math.h>

// ---------------- problem constants ----------------
#define NTOK   8282          // tokens incl. cls (1 + 8281)
#define PAD    166           // front zero-pad inside nystrom
#define NP     8448          // padded length = 33*256
#define D      512
#define H3D    1536          // 3*D
#define NH     8             // heads
#define DH     64
#define MLM    256           // landmarks
#define LWIN   33            // tokens per landmark
#define SCALE  0.125f        // DH^-0.5
#define HS     91            // ppeg grid 91x91 = 8281
#define NPIX   8281
#define KSPL   33            // (legacy) split-K chunks
#define SPL    4             // a3 flash splits
#define CHN    2112          // NP/SPL
#define A3T    33            // CHN/64

// ---------------- static device scratch ----------------
__device__ float g_h   [NP * D];
__device__ float g_t   [NP * D];
__device__ float g_xp  [NP * D];
__device__ float g_qkv [NP * H3D];
__device__ float g_s   [NH * NP * MLM];
__device__ float g_ql  [NH * MLM * DH];
__device__ float g_klT [NH * DH * MLM];
__device__ float g_a2  [NH * MLM * MLM];
__device__ float g_z0  [NH * MLM * MLM];
__device__ float g_z1  [NH * MLM * MLM];
__device__ float g_xz  [NH * MLM * MLM];
__device__ float g_u   [NH * MLM * MLM];
__device__ float g_tt  [NH * MLM * MLM];
__device__ float g_part[NH * KSPL * MLM * DH];
__device__ float g_a3v [NH * MLM * DH];
__device__ float g_z2  [NH * MLM * DH];
__device__ float g_ab  [NP * D];
__device__ float g_red [NH * 2];

// ---------------- block reductions ----------------
__device__ __forceinline__ float blkSum(float v, float* sh, int nt) {
    int tid = threadIdx.x;
    #pragma unroll
    for (int o = 16; o; o >>= 1) v += __shfl_down_sync(0xffffffffu, v, o);
    __syncthreads();
    if ((tid & 31) == 0) sh[tid >> 5] = v;
    __syncthreads();
    int nw = nt >> 5;
    float r = (tid < nw) ? sh[tid] : 0.0f;
    if (tid < 32) {
        for (int o = nw >> 1; o; o >>= 1) r += __shfl_down_sync(0xffffffffu, r, o);
    }
    if (tid == 0) sh[0] = r;
    __syncthreads();
    float res = sh[0];
    __syncthreads();
    return res;
}

__device__ __forceinline__ float blkMax(float v, float* sh, int nt) {
    int tid = threadIdx.x;
    #pragma unroll
    for (int o = 16; o; o >>= 1) v = fmaxf(v, __shfl_down_sync(0xffffffffu, v, o));
    __syncthreads();
    if ((tid & 31) == 0) sh[tid >> 5] = v;
    __syncthreads();
    int nw = nt >> 5;
    float r = (tid < nw) ? sh[tid] : -INFINITY;
    if (tid < 32) {
        for (int o = nw >> 1; o; o >>= 1) r = fmaxf(r, __shfl_down_sync(0xffffffffu, r, o));
    }
    if (tid == 0) sh[0] = r;
    __syncthreads();
    float res = sh[0];
    __syncthreads();
    return res;
}

// ---------------- bf16 helpers ----------------
__device__ __forceinline__ unsigned f2bf2(float lo, float hi) {
    unsigned u;
    asm("cvt.rn.bf16x2.f32 %0, %1, %2;" : "=r"(u) : "f"(hi), "f"(lo));
    return u;
}

__device__ __forceinline__ void mma_bf16(float& c0, float& c1, float& c2, float& c3,
                                         unsigned a0, unsigned a1, unsigned a2, unsigned a3,
                                         unsigned b0, unsigned b1) {
    asm volatile(
        "mma.sync.aligned.m16n8k16.row.col.f32.bf16.bf16.f32 "
        "{%0,%1,%2,%3}, {%4,%5,%6,%7}, {%8,%9}, {%0,%1,%2,%3};"
        : "+f"(c0), "+f"(c1), "+f"(c2), "+f"(c3)
        : "r"(a0), "r"(a1), "r"(a2), "r"(a3), "r"(b0), "r"(b1));
}

// ---------------- 64x64 bf16 tensor GEMM (double-buffered, emode, split-K) --
__global__ void __launch_bounds__(128) tgemm64(
    const float* __restrict__ A, int lda, long long sA,
    const float* __restrict__ B, int ldb, long long sB,
    float* __restrict__ C, int ldc, long long sC,
    int M, int N, int K, float alpha,
    const float* __restrict__ bias, int relu,
    int emode, float cval, int ksplit)
{
    __shared__ unsigned As[2][8][72];
    __shared__ unsigned Bs[2][8][72];
    int bz = blockIdx.z / ksplit, ch = blockIdx.z % ksplit;
    A += (long long)bz * sA + (long long)ch * K;
    B += (long long)bz * sB + (long long)ch * K * ldb;
    C += (long long)blockIdx.z * sC;
    int tid = threadIdx.x;
    int row0 = blockIdx.y * 64, col0 = blockIdx.x * 64;
    int wid = tid >> 5, lane = tid & 31;
    int wr = wid >> 1, wc = wid & 1;
    int g = lane >> 2, tg = lane & 3;
    int ar = tid >> 1, akp = (tid & 1) << 2;
    int bkp = tid >> 4, bc = (tid & 15) << 2;
    const float* Ap = A + (long long)(row0 + ar) * lda + (akp << 1);
    const float* Bp = B + (long long)(bkp << 1) * ldb + col0 + bc;
    float acc[2][4][4];
    #pragma unroll
    for (int i = 0; i < 2; i++)
        #pragma unroll
        for (int j = 0; j < 4; j++)
            #pragma unroll
            for (int k = 0; k < 4; k++) acc[i][j][k] = 0.0f;
    int nt = K >> 4;

    {
        float4 a0 = *reinterpret_cast<const float4*>(Ap);
        float4 a1 = *reinterpret_cast<const float4*>(Ap + 4);
        float4 r0 = *reinterpret_cast<const float4*>(Bp);
        float4 r1 = *reinterpret_cast<const float4*>(Bp + ldb);
        if (emode) {
            int k0 = bkp << 1, cb = col0 + bc;
            r0.x = ((k0 == cb + 0) ? cval : 0.0f) - r0.x;
            r0.y = ((k0 == cb + 1) ? cval : 0.0f) - r0.y;
            r0.z = ((k0 == cb + 2) ? cval : 0.0f) - r0.z;
            r0.w = ((k0 == cb + 3) ? cval : 0.0f) - r0.w;
            r1.x = ((k0 + 1 == cb + 0) ? cval : 0.0f) - r1.x;
            r1.y = ((k0 + 1 == cb + 1) ? cval : 0.0f) - r1.y;
            r1.z = ((k0 + 1 == cb + 2) ? cval : 0.0f) - r1.z;
            r1.w = ((k0 + 1 == cb + 3) ? cval : 0.0f) - r1.w;
        }
        As[0][akp + 0][ar] = f2bf2(a0.x, a0.y);
        As[0][akp + 1][ar] = f2bf2(a0.z, a0.w);
        As[0][akp + 2][ar] = f2bf2(a1.x, a1.y);
        As[0][akp + 3][ar] = f2bf2(a1.z, a1.w);
        Bs[0][bkp][bc + 0] = f2bf2(r0.x, r1.x);
        Bs[0][bkp][bc + 1] = f2bf2(r0.y, r1.y);
        Bs[0][bkp][bc + 2] = f2bf2(r0.z, r1.z);
        Bs[0][bkp][bc + 3] = f2bf2(r0.w, r1.w);
    }
    __syncthreads();

    int buf = 0;
    for (int t = 0; t < nt; t++) {
        float4 na0, na1, nr0, nr1;
        if (t + 1 < nt) {
            na0 = *reinterpret_cast<const float4*>(Ap + (t + 1) * 16);
            na1 = *reinterpret_cast<const float4*>(Ap + (t + 1) * 16 + 4);
            nr0 = *reinterpret_cast<const float4*>(Bp + (long long)(t + 1) * 16 * ldb);
            nr1 = *reinterpret_cast<const float4*>(Bp + (long long)(t + 1) * 16 * ldb + ldb);
            if (emode) {
                int k0 = (t + 1) * 16 + (bkp << 1), cb = col0 + bc;
                nr0.x = ((k0 == cb + 0) ? cval : 0.0f) - nr0.x;
                nr0.y = ((k0 == cb + 1) ? cval : 0.0f) - nr0.y;
                nr0.z = ((k0 == cb + 2) ? cval : 0.0f) - nr0.z;
                nr0.w = ((k0 == cb + 3) ? cval : 0.0f) - nr0.w;
                nr1.x = ((k0 + 1 == cb + 0) ? cval : 0.0f) - nr1.x;
                nr1.y = ((k0 + 1 == cb + 1) ? cval : 0.0f) - nr1.y;
                nr1.z = ((k0 + 1 == cb + 2) ? cval : 0.0f) - nr1.z;
                nr1.w = ((k0 + 1 == cb + 3) ? cval : 0.0f) - nr1.w;
            }
        }
        {
            unsigned af[2][4], bf[4][2];
            #pragma unroll
            for (int mi = 0; mi < 2; mi++) {
                int r = wr * 32 + mi * 16 + g;
                af[mi][0] = As[buf][tg][r];
                af[mi][1] = As[buf][tg][r + 8];
                af[mi][2] = As[buf][tg + 4][r];
                af[mi][3] = As[buf][tg + 4][r + 8];
            }
            #pragma unroll
            for (int ni = 0; ni < 4; ni++) {
                int cc = wc * 32 + ni * 8 + g;
                bf[ni][0] = Bs[buf][tg][cc];
                bf[ni][1] = Bs[buf][tg + 4][cc];
            }
            #pragma unroll
            for (int mi = 0; mi < 2; mi++)
                #pragma unroll
                for (int ni = 0; ni < 4; ni++)
                    mma_bf16(acc[mi][ni][0], acc[mi][ni][1], acc[mi][ni][2], acc[mi][ni][3],
                             af[mi][0], af[mi][1], af[mi][2], af[mi][3],
                             bf[ni][0], bf[ni][1]);
        }
        if (t + 1 < nt) {
            buf ^= 1;
            As[buf][akp + 0][ar] = f2bf2(na0.x, na0.y);
            As[buf][akp + 1][ar] = f2bf2(na0.z, na0.w);
            As[buf][akp + 2][ar] = f2bf2(na1.x, na1.y);
            As[buf][akp + 3][ar] = f2bf2(na1.z, na1.w);
            Bs[buf][bkp][bc + 0] = f2bf2(nr0.x, nr1.x);
            Bs[buf][bkp][bc + 1] = f2bf2(nr0.y, nr1.y);
            Bs[buf][bkp][bc + 2] = f2bf2(nr0.z, nr1.z);
            Bs[buf][bkp][bc + 3] = f2bf2(nr0.w, nr1.w);
            __syncthreads();
        }
    }

    #pragma unroll
    for (int mi = 0; mi < 2; mi++) {
        int r = row0 + wr * 32 + mi * 16 + g;
        #pragma unroll
        for (int ni = 0; ni < 4; ni++) {
            int cc = col0 + wc * 32 + ni * 8 + 2 * tg;
            float2 v0, v1;
            v0.x = alpha * acc[mi][ni][0]; v0.y = alpha * acc[mi][ni][1];
            v1.x = alpha * acc[mi][ni][2]; v1.y = alpha * acc[mi][ni][3];
            if (bias) {
                float b0 = bias[cc], b1 = bias[cc + 1];
                v0.x += b0; v0.y += b1; v1.x += b0; v1.y += b1;
            }
            if (relu) {
                v0.x = fmaxf(v0.x, 0.0f); v0.y = fmaxf(v0.y, 0.0f);
                v1.x = fmaxf(v1.x, 0.0f); v1.y = fmaxf(v1.y, 0.0f);
            }
            *reinterpret_cast<float2*>(&C[(long long)r * ldc + cc]) = v0;
            *reinterpret_cast<float2*>(&C[(long long)(r + 8) * ldc + cc]) = v1;
        }
    }
}

// ---------------- 128x128 bf16 tensor-core GEMM (double-buffered) --------
__global__ void __launch_bounds__(256) tgemm(
    const float* __restrict__ A, int lda, long long sA,
    const float* __restrict__ B, int ldb, long long sB,
    float* __restrict__ C, int ldc, long long sC,
    int M, int N, int K, float alpha,
    const float* __restrict__ bias, int relu)
{
    __shared__ unsigned As[2][8][136];
    __shared__ unsigned Bs[2][8][136];
    A += (long long)blockIdx.z * sA;
    B += (long long)blockIdx.z * sB;
    C += (long long)blockIdx.z * sC;
    int tid = threadIdx.x;
    int row0 = blockIdx.y * 128, col0 = blockIdx.x * 128;
    int wid = tid >> 5, lane = tid & 31;
    int wr = wid >> 2, wc = wid & 3;
    int g = lane >> 2, tg = lane & 3;
    int ar = tid >> 1, akp = (tid & 1) << 2;
    int bkp = tid >> 5, bc = (tid & 31) << 2;
    const float* Ap = A + (long long)(row0 + ar) * lda + (akp << 1);
    const float* Bp = B + (long long)(bkp << 1) * ldb + col0 + bc;
    float acc[4][4][4];
    #pragma unroll
    for (int i = 0; i < 4; i++)
        #pragma unroll
        for (int j = 0; j < 4; j++)
            #pragma unroll
            for (int k = 0; k < 4; k++) acc[i][j][k] = 0.0f;
    int nt = K >> 4;

    {
        float4 a0 = *reinterpret_cast<const float4*>(Ap);
        float4 a1 = *reinterpret_cast<const float4*>(Ap + 4);
        float4 r0 = *reinterpret_cast<const float4*>(Bp);
        float4 r1 = *reinterpret_cast<const float4*>(Bp + ldb);
        As[0][akp + 0][ar] = f2bf2(a0.x, a0.y);
        As[0][akp + 1][ar] = f2bf2(a0.z, a0.w);
        As[0][akp + 2][ar] = f2bf2(a1.x, a1.y);
        As[0][akp + 3][ar] = f2bf2(a1.z, a1.w);
        Bs[0][bkp][bc + 0] = f2bf2(r0.x, r1.x);
        Bs[0][bkp][bc + 1] = f2bf2(r0.y, r1.y);
        Bs[0][bkp][bc + 2] = f2bf2(r0.z, r1.z);
        Bs[0][bkp][bc + 3] = f2bf2(r0.w, r1.w);
    }
    __syncthreads();

    int buf = 0;
    for (int t = 0; t < nt; t++) {
        float4 na0, na1, nr0, nr1;
        if (t + 1 < nt) {
            na0 = *reinterpret_cast<const float4*>(Ap + (t + 1) * 16);
            na1 = *reinterpret_cast<const float4*>(Ap + (t + 1) * 16 + 4);
            nr0 = *reinterpret_cast<const float4*>(Bp + (long long)(t + 1) * 16 * ldb);
            nr1 = *reinterpret_cast<const float4*>(Bp + (long long)(t + 1) * 16 * ldb + ldb);
        }
        {
            unsigned af[4][4], bf[4][2];
            #pragma unroll
            for (int mi = 0; mi < 4; mi++) {
                int r = wr * 64 + mi * 16 + g;
                af[mi][0] = As[buf][tg][r];
                af[mi][1] = As[buf][tg][r + 8];
                af[mi][2] = As[buf][tg + 4][r];
                af[mi][3] = As[buf][tg + 4][r + 8];
            }
            #pragma unroll
            for (int ni = 0; ni < 4; ni++) {
                int cc = wc * 32 + ni * 8 + g;
                bf[ni][0] = Bs[buf][tg][cc];
                bf[ni][1] = Bs[buf][tg + 4][cc];
            }
            #pragma unroll
            for (int mi = 0; mi < 4; mi++)
                #pragma unroll
                for (int ni = 0; ni < 4; ni++)
                    mma_bf16(acc[mi][ni][0], acc[mi][ni][1], acc[mi][ni][2], acc[mi][ni][3],
                             af[mi][0], af[mi][1], af[mi][2], af[mi][3],
                             bf[ni][0], bf[ni][1]);
        }
        if (t + 1 < nt) {
            buf ^= 1;
            As[buf][akp + 0][ar] = f2bf2(na0.x, na0.y);
            As[buf][akp + 1][ar] = f2bf2(na0.z, na0.w);
            As[buf][akp + 2][ar] = f2bf2(na1.x, na1.y);
            As[buf][akp + 3][ar] = f2bf2(na1.z, na1.w);
            Bs[buf][bkp][bc + 0] = f2bf2(nr0.x, nr1.x);
            Bs[buf][bkp][bc + 1] = f2bf2(nr0.y, nr1.y);
            Bs[buf][bkp][bc + 2] = f2bf2(nr0.z, nr1.z);
            Bs[buf][bkp][bc + 3] = f2bf2(nr0.w, nr1.w);
            __syncthreads();
        }
    }

    #pragma unroll
    for (int mi = 0; mi < 4; mi++) {
        int r = row0 + wr * 64 + mi * 16 + g;
        #pragma unroll
        for (int ni = 0; ni < 4; ni++) {
            int cc = col0 + wc * 32 + ni * 8 + 2 * tg;
            float2 v0, v1;
            v0.x = alpha * acc[mi][ni][0]; v0.y = alpha * acc[mi][ni][1];
            v1.x = alpha * acc[mi][ni][2]; v1.y = alpha * acc[mi][ni][3];
            if (bias) {
                float b0 = bias[cc], b1 = bias[cc + 1];
                v0.x += b0; v0.y += b1; v1.x += b0; v1.y += b1;
            }
            if (relu) {
                v0.x = fmaxf(v0.x, 0.0f); v0.y = fmaxf(v0.y, 0.0f);
                v1.x = fmaxf(v1.x, 0.0f); v1.y = fmaxf(v1.y, 0.0f);
            }
            *reinterpret_cast<float2*>(&C[(long long)r * ldc + cc]) = v0;
            *reinterpret_cast<float2*>(&C[(long long)(r + 8) * ldc + cc]) = v1;
        }
    }
}

// ---------------- fused a1 chain -----------------------------------------
__global__ void __launch_bounds__(256) k_a1fused(
    const float* __restrict__ qkv, const float* __restrict__ klT,
    const float* __restrict__ z2, float* __restrict__ ab)
{
    __shared__ unsigned SM[10752];
    __shared__ unsigned Bzb[8][72];
    __shared__ float red[2][32][4];
    unsigned (*Aq)[72]  = reinterpret_cast<unsigned(*)[72]>(SM);
    unsigned (*Bk)[264] = reinterpret_cast<unsigned(*)[264]>(SM + 2304);
    unsigned (*PA)[72]  = reinterpret_cast<unsigned(*)[72]>(SM);

    int h = blockIdx.y;
    int n0 = blockIdx.x * 64;
    int tid = threadIdx.x;
    int wid = tid >> 5, lane = tid & 31;
    int wr = wid >> 2, wc = wid & 3;
    int g = lane >> 2, tg = lane & 3;

    {
        int ar = tid >> 2, d0 = (tid & 3) << 4;
        const float* qp = qkv + (long long)(n0 + ar) * H3D + h * DH + d0;
        #pragma unroll
        for (int j = 0; j < 4; j++) {
            float4 v = *reinterpret_cast<const float4*>(qp + 4 * j);
            Aq[(d0 >> 1) + 2 * j + 0][ar] = f2bf2(v.x, v.y);
            Aq[(d0 >> 1) + 2 * j + 1][ar] = f2bf2(v.z, v.w);
        }
    }
    {
        int dp = tid >> 3, mc = (tid & 7) << 5;
        const float* k0 = klT + ((long long)h * DH + 2 * dp) * MLM + mc;
        const float* k1 = k0 + MLM;
        #pragma unroll
        for (int j = 0; j < 8; j++) {
            float4 u0 = *reinterpret_cast<const float4*>(k0 + 4 * j);
            float4 u1 = *reinterpret_cast<const float4*>(k1 + 4 * j);
            Bk[dp][mc + 4 * j + 0] = f2bf2(u0.x, u1.x);
            Bk[dp][mc + 4 * j + 1] = f2bf2(u0.y, u1.y);
            Bk[dp][mc + 4 * j + 2] = f2bf2(u0.z, u1.z);
            Bk[dp][mc + 4 * j + 3] = f2bf2(u0.w, u1.w);
        }
    }
    __syncthreads();

    float acc[2][8][4];
    #pragma unroll
    for (int i = 0; i < 2; i++)
        #pragma unroll
        for (int j = 0; j < 8; j++)
            #pragma unroll
            for (int k = 0; k < 4; k++) acc[i][j][k] = 0.0f;
    #pragma unroll
    for (int kb = 0; kb < 4; kb++) {
        unsigned af[2][4], bf[8][2];
        #pragma unroll
        for (int mi = 0; mi < 2; mi++) {
            int r = wr * 32 + mi * 16 + g;
            af[mi][0] = Aq[kb * 8 + tg][r];
            af[mi][1] = Aq[kb * 8 + tg][r + 8];
            af[mi][2] = Aq[kb * 8 + tg + 4][r];
            af[mi][3] = Aq[kb * 8 + tg + 4][r + 8];
        }
        #pragma unroll
        for (int ni = 0; ni < 8; ni++) {
            int cc = wc * 64 + ni * 8 + g;
            bf[ni][0] = Bk[kb * 8 + tg][cc];
            bf[ni][1] = Bk[kb * 8 + tg + 4][cc];
        }
        #pragma unroll
        for (int mi = 0; mi < 2; mi++)
            #pragma unroll
            for (int ni = 0; ni < 8; ni++)
                mma_bf16(acc[mi][ni][0], acc[mi][ni][1], acc[mi][ni][2], acc[mi][ni][3],
                         af[mi][0], af[mi][1], af[mi][2], af[mi][3],
                         bf[ni][0], bf[ni][1]);
    }
    #pragma unroll
    for (int i = 0; i < 2; i++)
        #pragma unroll
        for (int j = 0; j < 8; j++)
            #pragma unroll
            for (int k = 0; k < 4; k++) acc[i][j][k] *= SCALE;
    __syncthreads();

    float mx[2][2];
    #pragma unroll
    for (int mi = 0; mi < 2; mi++)
        #pragma unroll
        for (int hf = 0; hf < 2; hf++) {
            float m = -INFINITY;
            #pragma unroll
            for (int ni = 0; ni < 8; ni++)
                m = fmaxf(m, fmaxf(acc[mi][ni][2 * hf], acc[mi][ni][2 * hf + 1]));
            m = fmaxf(m, __shfl_xor_sync(0xffffffffu, m, 1));
            m = fmaxf(m, __shfl_xor_sync(0xffffffffu, m, 2));
            mx[mi][hf] = m;
        }
    if (tg == 0) {
        #pragma unroll
        for (int mi = 0; mi < 2; mi++)
            #pragma unroll
            for (int hf = 0; hf < 2; hf++)
                red[wr][mi * 16 + hf * 8 + g][wc] = mx[mi][hf];
    }
    __syncthreads();
    #pragma unroll
    for (int mi = 0; mi < 2; mi++)
        #pragma unroll
        for (int hf = 0; hf < 2; hf++) {
            int rl = mi * 16 + hf * 8 + g;
            mx[mi][hf] = fmaxf(fmaxf(red[wr][rl][0], red[wr][rl][1]),
                               fmaxf(red[wr][rl][2], red[wr][rl][3]));
        }
    __syncthreads();
    float sm[2][2];
    #pragma unroll
    for (int mi = 0; mi < 2; mi++)
        #pragma unroll
        for (int hf = 0; hf < 2; hf++) {
            float s = 0.0f;
            #pragma unroll
            for (int ni = 0; ni < 8; ni++) {
                float e0 = __expf(acc[mi][ni][2 * hf]     - mx[mi][hf]);
                float e1 = __expf(acc[mi][ni][2 * hf + 1] - mx[mi][hf]);
                acc[mi][ni][2 * hf]     = e0;
                acc[mi][ni][2 * hf + 1] = e1;
                s += e0 + e1;
            }
            s += __shfl_xor_sync(0xffffffffu, s, 1);
            s += __shfl_xor_sync(0xffffffffu, s, 2);
            sm[mi][hf] = s;
        }
    if (tg == 0) {
        #pragma unroll
        for (int mi = 0; mi < 2; mi++)
            #pragma unroll
            for (int hf = 0; hf < 2; hf++)
                red[wr][mi * 16 + hf * 8 + g][wc] = sm[mi][hf];
    }
    __syncthreads();
    #pragma unroll
    for (int mi = 0; mi < 2; mi++)
        #pragma unroll
        for (int hf = 0; hf < 2; hf++) {
            int rl = mi * 16 + hf * 8 + g;
            float s = red[wr][rl][0] + red[wr][rl][1] + red[wr][rl][2] + red[wr][rl][3];
            sm[mi][hf] = 1.0f / s;
        }
    #pragma unroll
    for (int mi = 0; mi < 2; mi++) {
        int r = wr * 32 + mi * 16 + g;
        #pragma unroll
        for (int ni = 0; ni < 8; ni++) {
            int kp = wc * 32 + ni * 4 + tg;
            PA[kp][r]     = f2bf2(acc[mi][ni][0] * sm[mi][0], acc[mi][ni][1] * sm[mi][0]);
            PA[kp][r + 8] = f2bf2(acc[mi][ni][2] * sm[mi][1], acc[mi][ni][3] * sm[mi][1]);
        }
    }
    __syncthreads();

    float o2[2][2][4];
    #pragma unroll
    for (int i = 0; i < 2; i++)
        #pragma unroll
        for (int j = 0; j < 2; j++)
            #pragma unroll
            for (int k = 0; k < 4; k++) o2[i][j][k] = 0.0f;
    for (int kb = 0; kb < 16; kb++) {
        {
            int kp = tid >> 5, c0 = (tid & 31) * 2;
            const float* zp = z2 + ((long long)h * MLM + kb * 16 + 2 * kp) * DH + c0;
            float2 r0 = *reinterpret_cast<const float2*>(zp);
            float2 r1 = *reinterpret_cast<const float2*>(zp + DH);
            Bzb[kp][c0 + 0] = f2bf2(r0.x, r1.x);
            Bzb[kp][c0 + 1] = f2bf2(r0.y, r1.y);
        }
        __syncthreads();
        unsigned af[2][4], bf[2][2];
        #pragma unroll
        for (int mi = 0; mi < 2; mi++) {
            int r = wr * 32 + mi * 16 + g;
            af[mi][0] = PA[kb * 8 + tg][r];
            af[mi][1] = PA[kb * 8 + tg][r + 8];
            af[mi][2] = PA[kb * 8 + tg + 4][r];
            af[mi][3] = PA[kb * 8 + tg + 4][r + 8];
        }
        #pragma unroll
        for (int nj = 0; nj < 2; nj++) {
            int cc = wc * 16 + nj * 8 + g;
            bf[nj][0] = Bzb[tg][cc];
            bf[nj][1] = Bzb[tg + 4][cc];
        }
        #pragma unroll
        for (int mi = 0; mi < 2; mi++)
            #pragma unroll
            for (int nj = 0; nj < 2; nj++)
                mma_bf16(o2[mi][nj][0], o2[mi][nj][1], o2[mi][nj][2], o2[mi][nj][3],
                         af[mi][0], af[mi][1], af[mi][2], af[mi][3],
                         bf[nj][0], bf[nj][1]);
        __syncthreads();
    }
    #pragma unroll
    for (int mi = 0; mi < 2; mi++) {
        int r = n0 + wr * 32 + mi * 16 + g;
        #pragma unroll
        for (int nj = 0; nj < 2; nj++) {
            int cc = h * 64 + wc * 16 + nj * 8 + 2 * tg;
            float2 v0, v1;
            v0.x = o2[mi][nj][0]; v0.y = o2[mi][nj][1];
            v1.x = o2[mi][nj][2]; v1.y = o2[mi][nj][3];
            *reinterpret_cast<float2*>(&ab[(long long)r * D + cc]) = v0;
            *reinterpret_cast<float2*>(&ab[(long long)(r + 8) * D + cc]) = v1;
        }
    }
}

// ---------------- fused a3 chain (flash, split over n) --------------------
// Per CTA: 64 landmark rows (rb), head h, n-range [sp*CHN, +CHN).
// Streams 64-n tiles: S = SCALE*ql@k^T, online softmax, O += P@v.
// Partials (O, m, l) -> combine in k_a3comb.
__global__ void __launch_bounds__(256) k_a3fused(
    const float* __restrict__ qkv, const float* __restrict__ ql,
    float* __restrict__ pO, float* __restrict__ pm, float* __restrict__ pl)
{
    __shared__ unsigned Aq[32][72];
    __shared__ unsigned Bk[32][72];
    __shared__ unsigned PA[32][72];
    __shared__ unsigned Bv[32][72];
    __shared__ float redA[2][32][4];
    __shared__ float redB[2][32][4];

    int rb = blockIdx.x;
    int h  = blockIdx.y;
    int sp = blockIdx.z;
    int ns = sp * CHN;
    int tid = threadIdx.x;
    int wid = tid >> 5, lane = tid & 31;
    int wr = wid >> 2, wc = wid & 3;
    int g = lane >> 2, tg = lane & 3;

    // load ql tile (64 m x 64 d)
    {
        int ar = tid >> 2, d0 = (tid & 3) << 4;
        const float* qp = ql + ((long long)h * MLM + rb * 64 + ar) * DH + d0;
        #pragma unroll
        for (int j = 0; j < 4; j++) {
            float4 v = *reinterpret_cast<const float4*>(qp + 4 * j);
            Aq[(d0 >> 1) + 2 * j + 0][ar] = f2bf2(v.x, v.y);
            Aq[(d0 >> 1) + 2 * j + 1][ar] = f2bf2(v.z, v.w);
        }
    }

    float mrun[2][2], lrun[2][2], o2[2][2][4];
    #pragma unroll
    for (int i = 0; i < 2; i++)
        #pragma unroll
        for (int j = 0; j < 2; j++) {
            mrun[i][j] = -INFINITY; lrun[i][j] = 0.0f;
            #pragma unroll
            for (int k = 0; k < 4; k++) o2[i][j][k] = 0.0f;
        }

    for (int t = 0; t < A3T; t++) {
        int nb = ns + t * 64;
        // k tile: Bk[d/2][n]
        {
            int nr = tid >> 2, d0 = (tid & 3) << 4;
            const float* kp = qkv + (long long)(nb + nr) * H3D + D + h * DH + d0;
            #pragma unroll
            for (int j = 0; j < 4; j++) {
                float4 v = *reinterpret_cast<const float4*>(kp + 4 * j);
                Bk[(d0 >> 1) + 2 * j + 0][nr] = f2bf2(v.x, v.y);
                Bk[(d0 >> 1) + 2 * j + 1][nr] = f2bf2(v.z, v.w);
            }
        }
        // v tile: Bv[n/2][d]
        {
            int np_ = tid >> 3, d0 = (tid & 7) << 3;
            const float* v0 = qkv + (long long)(nb + 2 * np_) * H3D + 2 * D + h * DH + d0;
            const float* v1 = v0 + H3D;
            float4 a0 = *reinterpret_cast<const float4*>(v0);
            float4 a1 = *reinterpret_cast<const float4*>(v0 + 4);
            float4 b0 = *reinterpret_cast<const float4*>(v1);
            float4 b1 = *reinterpret_cast<const float4*>(v1 + 4);
            Bv[np_][d0 + 0] = f2bf2(a0.x, b0.x);
            Bv[np_][d0 + 1] = f2bf2(a0.y, b0.y);
            Bv[np_][d0 + 2] = f2bf2(a0.z, b0.z);
            Bv[np_][d0 + 3] = f2bf2(a0.w, b0.w);
            Bv[np_][d0 + 4] = f2bf2(a1.x, b1.x);
            Bv[np_][d0 + 5] = f2bf2(a1.y, b1.y);
            Bv[np_][d0 + 6] = f2bf2(a1.z, b1.z);
            Bv[np_][d0 + 7] = f2bf2(a1.w, b1.w);
        }
        __syncthreads();

        // S = SCALE * ql @ k^T (warp tile 32 x 16)
        float s[2][2][4];
        #pragma unroll
        for (int i = 0; i < 2; i++)
            #pragma unroll
            for (int j = 0; j < 2; j++)
                #pragma unroll
                for (int k = 0; k < 4; k++) s[i][j][k] = 0.0f;
        #pragma unroll
        for (int kb = 0; kb < 4; kb++) {
            unsigned af[2][4], bf[2][2];
            #pragma unroll
            for (int mi = 0; mi < 2; mi++) {
                int r = wr * 32 + mi * 16 + g;
                af[mi][0] = Aq[kb * 8 + tg][r];
                af[mi][1] = Aq[kb * 8 + tg][r + 8];
                af[mi][2] = Aq[kb * 8 + tg + 4][r];
                af[mi][3] = Aq[kb * 8 + tg + 4][r + 8];
            }
            #pragma unroll
            for (int ni = 0; ni < 2; ni++) {
                int cc = wc * 16 + ni * 8 + g;
                bf[ni][0] = Bk[kb * 8 + tg][cc];
                bf[ni][1] = Bk[kb * 8 + tg + 4][cc];
            }
            #pragma unroll
            for (int mi = 0; mi < 2; mi++)
                #pragma unroll
                for (int ni = 0; ni < 2; ni++)
                    mma_bf16(s[mi][ni][0], s[mi][ni][1], s[mi][ni][2], s[mi][ni][3],
                             af[mi][0], af[mi][1], af[mi][2], af[mi][3],
                             bf[ni][0], bf[ni][1]);
        }
        #pragma unroll
        for (int i = 0; i < 2; i++)
            #pragma unroll
            for (int j = 0; j < 2; j++)
                #pragma unroll
                for (int k = 0; k < 4; k++) s[i][j][k] *= SCALE;

        // tile row max
        float tm[2][2];
        #pragma unroll
        for (int mi = 0; mi < 2; mi++)
            #pragma unroll
            for (int hf = 0; hf < 2; hf++) {
                float m = fmaxf(fmaxf(s[mi][0][2 * hf], s[mi][0][2 * hf + 1]),
                                fmaxf(s[mi][1][2 * hf], s[mi][1][2 * hf + 1]));
                m = fmaxf(m, __shfl_xor_sync(0xffffffffu, m, 1));
                m = fmaxf(m, __shfl_xor_sync(0xffffffffu, m, 2));
                tm[mi][hf] = m;
            }
        if (tg == 0) {
            #pragma unroll
            for (int mi = 0; mi < 2; mi++)
                #pragma unroll
                for (int hf = 0; hf < 2; hf++)
                    redA[wr][mi * 16 + hf * 8 + g][wc] = tm[mi][hf];
        }
        __syncthreads();
        #pragma unroll
        for (int mi = 0; mi < 2; mi++)
            #pragma unroll
            for (int hf = 0; hf < 2; hf++) {
                int rl = mi * 16 + hf * 8 + g;
                tm[mi][hf] = fmaxf(fmaxf(redA[wr][rl][0], redA[wr][rl][1]),
                                   fmaxf(redA[wr][rl][2], redA[wr][rl][3]));
            }
        // online update
        float alpha[2][2], ts[2][2];
        #pragma unroll
        for (int mi = 0; mi < 2; mi++)
            #pragma unroll
            for (int hf = 0; hf < 2; hf++) {
                float mnew = fmaxf(mrun[mi][hf], tm[mi][hf]);
                alpha[mi][hf] = __expf(mrun[mi][hf] - mnew);
                mrun[mi][hf] = mnew;
                float e0 = __expf(s[mi][0][2 * hf]     - mnew);
                float e1 = __expf(s[mi][0][2 * hf + 1] - mnew);
                float e2 = __expf(s[mi][1][2 * hf]     - mnew);
                float e3 = __expf(s[mi][1][2 * hf + 1] - mnew);
                s[mi][0][2 * hf] = e0; s[mi][0][2 * hf + 1] = e1;
                s[mi][1][2 * hf] = e2; s[mi][1][2 * hf + 1] = e3;
                float su = e0 + e1 + e2 + e3;
                su += __shfl_xor_sync(0xffffffffu, su, 1);
                su += __shfl_xor_sync(0xffffffffu, su, 2);
                ts[mi][hf] = su;
            }
        if (tg == 0) {
            #pragma unroll
            for (int mi = 0; mi < 2; mi++)
                #pragma unroll
                for (int hf = 0; hf < 2; hf++)
                    redB[wr][mi * 16 + hf * 8 + g][wc] = ts[mi][hf];
        }
        __syncthreads();
        #pragma unroll
        for (int mi = 0; mi < 2; mi++)
            #pragma unroll
            for (int hf = 0; hf < 2; hf++) {
                int rl = mi * 16 + hf * 8 + g;
                float su = redB[wr][rl][0] + redB[wr][rl][1] +
                           redB[wr][rl][2] + redB[wr][rl][3];
                lrun[mi][hf] = lrun[mi][hf] * alpha[mi][hf] + su;
                #pragma unroll
                for (int nj = 0; nj < 2; nj++) {
                    o2[mi][nj][2 * hf]     *= alpha[mi][hf];
                    o2[mi][nj][2 * hf + 1] *= alpha[mi][hf];
                }
            }
        // pack P into PA (A-fragment layout); P cols n = wc*16+ni*8+2tg
        #pragma unroll
        for (int mi = 0; mi < 2; mi++) {
            int r = wr * 32 + mi * 16 + g;
            #pragma unroll
            for (int ni = 0; ni < 2; ni++) {
                int kp = wc * 8 + ni * 4 + tg;
                PA[kp][r]     = f2bf2(s[mi][ni][0], s[mi][ni][1]);
                PA[kp][r + 8] = f2bf2(s[mi][ni][2], s[mi][ni][3]);
            }
        }
        __syncthreads();
        // O += P @ v (warp tile 32 x 16)
        #pragma unroll
        for (int kb = 0; kb < 4; kb++) {
            unsigned af[2][4], bf[2][2];
            #pragma unroll
            for (int mi = 0; mi < 2; mi++) {
                int r = wr * 32 + mi * 16 + g;
                af[mi][0] = PA[kb * 8 + tg][r];
                af[mi][1] = PA[kb * 8 + tg][r + 8];
                af[mi][2] = PA[kb * 8 + tg + 4][r];
                af[mi][3] = PA[kb * 8 + tg + 4][r + 8];
            }
            #pragma unroll
            for (int nj = 0; nj < 2; nj++) {
                int cc = wc * 16 + nj * 8 + g;
                bf[nj][0] = Bv[kb * 8 + tg][cc];
                bf[nj][1] = Bv[kb * 8 + tg + 4][cc];
            }
            #pragma unroll
            for (int mi = 0; mi < 2; mi++)
                #pragma unroll
                for (int nj = 0; nj < 2; nj++)
                    mma_bf16(o2[mi][nj][0], o2[mi][nj][1], o2[mi][nj][2], o2[mi][nj][3],
                             af[mi][0], af[mi][1], af[mi][2], af[mi][3],
                             bf[nj][0], bf[nj][1]);
        }
        __syncthreads();
    }

    // write partials
    int base = (h * SPL + sp) * MLM + rb * 64;
    #pragma unroll
    for (int mi = 0; mi < 2; mi++) {
        int r = base + wr * 32 + mi * 16 + g;
        #pragma unroll
        for (int nj = 0; nj < 2; nj++) {
            int cc = wc * 16 + nj * 8 + 2 * tg;
            float2 v0, v1;
            v0.x = o2[mi][nj][0]; v0.y = o2[mi][nj][1];
            v1.x = o2[mi][nj][2]; v1.y = o2[mi][nj][3];
            *reinterpret_cast<float2*>(&pO[(long long)r * DH + cc]) = v0;
            *reinterpret_cast<float2*>(&pO[(long long)(r + 8) * DH + cc]) = v1;
        }
    }
    if (tg == 0 && wc == 0) {
        #pragma unroll
        for (int mi = 0; mi < 2; mi++)
            #pragma unroll
            for (int hf = 0; hf < 2; hf++) {
                int rowl = wr * 32 + mi * 16 + hf * 8 + g;
                pm[base + rowl] = mrun[mi][hf];
                pl[base + rowl] = lrun[mi][hf];
            }
    }
}

// combine a3 partials: a3v[h][m][d] = sum_s w_s O_s / sum_s w_s l_s
__global__ void k_a3comb(const float* __restrict__ pO, const float* __restrict__ pm,
                         const float* __restrict__ pl, float* __restrict__ a3v) {
    int i = blockIdx.x * 256 + threadIdx.x;
    if (i >= NH * MLM * DH) return;
    int hm = i / DH, d = i - hm * DH;
    int h = hm / MLM, m = hm - h * MLM;
    float ms = -INFINITY;
    #pragma unroll
    for (int s = 0; s < SPL; s++)
        ms = fmaxf(ms, pm[(h * SPL + s) * MLM + m]);
    float num = 0.0f, den = 0.0f;
    #pragma unroll
    for (int s = 0; s < SPL; s++) {
        int idx = (h * SPL + s) * MLM + m;
        float w = __expf(pm[idx] - ms);
        den += w * pl[idx];
        num += w * pO[(long long)idx * DH + d];
    }
    a3v[i] = num / den;
}

// ---------------- misc kernels ----------------
__global__ void k_zero(float* p, int n) {
    int i = blockIdx.x * 256 + threadIdx.x;
    if (i < n) p[i] = 0.0f;
}

__global__ void k_build(float* h, const float* cls) {
    int idx = blockIdx.x * 256 + threadIdx.x;
    if (idx < D) h[idx] = cls[idx];
    int j = idx - D;
    if (j >= 0 && j < 89 * D) {
        int r = j / D, c = j - r * D;
        h[(long long)(8193 + r) * D + c] = h[(long long)(1 + r) * D + c];
    }
}

__global__ void k_ln(const float* __restrict__ in, float* __restrict__ out,
                     const float* __restrict__ gg, const float* __restrict__ bb, int rows) {
    __shared__ float sh[32];
    int r = blockIdx.x;
    if (r >= rows) return;
    const float* x = in + (long long)r * D;
    int tid = threadIdx.x;
    float v0 = x[tid], v1 = x[tid + 256];
    float s  = blkSum(v0 + v1, sh, 256);
    float s2 = blkSum(v0 * v0 + v1 * v1, sh, 256);
    float mu = s * (1.0f / 512.0f);
    float var = s2 * (1.0f / 512.0f) - mu * mu;
    float inv = rsqrtf(var + 1e-5f);
    float* o = out + (long long)r * D;
    o[tid]       = (v0 - mu) * inv * gg[tid] + bb[tid];
    o[tid + 256] = (v1 - mu) * inv * gg[tid + 256] + bb[tid + 256];
}

// one-pass softmax for rows of exactly 256 (one element per thread)
__global__ void k_softmax256(float* __restrict__ S) {
    __shared__ float sh[32];
    int tid = threadIdx.x;
    float* row = S + (long long)blockIdx.x * 256;
    float v = row[tid];
    float m = blkMax(v, sh, 256);
    float e = __expf(v - m);
    float s = blkSum(e, sh, 256);
    row[tid] = e / s;
}

// landmark means
__global__ void k_landmark(const float* __restrict__ qkv, float* __restrict__ ql,
                           float* __restrict__ klT) {
    int m = blockIdx.x, h = blockIdx.y, d = threadIdx.x;
    const float* base = qkv + (long long)(m * LWIN) * H3D + h * DH + d;
    float qs = 0.0f, ks = 0.0f;
    for (int t = 0; t < LWIN; t++) {
        qs += base[(long long)t * H3D];
        ks += base[(long long)t * H3D + D];
    }
    ql[((h * MLM) + m) * DH + d]  = qs * (1.0f / 33.0f);
    klT[((h * DH) + d) * MLM + m] = ks * (1.0f / 33.0f);
}

// per-head reductions for pinv init
__global__ void k_pinv_red(const float* __restrict__ a2, float* __restrict__ red) {
    __shared__ float sh[32];
    int h = blockIdx.x;
    const float* A = a2 + (long long)h * MLM * MLM;
    int i = threadIdx.x;
    float rs = 0.0f, cs = 0.0f;
    for (int j = 0; j < MLM; j++) {
        rs += fabsf(A[i * MLM + j]);
        cs += fabsf(A[j * MLM + i]);
    }
    float colv = blkMax(rs, sh, 256);
    float rowv = blkMax(cs, sh, 256);
    if (i == 0) { red[h * 2] = colv; red[h * 2 + 1] = rowv; }
}

__global__ void k_pinv_zinit(const float* __restrict__ a2, const float* __restrict__ red,
                             float* __restrict__ z) {
    int idx = blockIdx.x * 256 + threadIdx.x;
    if (idx >= NH * MLM * MLM) return;
    float colm = 0.0f, rowm = 0.0f;
    #pragma unroll
    for (int hh = 0; hh < NH; hh++) {
        colm = fmaxf(colm, red[hh * 2]);
        rowm = fmaxf(rowm, red[hh * 2 + 1]);
    }
    int h = idx >> 16;
    int r = (idx >> 8) & 255;
    int c = idx & 255;
    z[idx] = a2[((long long)h << 16) + c * MLM + r] / (colm * rowm);
}

// depthwise 33-tap conv over sequence of v, added to ab
__global__ void k_conv(const float* __restrict__ qkv, const float* __restrict__ w,
                       float* __restrict__ ab) {
    __shared__ float ws[NH * LWIN];
    int tid = threadIdx.x;
    for (int i = tid; i < NH * LWIN; i += 128) ws[i] = w[i];
    __syncthreads();
    int n = blockIdx.x;
    int c4 = tid << 2;
    int h = c4 >> 6;
    const float* wrow = ws + h * LWIN;
    float4 s = make_float4(0.0f, 0.0f, 0.0f, 0.0f);
    #pragma unroll
    for (int t = 0; t < LWIN; t++) {
        int nn = n - 16 + t;
        if (nn >= 0 && nn < NP) {
            float wv = wrow[t];
            float4 v = *reinterpret_cast<const float4*>(
                qkv + (long long)nn * H3D + 2 * D + c4);
            s.x += wv * v.x; s.y += wv * v.y; s.z += wv * v.z; s.w += wv * v.w;
        }
    }
    float4* dst = reinterpret_cast<float4*>(ab + (long long)n * D + c4);
    float4 o = *dst;
    o.x += s.x; o.y += s.y; o.z += s.z; o.w += s.w;
    *dst = o;
}

__global__ void k_resid(float* __restrict__ h, const float* __restrict__ t) {
    int idx = blockIdx.x * 256 + threadIdx.x;
    if (idx < (NTOK * D) / 4) {
        float4 a = reinterpret_cast<float4*>(h)[idx];
        float4 b = reinterpret_cast<const float4*>(t + PAD * D)[idx];
        a.x += b.x; a.y += b.y; a.z += b.z; a.w += b.w;
        reinterpret_cast<float4*>(h)[idx] = a;
    }
}

// PPEG
__global__ void k_ppeg(const float* __restrict__ h, float* __restrict__ out,
                       const float* __restrict__ w7, const float* __restrict__ b7,
                       const float* __restrict__ w5, const float* __restrict__ b5,
                       const float* __restrict__ w3, const float* __restrict__ b3) {
    int p = blockIdx.x;
    int y = p / HS, x = p - y * HS;
    int c = threadIdx.x;
    if (p == 0) out[c] = h[c];
    float acc = h[(long long)(1 + p) * D + c] + b7[c] + b5[c] + b3[c];
    const float* W7 = w7 + c * 49;
    const float* W5 = w5 + c * 25;
    const float* W3 = w3 + c * 9;
    #pragma unroll
    for (int ky = 0; ky < 7; ky++) {
        int yy = y + ky - 3;
        if (yy < 0 || yy >= HS) continue;
        #pragma unroll
        for (int kx = 0; kx < 7; kx++) {
            int xx = x + kx - 3;
            if (xx < 0 || xx >= HS) continue;
            float v = h[(long long)(1 + yy * HS + xx) * D + c];
            float wsum = W7[ky * 7 + kx];
            if (ky >= 1 && ky <= 5 && kx >= 1 && kx <= 5) wsum += W5[(ky - 1) * 5 + (kx - 1)];
            if (ky >= 2 && ky <= 4 && kx >= 2 && kx <= 4) wsum += W3[(ky - 2) * 3 + (kx - 2)];
            acc += v * wsum;
        }
    }
    out[(long long)(1 + p) * D + c] = acc;
}

// final head
__global__ void k_final(const float* __restrict__ h, const float* __restrict__ gg,
                        const float* __restrict__ bb, const float* __restrict__ fw,
                        const float* __restrict__ fb, float* __restrict__ out, int out_size) {
    __shared__ float sh[32];
    __shared__ float emb[512];
    int tid = threadIdx.x;
    float v = h[tid];
    float s  = blkSum(v, sh, 512);
    float s2 = blkSum(v * v, sh, 512);
    float mu = s * (1.0f / 512.0f);
    float var = s2 * (1.0f / 512.0f) - mu * mu;
    float inv = rsqrtf(var + 1e-5f);
    float e = (v - mu) * inv * gg[tid] + bb[tid];
    emb[tid] = e;
    if (5 + tid < out_size) out[5 + tid] = e;
    __syncthreads();
    if (tid == 0) {
        float l0 = fb[0], l1 = fb[1];
        for (int c = 0; c < 512; c++) { l0 += emb[c] * fw[2 * c]; l1 += emb[c] * fw[2 * c + 1]; }
        if (out_size > 0) out[0] = l0;
        if (out_size > 1) out[1] = l1;
        float m = fmaxf(l0, l1);
        float e0 = __expf(l0 - m), e1 = __expf(l1 - m);
        float ss = e0 + e1;
        if (out_size > 2) out[2] = e0 / ss;
        if (out_size > 3) out[3] = e1 / ss;
        if (out_size > 4) out[4] = (l1 > l0) ? 1.0f : 0.0f;
    }
}

// ---------------- host orchestration ----------------
static inline void gemm(const float* A, int lda, long long sA,
                        const float* B, int ldb, long long sB,
                        float* C, int ldc, long long sC,
                        int M, int N, int K, float alpha,
                        const float* bias, int relu, int batch,
                        int emode = 0, float cval = 0.0f, int ksplit = 1) {
    dim3 g(N / 64, M / 64, batch * ksplit);
    tgemm64<<<g, 128>>>(A, lda, sA, B, ldb, sB, C, ldc, sC, M, N, K, alpha, bias, relu,
                        emode, cval, ksplit);
}

static inline void gemmL(const float* A, int lda, long long sA,
                         const float* B, int ldb, long long sB,
                         float* C, int ldc, long long sC,
                         int M, int N, int K, float alpha,
                         const float* bias, int relu, int batch) {
    dim3 g(N / 128, M / 128, batch);
    tgemm<<<g, 256>>>(A, lda, sA, B, ldb, sB, C, ldc, sC, M, N, K, alpha, bias, relu);
}

struct Bufs {
    float *h, *t, *xp, *qkv, *s, *ql, *klT, *a2, *z0, *z1, *xz, *u, *tt,
          *part, *a3v, *z2, *ab, *red;
};

static void run_attn(Bufs& b, const float* lng, const float* lnb,
                     const float* qkvw, const float* outw, const float* outb,
                     const float* convw) {
    k_zero<<<(PAD * D + 255) / 256, 256>>>(b.xp, PAD * D);
    k_ln<<<NTOK, 256>>>(b.h, b.xp + (long long)PAD * D, lng, lnb, NTOK);
    gemmL(b.xp, D, 0, qkvw, H3D, 0, b.qkv, H3D, 0, NP, H3D, D, 1.0f, nullptr, 0, 1);
    k_landmark<<<dim3(MLM, NH), DH>>>(b.qkv, b.ql, b.klT);
    // a2 = softmax(SCALE * ql @ kl^T)
    gemm(b.ql, DH, MLM * DH, b.klT, MLM, DH * MLM, b.a2, MLM, MLM * MLM,
         MLM, MLM, DH, SCALE, nullptr, 0, NH);
    k_softmax256<<<NH * MLM, 256>>>(b.a2);
    // pinv
    k_pinv_red<<<NH, 256>>>(b.a2, b.red);
    k_pinv_zinit<<<(NH * MLM * MLM + 255) / 256, 256>>>(b.a2, b.red, b.z0);
    float* zc = b.z0; float* zn = b.z1;
    const long long SB = (long long)MLM * MLM;
    for (int it = 0; it < 6; it++) {
        gemm(b.a2, MLM, SB, zc, MLM, SB, b.xz, MLM, SB, MLM, MLM, MLM, 1.0f, nullptr, 0, NH);
        gemm(b.xz, MLM, SB, b.xz, MLM, SB, b.u,  MLM, SB, MLM, MLM, MLM, 1.0f, nullptr, 0, NH, 1, 7.0f);
        gemm(b.xz, MLM, SB, b.u,  MLM, SB, b.tt, MLM, SB, MLM, MLM, MLM, 1.0f, nullptr, 0, NH, 1, 15.0f);
        gemm(zc,   MLM, SB, b.tt, MLM, SB, zn,   MLM, SB, MLM, MLM, MLM, 0.25f, nullptr, 0, NH, 1, 13.0f);
        float* sw = zc; zc = zn; zn = sw;
    }
    // fused a3 (flash over n): a3v = softmax_n(SCALE*ql@k^T) @ v
    float* pm = b.tt;                    // free after pinv loop
    float* pl = b.tt + NH * SPL * MLM;
    k_a3fused<<<dim3(4, NH, SPL), 256>>>(b.qkv, b.ql, b.part, pm, pl);
    k_a3comb<<<(NH * MLM * DH + 255) / 256, 256>>>(b.part, pm, pl, b.a3v);
    // z2 = pinv @ a3v
    gemm(zc, MLM, SB, b.a3v, DH, MLM * DH, b.z2, DH, MLM * DH, MLM, DH, MLM, 1.0f, nullptr, 0, NH);
    // fused a1 chain: ab = softmax(SCALE*q@klT) @ z2 per head
    k_a1fused<<<dim3(NP / 64, NH), 256>>>(b.qkv, b.klT, b.z2, b.ab);
    // + depthwise conv(v)
    k_conv<<<NP, 128>>>(b.qkv, convw, b.ab);
    // proj + residual (last NTOK rows)
    gemmL(b.ab, D, 0, outw, D, 0, b.t, D, 0, NP, D, D, 1.0f, outb, 0, 1);
    k_resid<<<((NTOK * D / 4) + 255) / 256, 256>>>(b.h, b.t);
}

extern "C" void kernel_launch(void* const* d_in, const int* in_sizes, int n_in,
                              void* d_out, int out_size) {
    const float* x      = (const float*)d_in[0];
    const float* fc1_w  = (const float*)d_in[1];
    const float* fc1_b  = (const float*)d_in[2];
    const float* cls    = (const float*)d_in[3];
    const float* ln1_g  = (const float*)d_in[4];
    const float* ln1_b  = (const float*)d_in[5];
    const float* qkv1_w = (const float*)d_in[6];
    const float* out1_w = (const float*)d_in[7];
    const float* out1_b = (const float*)d_in[8];
    const float* conv1_w= (const float*)d_in[9];
    const float* ln2_g  = (const float*)d_in[10];
    const float* ln2_b  = (const float*)d_in[11];
    const float* qkv2_w = (const float*)d_in[12];
    const float* out2_w = (const float*)d_in[13];
    const float* out2_b = (const float*)d_in[14];
    const float* conv2_w= (const float*)d_in[15];
    const float* pg7_w  = (const float*)d_in[16];
    const float* pg7_b  = (const float*)d_in[17];
    const float* pg5_w  = (const float*)d_in[18];
    const float* pg5_b  = (const float*)d_in[19];
    const float* pg3_w  = (const float*)d_in[20];
    const float* pg3_b  = (const float*)d_in[21];
    const float* norm_g = (const float*)d_in[22];
    const float* norm_b = (const float*)d_in[23];
    const float* fc2_w  = (const float*)d_in[24];
    const float* fc2_b  = (const float*)d_in[25];

    Bufs b;
    cudaGetSymbolAddress((void**)&b.h,    g_h);
    cudaGetSymbolAddress((void**)&b.t,    g_t);
    cudaGetSymbolAddress((void**)&b.xp,   g_xp);
    cudaGetSymbolAddress((void**)&b.qkv,  g_qkv);
    cudaGetSymbolAddress((void**)&b.s,    g_s);
    cudaGetSymbolAddress((void**)&b.ql,   g_ql);
    cudaGetSymbolAddress((void**)&b.klT,  g_klT);
    cudaGetSymbolAddress((void**)&b.a2,   g_a2);
    cudaGetSymbolAddress((void**)&b.z0,   g_z0);
    cudaGetSymbolAddress((void**)&b.z1,   g_z1);
    cudaGetSymbolAddress((void**)&b.xz,   g_xz);
    cudaGetSymbolAddress((void**)&b.u,    g_u);
    cudaGetSymbolAddress((void**)&b.tt,   g_tt);
    cudaGetSymbolAddress((void**)&b.part, g_part);
    cudaGetSymbolAddress((void**)&b.a3v,  g_a3v);
    cudaGetSymbolAddress((void**)&b.z2,   g_z2);
    cudaGetSymbolAddress((void**)&b.ab,   g_ab);
    cudaGetSymbolAddress((void**)&b.red,  g_red);

    // fc1: h rows 1..8192 = relu(x @ fc1_w + b)
    gemmL(x, 1024, 0, fc1_w, D, 0, b.h + D, D, 0, 8192, D, 1024, 1.0f, fc1_b, 1, 1);
    k_build<<<(90 * D + 255) / 256, 256>>>(b.h, cls);

    // layer 1 attention
    run_attn(b, ln1_g, ln1_b, qkv1_w, out1_w, out1_b, conv1_w);

    // PPEG: write into t (incl. cls row), then swap h <-> t
    k_ppeg<<<NPIX, 512>>>(b.h, b.t, pg7_w, pg7_b, pg5_w, pg5_b, pg3_w, pg3_b);
    { float* tmp = b.h; b.h = b.t; b.t = tmp; }

    // layer 2 attention
    run_attn(b, ln2_g, ln2_b, qkv2_w, out2_w, out2_b, conv2_w);

    // head
    k_final<<<1, 512>>>(b.h, norm_g, norm_b, fc2_w, fc2_b, (float*)d_out, out_size);
}